// round 11
// baseline (speedup 1.0000x reference)
#include <cuda_runtime.h>
#include <cuda_fp16.h>
#include <cstdint>

#define BB 4
#define CC 256
#define NN 4096
#define DD 64

// Scratch (device globals: allocation-free kernel_launch)
__device__ unsigned g_qh[(size_t)BB * NN * 32];         // 2 MB  q fp16 pairs [b][n][d/2]
__device__ unsigned g_vh[(size_t)BB * CC * (NN / 2)];   // 8 MB  v fp16 pairs [b][c][n/2]
__device__ unsigned g_xth[(size_t)BB * NN * (CC / 2)];  // 8 MB  x^T fp16 pairs [b][n][c/2]
__device__ unsigned g_xaTh[(size_t)BB * NN * (CC / 2)]; // 8 MB  x_a^T fp16 pairs [b][n][c/2]
__device__ unsigned g_wqh[DD * (CC / 2)];               // wq fp16 pairs [o][c/2]
__device__ unsigned g_wvh[CC * (CC / 2)];
__device__ unsigned g_wth[CC * (CC / 2)];
__device__ float g_rowmax[BB * NN];
__device__ float g_rowinv[BB * NN];
__device__ float g_t[(size_t)BB * CC * NN];             // 16 MB
__device__ float g_bnsum[CC];
__device__ float g_bnsum2[CC];
__device__ float g_mean[CC];
__device__ float g_rstd[CC];

// ---------------------------------------------------------------------------
// helpers
// ---------------------------------------------------------------------------
__device__ __forceinline__ void mma_fp16(
    float* c,
    unsigned a0, unsigned a1, unsigned a2, unsigned a3,
    unsigned b0, unsigned b1)
{
    asm volatile(
        "mma.sync.aligned.m16n8k16.row.col.f32.f16.f16.f32 "
        "{%0,%1,%2,%3}, {%4,%5,%6,%7}, {%8,%9}, {%0,%1,%2,%3};\n"
        : "+f"(c[0]), "+f"(c[1]), "+f"(c[2]), "+f"(c[3])
        : "r"(a0), "r"(a1), "r"(a2), "r"(a3), "r"(b0), "r"(b1));
}

__device__ __forceinline__ void cpa16(unsigned sdst, const void* gsrc)
{
    asm volatile("cp.async.cg.shared.global [%0], [%1], 16;\n"
                 :: "r"(sdst), "l"(gsrc));
}
__device__ __forceinline__ void cpa_commit()
{
    asm volatile("cp.async.commit_group;\n");
}
__device__ __forceinline__ void cpa_wait0()
{
    asm volatile("cp.async.wait_group 0;\n");
}

__device__ __forceinline__ unsigned pack_h2(float a, float b)
{
    __half2 h = __floats2half2_rn(a, b);
    return *reinterpret_cast<unsigned*>(&h);
}

// ---------------------------------------------------------------------------
// xt: transpose + convert x[b][c][n] fp32 -> g_xth[(b*N+n)*128 + c/2] fp16 pairs
// ---------------------------------------------------------------------------
__global__ __launch_bounds__(256) void xt_kernel(const float* __restrict__ x)
{
    const int b  = blockIdx.z;
    const int c0 = blockIdx.y * 64;
    const int n0 = blockIdx.x * 64;
    const float* xb = x + ((size_t)b * CC + c0) * NN + n0;

    __shared__ float sT[64][65];
    const int tid = threadIdx.x;

#pragma unroll
    for (int r = 0; r < 16; r++) {
        int idx = tid + r * 256;
        int c = idx >> 6, n = idx & 63;
        sT[c][n] = xb[(size_t)c * NN + n];
    }
    __syncthreads();
#pragma unroll
    for (int r = 0; r < 8; r++) {
        int idx = tid + r * 256;
        int n = idx >> 5, cp = idx & 31;
        g_xth[((size_t)b * NN + n0 + n) * 128 + c0 / 2 + cp] =
            pack_h2(sT[2 * cp][n], sT[2 * cp + 1][n]);
    }
}

// ---------------------------------------------------------------------------
// wcvt: convert wq/wv/wt to fp16 pairs; also zero BN accumulators
// ---------------------------------------------------------------------------
__global__ __launch_bounds__(256) void wcvt_kernel(
    const float* __restrict__ wq, const float* __restrict__ wv,
    const float* __restrict__ wt)
{
    int idx = blockIdx.x * 256 + threadIdx.x;
    if (idx < 256) { g_bnsum[idx] = 0.f; g_bnsum2[idx] = 0.f; }
    if (idx < 8192) {
        float2 f = *reinterpret_cast<const float2*>(&wq[idx * 2]);
        g_wqh[idx] = pack_h2(f.x, f.y);
    } else if (idx < 8192 + 32768) {
        int i = idx - 8192;
        float2 f = *reinterpret_cast<const float2*>(&wv[i * 2]);
        g_wvh[i] = pack_h2(f.x, f.y);
    } else if (idx < 8192 + 65536) {
        int i = idx - 8192 - 32768;
        float2 f = *reinterpret_cast<const float2*>(&wt[i * 2]);
        g_wth[i] = pack_h2(f.x, f.y);
    }
}

// ---------------------------------------------------------------------------
// convq_tc: q^T[n][o] = x^T[n][:] . wq[o][:]  -> g_qh[(b*N+n)*32 + o/2]
// ---------------------------------------------------------------------------
__global__ __launch_bounds__(256) void convq_tc_kernel()
{
    const int b  = blockIdx.z;
    const int n0 = blockIdx.x * 128;
    const unsigned* xth = g_xth + (size_t)b * NN * 128;

    __shared__ unsigned sA[128][36];
    __shared__ unsigned sB[64][36];

    const int tid = threadIdx.x;
    const int lane = tid & 31, wid = tid >> 5;
    const int wm = wid >> 2, wn = wid & 3;
    const int gp = lane >> 2, tg = lane & 3;

    float acc[4][2][4] = {};

    for (int ks = 0; ks < 4; ks++) {
        int kp0g = ks * 32;
        __syncthreads();
#pragma unroll
        for (int r = 0; r < 16; r++) {
            int idx = tid + r * 256;
            int row = idx >> 5, kp = idx & 31;
            sA[row][kp] = xth[(size_t)(n0 + row) * 128 + kp0g + kp];
        }
#pragma unroll
        for (int r = 0; r < 8; r++) {
            int idx = tid + r * 256;
            int row = idx >> 5, kp = idx & 31;
            sB[row][kp] = g_wqh[(size_t)row * 128 + kp0g + kp];
        }
        __syncthreads();
#pragma unroll
        for (int kk = 0; kk < 4; kk++) {
            int kp0 = kk * 8;
            unsigned a[4][4], bf[2][2];
#pragma unroll
            for (int i = 0; i < 4; i++) {
                int row = wm * 64 + i * 16 + gp;
                a[i][0] = sA[row][kp0 + tg];
                a[i][1] = sA[row + 8][kp0 + tg];
                a[i][2] = sA[row][kp0 + 4 + tg];
                a[i][3] = sA[row + 8][kp0 + 4 + tg];
            }
#pragma unroll
            for (int j = 0; j < 2; j++) {
                int col = wn * 16 + j * 8 + gp;
                bf[j][0] = sB[col][kp0 + tg];
                bf[j][1] = sB[col][kp0 + 4 + tg];
            }
#pragma unroll
            for (int i = 0; i < 4; i++)
#pragma unroll
                for (int j = 0; j < 2; j++)
                    mma_fp16(acc[i][j], a[i][0], a[i][1], a[i][2], a[i][3],
                             bf[j][0], bf[j][1]);
        }
    }

#pragma unroll
    for (int i = 0; i < 4; i++) {
        int n = n0 + wm * 64 + i * 16 + gp;
#pragma unroll
        for (int j = 0; j < 2; j++) {
            int op = wn * 8 + j * 4 + tg;
            g_qh[((size_t)b * NN + n) * 32 + op]     = pack_h2(acc[i][j][0], acc[i][j][1]);
            g_qh[((size_t)b * NN + n + 8) * 32 + op] = pack_h2(acc[i][j][2], acc[i][j][3]);
        }
    }
}

// ---------------------------------------------------------------------------
// convv_tc: v[o][n] = wv[o][:] . x^T[n][:] + bv  -> g_vh[(b*C+o)*(N/2) + n/2]
// ---------------------------------------------------------------------------
__global__ __launch_bounds__(256) void convv_tc_kernel(const float* __restrict__ bias)
{
    const int b  = blockIdx.z;
    const int o0 = blockIdx.y * 128;
    const int n0 = blockIdx.x * 128;
    const unsigned* xth = g_xth + (size_t)b * NN * 128;

    __shared__ unsigned sA[128][36];
    __shared__ unsigned sB[128][36];

    const int tid = threadIdx.x;
    const int lane = tid & 31, wid = tid >> 5;
    const int wm = wid >> 2, wn = wid & 3;
    const int gp = lane >> 2, tg = lane & 3;

    float acc[4][4][4] = {};

    for (int ks = 0; ks < 4; ks++) {
        int kp0g = ks * 32;
        __syncthreads();
#pragma unroll
        for (int r = 0; r < 16; r++) {
            int idx = tid + r * 256;
            int row = idx >> 5, kp = idx & 31;
            sA[row][kp] = g_wvh[(size_t)(o0 + row) * 128 + kp0g + kp];
            sB[row][kp] = xth[(size_t)(n0 + row) * 128 + kp0g + kp];
        }
        __syncthreads();
#pragma unroll
        for (int kk = 0; kk < 4; kk++) {
            int kp0 = kk * 8;
            unsigned a[4][4], bf[4][2];
#pragma unroll
            for (int i = 0; i < 4; i++) {
                int row = wm * 64 + i * 16 + gp;
                a[i][0] = sA[row][kp0 + tg];
                a[i][1] = sA[row + 8][kp0 + tg];
                a[i][2] = sA[row][kp0 + 4 + tg];
                a[i][3] = sA[row + 8][kp0 + 4 + tg];
            }
#pragma unroll
            for (int j = 0; j < 4; j++) {
                int col = wn * 32 + j * 8 + gp;
                bf[j][0] = sB[col][kp0 + tg];
                bf[j][1] = sB[col][kp0 + 4 + tg];
            }
#pragma unroll
            for (int i = 0; i < 4; i++)
#pragma unroll
                for (int j = 0; j < 4; j++)
                    mma_fp16(acc[i][j], a[i][0], a[i][1], a[i][2], a[i][3],
                             bf[j][0], bf[j][1]);
        }
    }

#pragma unroll
    for (int i = 0; i < 4; i++) {
        int o = o0 + wm * 64 + i * 16 + gp;
        float b0 = bias[o], b1 = bias[o + 8];
#pragma unroll
        for (int j = 0; j < 4; j++) {
            int np = (n0 + wn * 32 + j * 8 + 2 * tg) / 2;
            g_vh[((size_t)b * CC + o) * (NN / 2) + np] =
                pack_h2(acc[i][j][0] + b0, acc[i][j][1] + b0);
            g_vh[((size_t)b * CC + o + 8) * (NN / 2) + np] =
                pack_h2(acc[i][j][2] + b1, acc[i][j][3] + b1);
        }
    }
}

// ---------------------------------------------------------------------------
// convt_tc: t[o][n] = wt[o][:] . (x^T - x_a^T)[n][:] + bt  -> g_t fp32
// Fused BN partial sums: per-channel sum/sumsq -> g_bnsum/g_bnsum2 (atomics).
// ---------------------------------------------------------------------------
__global__ __launch_bounds__(256) void convt_tc_kernel(const float* __restrict__ bias)
{
    const int b  = blockIdx.z;
    const int o0 = blockIdx.y * 128;
    const int n0 = blockIdx.x * 128;
    const unsigned* xth  = g_xth  + (size_t)b * NN * 128;
    const unsigned* xath = g_xaTh + (size_t)b * NN * 128;

    __shared__ unsigned sA[128][36];
    __shared__ unsigned sB[128][36];
    __shared__ float sS[128], sS2[128];

    const int tid = threadIdx.x;
    const int lane = tid & 31, wid = tid >> 5;
    const int wm = wid >> 2, wn = wid & 3;
    const int gp = lane >> 2, tg = lane & 3;

    if (tid < 128) { sS[tid] = 0.f; sS2[tid] = 0.f; }

    float acc[4][4][4] = {};

    for (int ks = 0; ks < 4; ks++) {
        int kp0g = ks * 32;
        __syncthreads();
#pragma unroll
        for (int r = 0; r < 16; r++) {
            int idx = tid + r * 256;
            int row = idx >> 5, kp = idx & 31;
            sA[row][kp] = g_wth[(size_t)(o0 + row) * 128 + kp0g + kp];
            size_t gi = (size_t)(n0 + row) * 128 + kp0g + kp;
            __half2 xv = *reinterpret_cast<const __half2*>(&xth[gi]);
            __half2 av = *reinterpret_cast<const __half2*>(&xath[gi]);
            __half2 d = __hsub2(xv, av);
            sB[row][kp] = *reinterpret_cast<unsigned*>(&d);
        }
        __syncthreads();
#pragma unroll
        for (int kk = 0; kk < 4; kk++) {
            int kp0 = kk * 8;
            unsigned a[4][4], bf[4][2];
#pragma unroll
            for (int i = 0; i < 4; i++) {
                int row = wm * 64 + i * 16 + gp;
                a[i][0] = sA[row][kp0 + tg];
                a[i][1] = sA[row + 8][kp0 + tg];
                a[i][2] = sA[row][kp0 + 4 + tg];
                a[i][3] = sA[row + 8][kp0 + 4 + tg];
            }
#pragma unroll
            for (int j = 0; j < 4; j++) {
                int col = wn * 32 + j * 8 + gp;
                bf[j][0] = sB[col][kp0 + tg];
                bf[j][1] = sB[col][kp0 + 4 + tg];
            }
#pragma unroll
            for (int i = 0; i < 4; i++)
#pragma unroll
                for (int j = 0; j < 4; j++)
                    mma_fp16(acc[i][j], a[i][0], a[i][1], a[i][2], a[i][3],
                             bf[j][0], bf[j][1]);
        }
    }

#pragma unroll
    for (int i = 0; i < 4; i++) {
        int ol = wm * 64 + i * 16 + gp;
        int o = o0 + ol;
        float b0 = bias[o], b1 = bias[o + 8];
        float sa = 0.f, sa2 = 0.f, sb = 0.f, sb2 = 0.f;
#pragma unroll
        for (int j = 0; j < 4; j++) {
            int n = n0 + wn * 32 + j * 8 + 2 * tg;
            float t00 = acc[i][j][0] + b0, t01 = acc[i][j][1] + b0;
            float t10 = acc[i][j][2] + b1, t11 = acc[i][j][3] + b1;
            sa += t00 + t01;  sa2 += t00 * t00 + t01 * t01;
            sb += t10 + t11;  sb2 += t10 * t10 + t11 * t11;
            *reinterpret_cast<float2*>(&g_t[((size_t)b * CC + o) * NN + n]) =
                make_float2(t00, t01);
            *reinterpret_cast<float2*>(&g_t[((size_t)b * CC + o + 8) * NN + n]) =
                make_float2(t10, t11);
        }
        // reduce across tg (4 lanes share the same rows)
#pragma unroll
        for (int off = 1; off <= 2; off <<= 1) {
            sa  += __shfl_xor_sync(0xffffffffu, sa,  off);
            sa2 += __shfl_xor_sync(0xffffffffu, sa2, off);
            sb  += __shfl_xor_sync(0xffffffffu, sb,  off);
            sb2 += __shfl_xor_sync(0xffffffffu, sb2, off);
        }
        if (tg == 0) {
            atomicAdd(&sS[ol], sa);      atomicAdd(&sS2[ol], sa2);
            atomicAdd(&sS[ol + 8], sb);  atomicAdd(&sS2[ol + 8], sb2);
        }
    }
    __syncthreads();
    if (tid < 128) {
        atomicAdd(&g_bnsum[o0 + tid], sS[tid]);
        atomicAdd(&g_bnsum2[o0 + tid], sS2[tid]);
    }
}

// ---------------------------------------------------------------------------
// bnfin: mean/rstd from accumulated sums (1 block)
// ---------------------------------------------------------------------------
__global__ void bnfin_kernel()
{
    int c = threadIdx.x;
    const float invM = 1.f / (float)(BB * NN);
    float mean = g_bnsum[c] * invM;
    float var = g_bnsum2[c] * invM - mean * mean;
    g_mean[c] = mean;
    g_rstd[c] = rsqrtf(var + 1e-5f);
}

// ---------------------------------------------------------------------------
// pass1: fused energy + row softmax stats (flash pass).
// ---------------------------------------------------------------------------
__global__ __launch_bounds__(256) void pass1_kernel()
{
    const int b  = blockIdx.y;
    const int n0 = blockIdx.x * 128;
    const unsigned* qh = g_qh + (size_t)b * NN * 32;

    __shared__ unsigned sA[128][36];
    __shared__ unsigned sB[128][36];
    __shared__ float2 sMrg[4][128];

    const int tid = threadIdx.x;
    const int lane = tid & 31, wid = tid >> 5;
    const int wm = wid >> 2, wn = wid & 3;
    const int gp = lane >> 2, tg = lane & 3;

#pragma unroll
    for (int r = 0; r < 16; r++) {
        int idx = tid + r * 256;
        int row = idx >> 5, kp = idx & 31;
        sA[row][kp] = qh[(size_t)(n0 + row) * 32 + kp];
    }

    float rmax[8], rsum[8];
#pragma unroll
    for (int i = 0; i < 8; i++) { rmax[i] = -1e30f; rsum[i] = 0.f; }

    for (int m0 = 0; m0 < NN; m0 += 128) {
        __syncthreads();
#pragma unroll
        for (int r = 0; r < 16; r++) {
            int idx = tid + r * 256;
            int row = idx >> 5, kp = idx & 31;
            sB[row][kp] = qh[(size_t)(m0 + row) * 32 + kp];
        }
        __syncthreads();

        float acc[4][4][4] = {};
#pragma unroll
        for (int ks = 0; ks < 4; ks++) {
            int kp0 = ks * 8;
            unsigned a[4][4], bf[4][2];
#pragma unroll
            for (int i = 0; i < 4; i++) {
                int row = wm * 64 + i * 16 + gp;
                a[i][0] = sA[row][kp0 + tg];
                a[i][1] = sA[row + 8][kp0 + tg];
                a[i][2] = sA[row][kp0 + 4 + tg];
                a[i][3] = sA[row + 8][kp0 + 4 + tg];
            }
#pragma unroll
            for (int j = 0; j < 4; j++) {
                int col = wn * 32 + j * 8 + gp;
                bf[j][0] = sB[col][kp0 + tg];
                bf[j][1] = sB[col][kp0 + 4 + tg];
            }
#pragma unroll
            for (int i = 0; i < 4; i++)
#pragma unroll
                for (int j = 0; j < 4; j++)
                    mma_fp16(acc[i][j], a[i][0], a[i][1], a[i][2], a[i][3],
                             bf[j][0], bf[j][1]);
        }

#pragma unroll
        for (int i = 0; i < 4; i++) {
            float m0v = -1e30f, m1v = -1e30f;
#pragma unroll
            for (int j = 0; j < 4; j++) {
                m0v = fmaxf(m0v, fmaxf(acc[i][j][0], acc[i][j][1]));
                m1v = fmaxf(m1v, fmaxf(acc[i][j][2], acc[i][j][3]));
            }
            m0v = fmaxf(m0v, __shfl_xor_sync(0xffffffffu, m0v, 1));
            m0v = fmaxf(m0v, __shfl_xor_sync(0xffffffffu, m0v, 2));
            m1v = fmaxf(m1v, __shfl_xor_sync(0xffffffffu, m1v, 1));
            m1v = fmaxf(m1v, __shfl_xor_sync(0xffffffffu, m1v, 2));
            float nm0 = fmaxf(rmax[2 * i],     m0v);
            float nm1 = fmaxf(rmax[2 * i + 1], m1v);
            float s0 = 0.f, s1 = 0.f;
#pragma unroll
            for (int j = 0; j < 4; j++) {
                s0 += __expf(acc[i][j][0] - nm0) + __expf(acc[i][j][1] - nm0);
                s1 += __expf(acc[i][j][2] - nm1) + __expf(acc[i][j][3] - nm1);
            }
            s0 += __shfl_xor_sync(0xffffffffu, s0, 1);
            s0 += __shfl_xor_sync(0xffffffffu, s0, 2);
            s1 += __shfl_xor_sync(0xffffffffu, s1, 1);
            s1 += __shfl_xor_sync(0xffffffffu, s1, 2);
            rsum[2 * i]     = rsum[2 * i]     * __expf(rmax[2 * i]     - nm0) + s0;
            rsum[2 * i + 1] = rsum[2 * i + 1] * __expf(rmax[2 * i + 1] - nm1) + s1;
            rmax[2 * i]     = nm0;
            rmax[2 * i + 1] = nm1;
        }
    }

    if (tg == 0) {
#pragma unroll
        for (int i = 0; i < 4; i++) {
            int row = wm * 64 + i * 16 + gp;
            sMrg[wn][row]     = make_float2(rmax[2 * i],     rsum[2 * i]);
            sMrg[wn][row + 8] = make_float2(rmax[2 * i + 1], rsum[2 * i + 1]);
        }
    }
    __syncthreads();
    if (tid < 128) {
        float2 v0 = sMrg[0][tid], v1 = sMrg[1][tid];
        float2 v2 = sMrg[2][tid], v3 = sMrg[3][tid];
        float M = fmaxf(fmaxf(v0.x, v1.x), fmaxf(v2.x, v3.x));
        float S = v0.y * __expf(v0.x - M) + v1.y * __expf(v1.x - M)
                + v2.y * __expf(v2.x - M) + v3.y * __expf(v3.x - M);
        g_rowmax[b * NN + n0 + tid] = M;
        g_rowinv[b * NN + n0 + tid] = 1.f / S;
    }
}

// ---------------------------------------------------------------------------
// xa: fused E-recompute + P + colsum + x_a^T, single-sync software pipeline.
// iter i: mma1(i+1) -> P(i+1) write | colsum(i) | mma2(i) | wait | sync | loads
// ---------------------------------------------------------------------------
#define XA_W_SVH 0
#define XA_W_SQM (2 * 256 * 36)
#define XA_W_SQN (XA_W_SQM + 128 * 36)
#define XA_W_SPH (XA_W_SQN + 2 * 64 * 36)
#define XA_W_COL (XA_W_SPH + 2 * 128 * 36)
#define XA_SMEM_WORDS (XA_W_COL + 128)

__global__ __launch_bounds__(512, 1) void xa_kernel()
{
    const int b  = blockIdx.y;
    const int m0 = blockIdx.x * 128;
    const unsigned* vbh = g_vh + (size_t)b * CC * (NN / 2);
    const float* rmx = g_rowmax + b * NN;
    const float* rin = g_rowinv + b * NN;
    const unsigned* qh = g_qh + (size_t)b * NN * 32;

    extern __shared__ unsigned shm[];
    unsigned (*sQm)[36] = reinterpret_cast<unsigned(*)[36]>(shm + XA_W_SQM);
    float* sCol = reinterpret_cast<float*>(shm + XA_W_COL);
    const unsigned sbase = (unsigned)__cvta_generic_to_shared(shm);

    const int tid = threadIdx.x;
    const int lane = tid & 31, wid = tid >> 5;
    const int gp = lane >> 2, tg = lane & 3;
    const int nh = wid & 3, mh = wid >> 2;       // mma1 roles (4x4)
    const int wm = wid >> 2, wn = wid & 3;       // mma2 roles

    // q_m tile (constant for the block)
#pragma unroll
    for (int r = 0; r < 8; r++) {
        int idx = tid + r * 512;
        int row = idx >> 5, kp = idx & 31;
        sQm[row][kp] = qh[(size_t)(m0 + row) * 32 + kp];
    }
    if (tid < 128) sCol[tid] = 0.f;

    auto issue_V = [&](int chunk) {
        int buf = chunk & 1;
        int np0 = chunk * 32;
#pragma unroll
        for (int t = 0; t < 4; t++) {
            int idx = tid + t * 512;
            int row = idx >> 3, seg = idx & 7;
            unsigned dst = sbase + (XA_W_SVH + buf * 256 * 36 + row * 36 + seg * 4) * 4;
            cpa16(dst, vbh + (size_t)row * (NN / 2) + np0 + seg * 4);
        }
    };
    auto issue_Qn = [&](int chunk) {
        int buf = chunk & 1;
        int row = tid >> 3, seg = tid & 7;
        unsigned dst = sbase + (XA_W_SQN + buf * 64 * 36 + row * 36 + seg * 4) * 4;
        cpa16(dst, qh + (size_t)(chunk * 64 + row) * 32 + seg * 4);
    };

    // mma1 for chunk: compute E^chunk and write P into sPh[chunk&1]
    auto do_mma1 = [&](int chunk) {
        int buf = chunk & 1;
        unsigned (*sQnB)[36] = reinterpret_cast<unsigned(*)[36]>(shm + XA_W_SQN + buf * 64 * 36);
        __half (*sPhB)[72] = reinterpret_cast<__half(*)[72]>(shm + XA_W_SPH + buf * 128 * 36);
        float e[4][4] = {};
#pragma unroll
        for (int ks = 0; ks < 4; ks++) {
            int kp0 = ks * 8;
            unsigned a0 = sQnB[nh * 16 + gp][kp0 + tg];
            unsigned a1 = sQnB[nh * 16 + gp + 8][kp0 + tg];
            unsigned a2 = sQnB[nh * 16 + gp][kp0 + 4 + tg];
            unsigned a3 = sQnB[nh * 16 + gp + 8][kp0 + 4 + tg];
#pragma unroll
            for (int j = 0; j < 4; j++) {
                int col = mh * 32 + j * 8 + gp;
                mma_fp16(e[j], a0, a1, a2, a3,
                         sQm[col][kp0 + tg], sQm[col][kp0 + 4 + tg]);
            }
        }
        int r0 = chunk * 64 + nh * 16 + gp;
        float mx0 = __ldg(&rmx[r0]),     iv0 = __ldg(&rin[r0]);
        float mx1 = __ldg(&rmx[r0 + 8]), iv1 = __ldg(&rin[r0 + 8]);
        int nr0 = nh * 16 + gp, nr1 = nr0 + 8;
#pragma unroll
        for (int j = 0; j < 4; j++) {
            int cb = mh * 32 + j * 8 + 2 * tg;
            sPhB[cb][nr0]     = __float2half(__expf(e[j][0] - mx0) * iv0);
            sPhB[cb + 1][nr0] = __float2half(__expf(e[j][1] - mx0) * iv0);
            sPhB[cb][nr1]     = __float2half(__expf(e[j][2] - mx1) * iv1);
            sPhB[cb + 1][nr1] = __float2half(__expf(e[j][3] - mx1) * iv1);
        }
    };

    // prologue: V(0),V(1),Qn(0),Qn(1) in flight
    issue_V(0); issue_V(1); issue_Qn(0); issue_Qn(1); cpa_commit();
    cpa_wait0();
    __syncthreads();

    do_mma1(0);            // P(0)
    __syncthreads();
    issue_Qn(2); cpa_commit();

    float acc[2][8][4] = {};

    for (int i = 0; i < 64; i++) {
        const int buf = i & 1;
        unsigned (*sVhB)[36] = reinterpret_cast<unsigned(*)[36]>(shm + XA_W_SVH + buf * 256 * 36);
        __half  (*sPhB)[72] = reinterpret_cast<__half(*)[72]>(shm + XA_W_SPH + buf * 128 * 36);
        unsigned (*sPhU)[36] = reinterpret_cast<unsigned(*)[36]>(shm + XA_W_SPH + buf * 128 * 36);

        // 1. mma1(i+1): E chunk + P(i+1) into the other buffer (safe: all
        //    readers of P(i-1) retired at the previous iteration's sync)
        if (i < 63)
            do_mma1(i + 1);

        // 2. colsum(i)
        {
            int m = tid & 127, seg = tid >> 7;
            const __half2* prow = reinterpret_cast<const __half2*>(sPhB[m]);
            float cs = 0.f;
#pragma unroll
            for (int k = 0; k < 8; k++) {
                float2 f = __half22float2(prow[seg * 8 + k]);
                cs += f.x + f.y;
            }
            atomicAdd(&sCol[m], cs);
        }

        // 3. mma2(i): acc[m,c] += P[m][n] * V[c][n]
#pragma unroll
        for (int ks = 0; ks < 4; ks++) {
            int kp0 = ks * 8;
            unsigned pa[2][4], bf[8][2];
#pragma unroll
            for (int ii = 0; ii < 2; ii++) {
                int row = wm * 32 + ii * 16 + gp;
                pa[ii][0] = sPhU[row][kp0 + tg];
                pa[ii][1] = sPhU[row + 8][kp0 + tg];
                pa[ii][2] = sPhU[row][kp0 + 4 + tg];
                pa[ii][3] = sPhU[row + 8][kp0 + 4 + tg];
            }
#pragma unroll
            for (int j = 0; j < 8; j++) {
                int col = wn * 64 + j * 8 + gp;
                bf[j][0] = sVhB[col][kp0 + tg];
                bf[j][1] = sVhB[col][kp0 + 4 + tg];
            }
#pragma unroll
            for (int ii = 0; ii < 2; ii++)
#pragma unroll
                for (int j = 0; j < 8; j++)
                    mma_fp16(acc[ii][j], pa[ii][0], pa[ii][1], pa[ii][2], pa[ii][3],
                             bf[j][0], bf[j][1]);
        }

        // 4. wait for V(i+1), Qn(i+2); 5. single sync; 6. next loads
        cpa_wait0();
        __syncthreads();
        if (i + 2 < 64) issue_V(i + 2);
        if (i + 3 < 64) issue_Qn(i + 3);
        cpa_commit();
    }

    // epilogue: x_a^T[m][c] = acc * inv(m); write fp16 pairs (c contig)
#pragma unroll
    for (int ii = 0; ii < 2; ii++) {
        int mr = wm * 32 + ii * 16 + gp;
        float i0 = 1.f / (1e-9f + sCol[mr]);
        float i1 = 1.f / (1e-9f + sCol[mr + 8]);
        size_t r0 = ((size_t)b * NN + m0 + mr) * 128;
        size_t r1 = r0 + 8 * 128;
#pragma unroll
        for (int j = 0; j < 8; j++) {
            int cp = wn * 32 + j * 4 + tg;
            g_xaTh[r0 + cp] = pack_h2(acc[ii][j][0] * i0, acc[ii][j][1] * i0);
            g_xaTh[r1 + cp] = pack_h2(acc[ii][j][2] * i1, acc[ii][j][3] * i1);
        }
    }
}

// ---------------------------------------------------------------------------
// Final: out = x + relu(gamma * (t - mean) * rstd + beta)
// ---------------------------------------------------------------------------
__global__ __launch_bounds__(256) void final_kernel(
    const float* __restrict__ x, const float* __restrict__ gamma,
    const float* __restrict__ beta, float* __restrict__ out)
{
    size_t i = (size_t)blockIdx.x * 256 + threadIdx.x;
    int c = (int)((i >> 12) & 255);
    float t = g_t[i];
    float th = (t - g_mean[c]) * g_rstd[c];
    float r = fmaxf(0.f, gamma[c] * th + beta[c]);
    out[i] = x[i] + r;
}

// ---------------------------------------------------------------------------
extern "C" void kernel_launch(void* const* d_in, const int* in_sizes, int n_in,
                              void* d_out, int out_size)
{
    const float* x     = (const float*)d_in[0];
    const float* wq    = (const float*)d_in[1];
    const float* wv    = (const float*)d_in[2];
    const float* bv    = (const float*)d_in[3];
    const float* wt    = (const float*)d_in[4];
    const float* bt    = (const float*)d_in[5];
    const float* gamma = (const float*)d_in[6];
    const float* beta  = (const float*)d_in[7];
    float* out = (float*)d_out;

    const int xa_smem = XA_SMEM_WORDS * 4;
    cudaFuncSetAttribute(xa_kernel,
                         cudaFuncAttributeMaxDynamicSharedMemorySize, xa_smem);

    // x^T fp16 + weight fp16 conversions (also zeroes BN accumulators)
    xt_kernel<<<dim3(NN / 64, CC / 64, BB), 256>>>(x);
    wcvt_kernel<<<(8192 + 65536 + 255) / 256, 256>>>(wq, wv, wt);
    // q^T = x^T wq^T  (weight-tied Q/K), fp16 mma
    convq_tc_kernel<<<dim3(NN / 128, 1, BB), 256>>>();
    // v = wv x + bv, fp16 mma
    convv_tc_kernel<<<dim3(NN / 128, CC / 128, BB), 256>>>(bv);
    // fused energy + row softmax stats
    pass1_kernel<<<dim3(NN / 128, BB), 256>>>();
    // fused E-recompute + softmax + double-norm + x_a^T (1-sync pipeline)
    xa_kernel<<<dim3(NN / 128, BB), 512, xa_smem>>>();
    // t = wt (x - x_a) + bt, fp16 mma, fused BN partial sums
    convt_tc_kernel<<<dim3(NN / 128, CC / 128, BB), 256>>>(bt);
    // BN finalize + fused relu/residual
    bnfin_kernel<<<1, CC>>>();
    final_kernel<<<(BB * CC * NN) / 256, 256>>>(x, gamma, beta, out);
}

// round 12
// speedup vs baseline: 1.0500x; 1.0500x over previous
#include <cuda_runtime.h>
#include <cuda_fp16.h>
#include <cstdint>

#define BB 4
#define CC 256
#define NN 4096
#define DD 64

// Scratch (device globals: allocation-free kernel_launch)
__device__ unsigned g_qh[(size_t)BB * NN * 32];         // 2 MB  q fp16 pairs [b][n][d/2]
__device__ unsigned g_vh[(size_t)BB * CC * (NN / 2)];   // 8 MB  v fp16 pairs [b][c][n/2]
__device__ unsigned g_xth[(size_t)BB * NN * (CC / 2)];  // 8 MB  x^T fp16 pairs [b][n][c/2]
__device__ unsigned g_xaTh[(size_t)BB * NN * (CC / 2)]; // 8 MB  x_a^T fp16 pairs [b][n][c/2]
__device__ unsigned g_wqh[DD * (CC / 2)];               // wq fp16 pairs [o][c/2]
__device__ unsigned g_wvh[CC * (CC / 2)];
__device__ unsigned g_wth[CC * (CC / 2)];
__device__ float g_rowmax[BB * NN];
__device__ float g_rowinv[BB * NN];
__device__ float g_t[(size_t)BB * CC * NN];             // 16 MB
__device__ float g_bnsum[CC];
__device__ float g_bnsum2[CC];
__device__ float g_mean[CC];
__device__ float g_rstd[CC];

// ---------------------------------------------------------------------------
// helpers
// ---------------------------------------------------------------------------
__device__ __forceinline__ void mma_fp16(
    float* c,
    unsigned a0, unsigned a1, unsigned a2, unsigned a3,
    unsigned b0, unsigned b1)
{
    asm volatile(
        "mma.sync.aligned.m16n8k16.row.col.f32.f16.f16.f32 "
        "{%0,%1,%2,%3}, {%4,%5,%6,%7}, {%8,%9}, {%0,%1,%2,%3};\n"
        : "+f"(c[0]), "+f"(c[1]), "+f"(c[2]), "+f"(c[3])
        : "r"(a0), "r"(a1), "r"(a2), "r"(a3), "r"(b0), "r"(b1));
}

__device__ __forceinline__ void ldsm4(
    unsigned& r0, unsigned& r1, unsigned& r2, unsigned& r3, unsigned addr)
{
    asm volatile(
        "ldmatrix.sync.aligned.m8n8.x4.shared.b16 {%0,%1,%2,%3}, [%4];\n"
        : "=r"(r0), "=r"(r1), "=r"(r2), "=r"(r3) : "r"(addr));
}

// A-layout x4 address: matrices (r0..7,k0..3w),(r8..15,k0..3w),(r0..7,+4w),(r8..15,+4w)
__device__ __forceinline__ unsigned adrA(unsigned sb, int Wwords, int stride,
                                         int row0, int kp0, int lane)
{
    int row = row0 + ((lane >> 3) & 1) * 8 + (lane & 7);
    int col = kp0 + ((lane >> 4) & 1) * 4;
    return sb + (unsigned)(Wwords + row * stride + col) * 4u;
}

// B-layout x4 address: matrices (c0..7,k0w),(c0..7,+4w),(c8..15,k0w),(c8..15,+4w)
__device__ __forceinline__ unsigned adrB(unsigned sb, int Wwords, int stride,
                                         int col0, int kp0, int lane)
{
    int row = col0 + ((lane >> 4) & 1) * 8 + (lane & 7);
    int col = kp0 + ((lane >> 3) & 1) * 4;
    return sb + (unsigned)(Wwords + row * stride + col) * 4u;
}

__device__ __forceinline__ void cpa16(unsigned sdst, const void* gsrc)
{
    asm volatile("cp.async.cg.shared.global [%0], [%1], 16;\n"
                 :: "r"(sdst), "l"(gsrc));
}
__device__ __forceinline__ void cpa_commit()
{
    asm volatile("cp.async.commit_group;\n");
}
__device__ __forceinline__ void cpa_wait0()
{
    asm volatile("cp.async.wait_group 0;\n");
}

__device__ __forceinline__ unsigned pack_h2(float a, float b)
{
    __half2 h = __floats2half2_rn(a, b);
    return *reinterpret_cast<unsigned*>(&h);
}

// ---------------------------------------------------------------------------
// xt: transpose + convert x[b][c][n] fp32 -> g_xth[(b*N+n)*128 + c/2] fp16 pairs
// ---------------------------------------------------------------------------
__global__ __launch_bounds__(256) void xt_kernel(const float* __restrict__ x)
{
    const int b  = blockIdx.z;
    const int c0 = blockIdx.y * 64;
    const int n0 = blockIdx.x * 64;
    const float* xb = x + ((size_t)b * CC + c0) * NN + n0;

    __shared__ float sT[64][65];
    const int tid = threadIdx.x;

#pragma unroll
    for (int r = 0; r < 16; r++) {
        int idx = tid + r * 256;
        int c = idx >> 6, n = idx & 63;
        sT[c][n] = xb[(size_t)c * NN + n];
    }
    __syncthreads();
#pragma unroll
    for (int r = 0; r < 8; r++) {
        int idx = tid + r * 256;
        int n = idx >> 5, cp = idx & 31;
        g_xth[((size_t)b * NN + n0 + n) * 128 + c0 / 2 + cp] =
            pack_h2(sT[2 * cp][n], sT[2 * cp + 1][n]);
    }
}

// ---------------------------------------------------------------------------
// wcvt: convert wq/wv/wt to fp16 pairs; also zero BN accumulators
// ---------------------------------------------------------------------------
__global__ __launch_bounds__(256) void wcvt_kernel(
    const float* __restrict__ wq, const float* __restrict__ wv,
    const float* __restrict__ wt)
{
    int idx = blockIdx.x * 256 + threadIdx.x;
    if (idx < 256) { g_bnsum[idx] = 0.f; g_bnsum2[idx] = 0.f; }
    if (idx < 8192) {
        float2 f = *reinterpret_cast<const float2*>(&wq[idx * 2]);
        g_wqh[idx] = pack_h2(f.x, f.y);
    } else if (idx < 8192 + 32768) {
        int i = idx - 8192;
        float2 f = *reinterpret_cast<const float2*>(&wv[i * 2]);
        g_wvh[i] = pack_h2(f.x, f.y);
    } else if (idx < 8192 + 65536) {
        int i = idx - 8192 - 32768;
        float2 f = *reinterpret_cast<const float2*>(&wt[i * 2]);
        g_wth[i] = pack_h2(f.x, f.y);
    }
}

// ---------------------------------------------------------------------------
// convq_tc: q^T[n][o] = x^T[n][:] . wq[o][:]  -> g_qh[(b*N+n)*32 + o/2]
// ---------------------------------------------------------------------------
__global__ __launch_bounds__(256) void convq_tc_kernel()
{
    const int b  = blockIdx.z;
    const int n0 = blockIdx.x * 128;
    const unsigned* xth = g_xth + (size_t)b * NN * 128;

    __shared__ unsigned sA[128][36];
    __shared__ unsigned sB[64][36];

    const int tid = threadIdx.x;
    const int lane = tid & 31, wid = tid >> 5;
    const int wm = wid >> 2, wn = wid & 3;
    const int gp = lane >> 2, tg = lane & 3;
    const unsigned sbA = (unsigned)__cvta_generic_to_shared(&sA[0][0]);
    const unsigned sbB = (unsigned)__cvta_generic_to_shared(&sB[0][0]);

    float acc[4][2][4] = {};

    for (int ks = 0; ks < 4; ks++) {
        int kp0g = ks * 32;
        __syncthreads();
#pragma unroll
        for (int r = 0; r < 16; r++) {
            int idx = tid + r * 256;
            int row = idx >> 5, kp = idx & 31;
            sA[row][kp] = xth[(size_t)(n0 + row) * 128 + kp0g + kp];
        }
#pragma unroll
        for (int r = 0; r < 8; r++) {
            int idx = tid + r * 256;
            int row = idx >> 5, kp = idx & 31;
            sB[row][kp] = g_wqh[(size_t)row * 128 + kp0g + kp];
        }
        __syncthreads();
#pragma unroll
        for (int kk = 0; kk < 4; kk++) {
            int kp0 = kk * 8;
            unsigned a[4][4], bf[2][2];
#pragma unroll
            for (int i = 0; i < 4; i++)
                ldsm4(a[i][0], a[i][1], a[i][2], a[i][3],
                      adrA(sbA, 0, 36, wm * 64 + i * 16, kp0, lane));
            ldsm4(bf[0][0], bf[0][1], bf[1][0], bf[1][1],
                  adrB(sbB, 0, 36, wn * 16, kp0, lane));
#pragma unroll
            for (int i = 0; i < 4; i++)
#pragma unroll
                for (int j = 0; j < 2; j++)
                    mma_fp16(acc[i][j], a[i][0], a[i][1], a[i][2], a[i][3],
                             bf[j][0], bf[j][1]);
        }
    }

#pragma unroll
    for (int i = 0; i < 4; i++) {
        int n = n0 + wm * 64 + i * 16 + gp;
#pragma unroll
        for (int j = 0; j < 2; j++) {
            int op = wn * 8 + j * 4 + tg;
            g_qh[((size_t)b * NN + n) * 32 + op]     = pack_h2(acc[i][j][0], acc[i][j][1]);
            g_qh[((size_t)b * NN + n + 8) * 32 + op] = pack_h2(acc[i][j][2], acc[i][j][3]);
        }
    }
}

// ---------------------------------------------------------------------------
// convv_tc: v[o][n] = wv[o][:] . x^T[n][:] + bv  -> g_vh[(b*C+o)*(N/2) + n/2]
// ---------------------------------------------------------------------------
__global__ __launch_bounds__(256) void convv_tc_kernel(const float* __restrict__ bias)
{
    const int b  = blockIdx.z;
    const int o0 = blockIdx.y * 128;
    const int n0 = blockIdx.x * 128;
    const unsigned* xth = g_xth + (size_t)b * NN * 128;

    __shared__ unsigned sA[128][36];
    __shared__ unsigned sB[128][36];

    const int tid = threadIdx.x;
    const int lane = tid & 31, wid = tid >> 5;
    const int wm = wid >> 2, wn = wid & 3;
    const int gp = lane >> 2, tg = lane & 3;
    const unsigned sbA = (unsigned)__cvta_generic_to_shared(&sA[0][0]);
    const unsigned sbB = (unsigned)__cvta_generic_to_shared(&sB[0][0]);

    float acc[4][4][4] = {};

    for (int ks = 0; ks < 4; ks++) {
        int kp0g = ks * 32;
        __syncthreads();
#pragma unroll
        for (int r = 0; r < 16; r++) {
            int idx = tid + r * 256;
            int row = idx >> 5, kp = idx & 31;
            sA[row][kp] = g_wvh[(size_t)(o0 + row) * 128 + kp0g + kp];
            sB[row][kp] = xth[(size_t)(n0 + row) * 128 + kp0g + kp];
        }
        __syncthreads();
#pragma unroll
        for (int kk = 0; kk < 4; kk++) {
            int kp0 = kk * 8;
            unsigned a[4][4], bf[4][2];
#pragma unroll
            for (int i = 0; i < 4; i++)
                ldsm4(a[i][0], a[i][1], a[i][2], a[i][3],
                      adrA(sbA, 0, 36, wm * 64 + i * 16, kp0, lane));
            ldsm4(bf[0][0], bf[0][1], bf[1][0], bf[1][1],
                  adrB(sbB, 0, 36, wn * 32, kp0, lane));
            ldsm4(bf[2][0], bf[2][1], bf[3][0], bf[3][1],
                  adrB(sbB, 0, 36, wn * 32 + 16, kp0, lane));
#pragma unroll
            for (int i = 0; i < 4; i++)
#pragma unroll
                for (int j = 0; j < 4; j++)
                    mma_fp16(acc[i][j], a[i][0], a[i][1], a[i][2], a[i][3],
                             bf[j][0], bf[j][1]);
        }
    }

#pragma unroll
    for (int i = 0; i < 4; i++) {
        int o = o0 + wm * 64 + i * 16 + gp;
        float b0 = bias[o], b1 = bias[o + 8];
#pragma unroll
        for (int j = 0; j < 4; j++) {
            int np = (n0 + wn * 32 + j * 8 + 2 * tg) / 2;
            g_vh[((size_t)b * CC + o) * (NN / 2) + np] =
                pack_h2(acc[i][j][0] + b0, acc[i][j][1] + b0);
            g_vh[((size_t)b * CC + o + 8) * (NN / 2) + np] =
                pack_h2(acc[i][j][2] + b1, acc[i][j][3] + b1);
        }
    }
}

// ---------------------------------------------------------------------------
// convt_tc: t[o][n] = wt[o][:] . (x^T - x_a^T)[n][:] + bt  -> g_t fp32
// Fused BN partial sums -> g_bnsum/g_bnsum2 (atomics).
// ---------------------------------------------------------------------------
__global__ __launch_bounds__(256) void convt_tc_kernel(const float* __restrict__ bias)
{
    const int b  = blockIdx.z;
    const int o0 = blockIdx.y * 128;
    const int n0 = blockIdx.x * 128;
    const unsigned* xth  = g_xth  + (size_t)b * NN * 128;
    const unsigned* xath = g_xaTh + (size_t)b * NN * 128;

    __shared__ unsigned sA[128][36];
    __shared__ unsigned sB[128][36];
    __shared__ float sS[128], sS2[128];

    const int tid = threadIdx.x;
    const int lane = tid & 31, wid = tid >> 5;
    const int wm = wid >> 2, wn = wid & 3;
    const int gp = lane >> 2, tg = lane & 3;
    const unsigned sbA = (unsigned)__cvta_generic_to_shared(&sA[0][0]);
    const unsigned sbB = (unsigned)__cvta_generic_to_shared(&sB[0][0]);

    if (tid < 128) { sS[tid] = 0.f; sS2[tid] = 0.f; }

    float acc[4][4][4] = {};

    for (int ks = 0; ks < 4; ks++) {
        int kp0g = ks * 32;
        __syncthreads();
#pragma unroll
        for (int r = 0; r < 16; r++) {
            int idx = tid + r * 256;
            int row = idx >> 5, kp = idx & 31;
            sA[row][kp] = g_wth[(size_t)(o0 + row) * 128 + kp0g + kp];
            size_t gi = (size_t)(n0 + row) * 128 + kp0g + kp;
            __half2 xv = *reinterpret_cast<const __half2*>(&xth[gi]);
            __half2 av = *reinterpret_cast<const __half2*>(&xath[gi]);
            __half2 d = __hsub2(xv, av);
            sB[row][kp] = *reinterpret_cast<unsigned*>(&d);
        }
        __syncthreads();
#pragma unroll
        for (int kk = 0; kk < 4; kk++) {
            int kp0 = kk * 8;
            unsigned a[4][4], bf[4][2];
#pragma unroll
            for (int i = 0; i < 4; i++)
                ldsm4(a[i][0], a[i][1], a[i][2], a[i][3],
                      adrA(sbA, 0, 36, wm * 64 + i * 16, kp0, lane));
            ldsm4(bf[0][0], bf[0][1], bf[1][0], bf[1][1],
                  adrB(sbB, 0, 36, wn * 32, kp0, lane));
            ldsm4(bf[2][0], bf[2][1], bf[3][0], bf[3][1],
                  adrB(sbB, 0, 36, wn * 32 + 16, kp0, lane));
#pragma unroll
            for (int i = 0; i < 4; i++)
#pragma unroll
                for (int j = 0; j < 4; j++)
                    mma_fp16(acc[i][j], a[i][0], a[i][1], a[i][2], a[i][3],
                             bf[j][0], bf[j][1]);
        }
    }

#pragma unroll
    for (int i = 0; i < 4; i++) {
        int ol = wm * 64 + i * 16 + gp;
        int o = o0 + ol;
        float b0 = bias[o], b1 = bias[o + 8];
        float sa = 0.f, sa2 = 0.f, sb = 0.f, sb2 = 0.f;
#pragma unroll
        for (int j = 0; j < 4; j++) {
            int n = n0 + wn * 32 + j * 8 + 2 * tg;
            float t00 = acc[i][j][0] + b0, t01 = acc[i][j][1] + b0;
            float t10 = acc[i][j][2] + b1, t11 = acc[i][j][3] + b1;
            sa += t00 + t01;  sa2 += t00 * t00 + t01 * t01;
            sb += t10 + t11;  sb2 += t10 * t10 + t11 * t11;
            *reinterpret_cast<float2*>(&g_t[((size_t)b * CC + o) * NN + n]) =
                make_float2(t00, t01);
            *reinterpret_cast<float2*>(&g_t[((size_t)b * CC + o + 8) * NN + n]) =
                make_float2(t10, t11);
        }
#pragma unroll
        for (int off = 1; off <= 2; off <<= 1) {
            sa  += __shfl_xor_sync(0xffffffffu, sa,  off);
            sa2 += __shfl_xor_sync(0xffffffffu, sa2, off);
            sb  += __shfl_xor_sync(0xffffffffu, sb,  off);
            sb2 += __shfl_xor_sync(0xffffffffu, sb2, off);
        }
        if (tg == 0) {
            atomicAdd(&sS[ol], sa);      atomicAdd(&sS2[ol], sa2);
            atomicAdd(&sS[ol + 8], sb);  atomicAdd(&sS2[ol + 8], sb2);
        }
    }
    __syncthreads();
    if (tid < 128) {
        atomicAdd(&g_bnsum[o0 + tid], sS[tid]);
        atomicAdd(&g_bnsum2[o0 + tid], sS2[tid]);
    }
}

// ---------------------------------------------------------------------------
// bnfin: mean/rstd from accumulated sums (1 block)
// ---------------------------------------------------------------------------
__global__ void bnfin_kernel()
{
    int c = threadIdx.x;
    const float invM = 1.f / (float)(BB * NN);
    float mean = g_bnsum[c] * invM;
    float var = g_bnsum2[c] * invM - mean * mean;
    g_mean[c] = mean;
    g_rstd[c] = rsqrtf(var + 1e-5f);
}

// ---------------------------------------------------------------------------
// pass1: fused energy + row softmax stats (flash pass).
// ---------------------------------------------------------------------------
__global__ __launch_bounds__(256) void pass1_kernel()
{
    const int b  = blockIdx.y;
    const int n0 = blockIdx.x * 128;
    const unsigned* qh = g_qh + (size_t)b * NN * 32;

    __shared__ unsigned sA[128][36];
    __shared__ unsigned sB[128][36];
    __shared__ float2 sMrg[4][128];

    const int tid = threadIdx.x;
    const int lane = tid & 31, wid = tid >> 5;
    const int wm = wid >> 2, wn = wid & 3;
    const int gp = lane >> 2, tg = lane & 3;
    const unsigned sbA = (unsigned)__cvta_generic_to_shared(&sA[0][0]);
    const unsigned sbB = (unsigned)__cvta_generic_to_shared(&sB[0][0]);

#pragma unroll
    for (int r = 0; r < 16; r++) {
        int idx = tid + r * 256;
        int row = idx >> 5, kp = idx & 31;
        sA[row][kp] = qh[(size_t)(n0 + row) * 32 + kp];
    }

    float rmax[8], rsum[8];
#pragma unroll
    for (int i = 0; i < 8; i++) { rmax[i] = -1e30f; rsum[i] = 0.f; }

    for (int m0 = 0; m0 < NN; m0 += 128) {
        __syncthreads();
#pragma unroll
        for (int r = 0; r < 16; r++) {
            int idx = tid + r * 256;
            int row = idx >> 5, kp = idx & 31;
            sB[row][kp] = qh[(size_t)(m0 + row) * 32 + kp];
        }
        __syncthreads();

        float acc[4][4][4] = {};
#pragma unroll
        for (int ks = 0; ks < 4; ks++) {
            int kp0 = ks * 8;
            unsigned a[4][4], bf[4][2];
#pragma unroll
            for (int i = 0; i < 4; i++)
                ldsm4(a[i][0], a[i][1], a[i][2], a[i][3],
                      adrA(sbA, 0, 36, wm * 64 + i * 16, kp0, lane));
            ldsm4(bf[0][0], bf[0][1], bf[1][0], bf[1][1],
                  adrB(sbB, 0, 36, wn * 32, kp0, lane));
            ldsm4(bf[2][0], bf[2][1], bf[3][0], bf[3][1],
                  adrB(sbB, 0, 36, wn * 32 + 16, kp0, lane));
#pragma unroll
            for (int i = 0; i < 4; i++)
#pragma unroll
                for (int j = 0; j < 4; j++)
                    mma_fp16(acc[i][j], a[i][0], a[i][1], a[i][2], a[i][3],
                             bf[j][0], bf[j][1]);
        }

#pragma unroll
        for (int i = 0; i < 4; i++) {
            float m0v = -1e30f, m1v = -1e30f;
#pragma unroll
            for (int j = 0; j < 4; j++) {
                m0v = fmaxf(m0v, fmaxf(acc[i][j][0], acc[i][j][1]));
                m1v = fmaxf(m1v, fmaxf(acc[i][j][2], acc[i][j][3]));
            }
            m0v = fmaxf(m0v, __shfl_xor_sync(0xffffffffu, m0v, 1));
            m0v = fmaxf(m0v, __shfl_xor_sync(0xffffffffu, m0v, 2));
            m1v = fmaxf(m1v, __shfl_xor_sync(0xffffffffu, m1v, 1));
            m1v = fmaxf(m1v, __shfl_xor_sync(0xffffffffu, m1v, 2));
            float nm0 = fmaxf(rmax[2 * i],     m0v);
            float nm1 = fmaxf(rmax[2 * i + 1], m1v);
            float s0 = 0.f, s1 = 0.f;
#pragma unroll
            for (int j = 0; j < 4; j++) {
                s0 += __expf(acc[i][j][0] - nm0) + __expf(acc[i][j][1] - nm0);
                s1 += __expf(acc[i][j][2] - nm1) + __expf(acc[i][j][3] - nm1);
            }
            s0 += __shfl_xor_sync(0xffffffffu, s0, 1);
            s0 += __shfl_xor_sync(0xffffffffu, s0, 2);
            s1 += __shfl_xor_sync(0xffffffffu, s1, 1);
            s1 += __shfl_xor_sync(0xffffffffu, s1, 2);
            rsum[2 * i]     = rsum[2 * i]     * __expf(rmax[2 * i]     - nm0) + s0;
            rsum[2 * i + 1] = rsum[2 * i + 1] * __expf(rmax[2 * i + 1] - nm1) + s1;
            rmax[2 * i]     = nm0;
            rmax[2 * i + 1] = nm1;
        }
    }

    if (tg == 0) {
#pragma unroll
        for (int i = 0; i < 4; i++) {
            int row = wm * 64 + i * 16 + gp;
            sMrg[wn][row]     = make_float2(rmax[2 * i],     rsum[2 * i]);
            sMrg[wn][row + 8] = make_float2(rmax[2 * i + 1], rsum[2 * i + 1]);
        }
    }
    __syncthreads();
    if (tid < 128) {
        float2 v0 = sMrg[0][tid], v1 = sMrg[1][tid];
        float2 v2 = sMrg[2][tid], v3 = sMrg[3][tid];
        float M = fmaxf(fmaxf(v0.x, v1.x), fmaxf(v2.x, v3.x));
        float S = v0.y * __expf(v0.x - M) + v1.y * __expf(v1.x - M)
                + v2.y * __expf(v2.x - M) + v3.y * __expf(v3.x - M);
        g_rowmax[b * NN + n0 + tid] = M;
        g_rowinv[b * NN + n0 + tid] = 1.f / S;
    }
}

// ---------------------------------------------------------------------------
// xa: fused E-recompute + P + colsum + x_a^T, single-sync software pipeline,
// ldmatrix fragment loads.
// ---------------------------------------------------------------------------
#define XA_W_SVH 0
#define XA_W_SQM (2 * 256 * 36)
#define XA_W_SQN (XA_W_SQM + 128 * 36)
#define XA_W_SPH (XA_W_SQN + 2 * 64 * 36)
#define XA_W_COL (XA_W_SPH + 2 * 128 * 36)
#define XA_SMEM_WORDS (XA_W_COL + 128)

__global__ __launch_bounds__(512, 1) void xa_kernel()
{
    const int b  = blockIdx.y;
    const int m0 = blockIdx.x * 128;
    const unsigned* vbh = g_vh + (size_t)b * CC * (NN / 2);
    const float* rmx = g_rowmax + b * NN;
    const float* rin = g_rowinv + b * NN;
    const unsigned* qh = g_qh + (size_t)b * NN * 32;

    extern __shared__ unsigned shm[];
    unsigned (*sQm)[36] = reinterpret_cast<unsigned(*)[36]>(shm + XA_W_SQM);
    float* sCol = reinterpret_cast<float*>(shm + XA_W_COL);
    const unsigned sbase = (unsigned)__cvta_generic_to_shared(shm);

    const int tid = threadIdx.x;
    const int lane = tid & 31, wid = tid >> 5;
    const int gp = lane >> 2, tg = lane & 3;
    const int nh = wid & 3, mh = wid >> 2;       // mma1 roles (4x4)
    const int wm = wid >> 2, wn = wid & 3;       // mma2 roles

    // q_m tile (constant for the block)
#pragma unroll
    for (int r = 0; r < 8; r++) {
        int idx = tid + r * 512;
        int row = idx >> 5, kp = idx & 31;
        sQm[row][kp] = qh[(size_t)(m0 + row) * 32 + kp];
    }
    if (tid < 128) sCol[tid] = 0.f;

    auto issue_V = [&](int chunk) {
        int buf = chunk & 1;
        int np0 = chunk * 32;
#pragma unroll
        for (int t = 0; t < 4; t++) {
            int idx = tid + t * 512;
            int row = idx >> 3, seg = idx & 7;
            unsigned dst = sbase + (XA_W_SVH + buf * 256 * 36 + row * 36 + seg * 4) * 4;
            cpa16(dst, vbh + (size_t)row * (NN / 2) + np0 + seg * 4);
        }
    };
    auto issue_Qn = [&](int chunk) {
        int buf = chunk & 1;
        int row = tid >> 3, seg = tid & 7;
        unsigned dst = sbase + (XA_W_SQN + buf * 64 * 36 + row * 36 + seg * 4) * 4;
        cpa16(dst, qh + (size_t)(chunk * 64 + row) * 32 + seg * 4);
    };

    // mma1 for chunk: compute E^chunk and write P into sPh[chunk&1]
    auto do_mma1 = [&](int chunk) {
        int buf = chunk & 1;
        int WQn = XA_W_SQN + buf * 64 * 36;
        __half (*sPhB)[72] = reinterpret_cast<__half(*)[72]>(shm + XA_W_SPH + buf * 128 * 36);
        float e[4][4] = {};
#pragma unroll
        for (int ks = 0; ks < 4; ks++) {
            int kp0 = ks * 8;
            unsigned a0, a1, a2, a3, bf[4][2];
            ldsm4(a0, a1, a2, a3, adrA(sbase, WQn, 36, nh * 16, kp0, lane));
            ldsm4(bf[0][0], bf[0][1], bf[1][0], bf[1][1],
                  adrB(sbase, XA_W_SQM, 36, mh * 32, kp0, lane));
            ldsm4(bf[2][0], bf[2][1], bf[3][0], bf[3][1],
                  adrB(sbase, XA_W_SQM, 36, mh * 32 + 16, kp0, lane));
#pragma unroll
            for (int j = 0; j < 4; j++)
                mma_fp16(e[j], a0, a1, a2, a3, bf[j][0], bf[j][1]);
        }
        int r0 = chunk * 64 + nh * 16 + gp;
        float mx0 = __ldg(&rmx[r0]),     iv0 = __ldg(&rin[r0]);
        float mx1 = __ldg(&rmx[r0 + 8]), iv1 = __ldg(&rin[r0 + 8]);
        int nr0 = nh * 16 + gp, nr1 = nr0 + 8;
#pragma unroll
        for (int j = 0; j < 4; j++) {
            int cb = mh * 32 + j * 8 + 2 * tg;
            sPhB[cb][nr0]     = __float2half(__expf(e[j][0] - mx0) * iv0);
            sPhB[cb + 1][nr0] = __float2half(__expf(e[j][1] - mx0) * iv0);
            sPhB[cb][nr1]     = __float2half(__expf(e[j][2] - mx1) * iv1);
            sPhB[cb + 1][nr1] = __float2half(__expf(e[j][3] - mx1) * iv1);
        }
    };

    // prologue
    issue_V(0); issue_V(1); issue_Qn(0); issue_Qn(1); cpa_commit();
    cpa_wait0();
    __syncthreads();

    do_mma1(0);            // P(0)
    __syncthreads();
    issue_Qn(2); cpa_commit();

    float acc[2][8][4] = {};

    for (int i = 0; i < 64; i++) {
        const int buf = i & 1;
        int WV = XA_W_SVH + buf * 256 * 36;
        int WP = XA_W_SPH + buf * 128 * 36;
        __half (*sPhB)[72] = reinterpret_cast<__half(*)[72]>(shm + WP);

        // 1. mma1(i+1) into the other P buffer
        if (i < 63)
            do_mma1(i + 1);

        // 2. colsum(i)
        {
            int m = tid & 127, seg = tid >> 7;
            const __half2* prow = reinterpret_cast<const __half2*>(sPhB[m]);
            float cs = 0.f;
#pragma unroll
            for (int k = 0; k < 8; k++) {
                float2 f = __half22float2(prow[seg * 8 + k]);
                cs += f.x + f.y;
            }
            atomicAdd(&sCol[m], cs);
        }

        // 3. mma2(i): acc[m,c] += P[m][n] * V[c][n]
#pragma unroll
        for (int ks = 0; ks < 4; ks++) {
            int kp0 = ks * 8;
            unsigned pa[2][4], bf[8][2];
#pragma unroll
            for (int ii = 0; ii < 2; ii++)
                ldsm4(pa[ii][0], pa[ii][1], pa[ii][2], pa[ii][3],
                      adrA(sbase, WP, 36, wm * 32 + ii * 16, kp0, lane));
#pragma unroll
            for (int g = 0; g < 4; g++)
                ldsm4(bf[2 * g][0], bf[2 * g][1], bf[2 * g + 1][0], bf[2 * g + 1][1],
                      adrB(sbase, WV, 36, wn * 64 + g * 16, kp0, lane));
#pragma unroll
            for (int ii = 0; ii < 2; ii++)
#pragma unroll
                for (int j = 0; j < 8; j++)
                    mma_fp16(acc[ii][j], pa[ii][0], pa[ii][1], pa[ii][2], pa[ii][3],
                             bf[j][0], bf[j][1]);
        }

        // 4. wait; 5. single sync; 6. next loads
        cpa_wait0();
        __syncthreads();
        if (i + 2 < 64) issue_V(i + 2);
        if (i + 3 < 64) issue_Qn(i + 3);
        cpa_commit();
    }

    // epilogue: x_a^T[m][c] = acc * inv(m); write fp16 pairs (c contig)
#pragma unroll
    for (int ii = 0; ii < 2; ii++) {
        int mr = wm * 32 + ii * 16 + gp;
        float i0 = 1.f / (1e-9f + sCol[mr]);
        float i1 = 1.f / (1e-9f + sCol[mr + 8]);
        size_t r0 = ((size_t)b * NN + m0 + mr) * 128;
        size_t r1 = r0 + 8 * 128;
#pragma unroll
        for (int j = 0; j < 8; j++) {
            int cp = wn * 32 + j * 4 + tg;
            g_xaTh[r0 + cp] = pack_h2(acc[ii][j][0] * i0, acc[ii][j][1] * i0);
            g_xaTh[r1 + cp] = pack_h2(acc[ii][j][2] * i1, acc[ii][j][3] * i1);
        }
    }
}

// ---------------------------------------------------------------------------
// Final: out = x + relu(gamma * (t - mean) * rstd + beta)
// ---------------------------------------------------------------------------
__global__ __launch_bounds__(256) void final_kernel(
    const float* __restrict__ x, const float* __restrict__ gamma,
    const float* __restrict__ beta, float* __restrict__ out)
{
    size_t i = (size_t)blockIdx.x * 256 + threadIdx.x;
    int c = (int)((i >> 12) & 255);
    float t = g_t[i];
    float th = (t - g_mean[c]) * g_rstd[c];
    float r = fmaxf(0.f, gamma[c] * th + beta[c]);
    out[i] = x[i] + r;
}

// ---------------------------------------------------------------------------
extern "C" void kernel_launch(void* const* d_in, const int* in_sizes, int n_in,
                              void* d_out, int out_size)
{
    const float* x     = (const float*)d_in[0];
    const float* wq    = (const float*)d_in[1];
    const float* wv    = (const float*)d_in[2];
    const float* bv    = (const float*)d_in[3];
    const float* wt    = (const float*)d_in[4];
    const float* bt    = (const float*)d_in[5];
    const float* gamma = (const float*)d_in[6];
    const float* beta  = (const float*)d_in[7];
    float* out = (float*)d_out;

    const int xa_smem = XA_SMEM_WORDS * 4;
    cudaFuncSetAttribute(xa_kernel,
                         cudaFuncAttributeMaxDynamicSharedMemorySize, xa_smem);

    // x^T fp16 + weight fp16 conversions (also zeroes BN accumulators)
    xt_kernel<<<dim3(NN / 64, CC / 64, BB), 256>>>(x);
    wcvt_kernel<<<(8192 + 65536 + 255) / 256, 256>>>(wq, wv, wt);
    // q^T = x^T wq^T  (weight-tied Q/K), fp16 mma
    convq_tc_kernel<<<dim3(NN / 128, 1, BB), 256>>>();
    // v = wv x + bv, fp16 mma
    convv_tc_kernel<<<dim3(NN / 128, CC / 128, BB), 256>>>(bv);
    // fused energy + row softmax stats
    pass1_kernel<<<dim3(NN / 128, BB), 256>>>();
    // fused E-recompute + softmax + double-norm + x_a^T (ldmatrix pipeline)
    xa_kernel<<<dim3(NN / 128, BB), 512, xa_smem>>>();
    // t = wt (x - x_a) + bt, fp16 mma, fused BN partial sums
    convt_tc_kernel<<<dim3(NN / 128, CC / 128, BB), 256>>>(bt);
    // BN finalize + fused relu/residual
    bnfin_kernel<<<1, CC>>>();
    final_kernel<<<(BB * CC * NN) / 256, 256>>>(x, gamma, beta, out);
}

// round 13
// speedup vs baseline: 1.0564x; 1.0061x over previous
#include <cuda_runtime.h>
#include <cuda_fp16.h>
#include <cstdint>

#define BB 4
#define CC 256
#define NN 4096
#define DD 64

// Scratch (device globals: allocation-free kernel_launch)
__device__ unsigned g_qh[(size_t)BB * NN * 32];         // 2 MB  q fp16 pairs [b][n][d/2]
__device__ unsigned g_vh[(size_t)BB * CC * (NN / 2)];   // 8 MB  v fp16 pairs [b][c][n/2]
__device__ unsigned g_xth[(size_t)BB * NN * (CC / 2)];  // 8 MB  x^T fp16 pairs [b][n][c/2]
__device__ unsigned g_xaTh[(size_t)BB * NN * (CC / 2)]; // 8 MB  x_a^T fp16 pairs [b][n][c/2]
__device__ unsigned g_wqh[DD * (CC / 2)];               // wq fp16 pairs [o][c/2]
__device__ unsigned g_wvh[CC * (CC / 2)];
__device__ unsigned g_wth[CC * (CC / 2)];
__device__ float g_rowmax[BB * NN];
__device__ float g_rowinv[BB * NN];
__device__ float g_t[(size_t)BB * CC * NN];             // 16 MB
__device__ float g_bnsum[CC];
__device__ float g_bnsum2[CC];
__device__ float g_mean[CC];
__device__ float g_rstd[CC];

// ---------------------------------------------------------------------------
// helpers
// ---------------------------------------------------------------------------
__device__ __forceinline__ void mma_fp16(
    float* c,
    unsigned a0, unsigned a1, unsigned a2, unsigned a3,
    unsigned b0, unsigned b1)
{
    asm volatile(
        "mma.sync.aligned.m16n8k16.row.col.f32.f16.f16.f32 "
        "{%0,%1,%2,%3}, {%4,%5,%6,%7}, {%8,%9}, {%0,%1,%2,%3};\n"
        : "+f"(c[0]), "+f"(c[1]), "+f"(c[2]), "+f"(c[3])
        : "r"(a0), "r"(a1), "r"(a2), "r"(a3), "r"(b0), "r"(b1));
}

__device__ __forceinline__ void ldsm4(
    unsigned& r0, unsigned& r1, unsigned& r2, unsigned& r3, unsigned addr)
{
    asm volatile(
        "ldmatrix.sync.aligned.m8n8.x4.shared.b16 {%0,%1,%2,%3}, [%4];\n"
        : "=r"(r0), "=r"(r1), "=r"(r2), "=r"(r3) : "r"(addr));
}

// A-layout x4 address: matrices (r0..7,k0..3w),(r8..15,k0..3w),(r0..7,+4w),(r8..15,+4w)
__device__ __forceinline__ unsigned adrA(unsigned sb, int Wwords, int stride,
                                         int row0, int kp0, int lane)
{
    int row = row0 + ((lane >> 3) & 1) * 8 + (lane & 7);
    int col = kp0 + ((lane >> 4) & 1) * 4;
    return sb + (unsigned)(Wwords + row * stride + col) * 4u;
}

// B-layout x4 address: matrices (c0..7,k0w),(c0..7,+4w),(c8..15,k0w),(c8..15,+4w)
__device__ __forceinline__ unsigned adrB(unsigned sb, int Wwords, int stride,
                                         int col0, int kp0, int lane)
{
    int row = col0 + ((lane >> 4) & 1) * 8 + (lane & 7);
    int col = kp0 + ((lane >> 3) & 1) * 4;
    return sb + (unsigned)(Wwords + row * stride + col) * 4u;
}

__device__ __forceinline__ void cpa16(unsigned sdst, const void* gsrc)
{
    asm volatile("cp.async.cg.shared.global [%0], [%1], 16;\n"
                 :: "r"(sdst), "l"(gsrc));
}
__device__ __forceinline__ void cpa_commit()
{
    asm volatile("cp.async.commit_group;\n");
}
__device__ __forceinline__ void cpa_wait0()
{
    asm volatile("cp.async.wait_group 0;\n");
}

__device__ __forceinline__ unsigned pack_h2(float a, float b)
{
    __half2 h = __floats2half2_rn(a, b);
    return *reinterpret_cast<unsigned*>(&h);
}

// ---------------------------------------------------------------------------
// xt: transpose + convert x[b][c][n] fp32 -> g_xth[(b*N+n)*128 + c/2] fp16 pairs
// ---------------------------------------------------------------------------
__global__ __launch_bounds__(256) void xt_kernel(const float* __restrict__ x)
{
    const int b  = blockIdx.z;
    const int c0 = blockIdx.y * 64;
    const int n0 = blockIdx.x * 64;
    const float* xb = x + ((size_t)b * CC + c0) * NN + n0;

    __shared__ float sT[64][65];
    const int tid = threadIdx.x;

#pragma unroll
    for (int r = 0; r < 16; r++) {
        int idx = tid + r * 256;
        int c = idx >> 6, n = idx & 63;
        sT[c][n] = xb[(size_t)c * NN + n];
    }
    __syncthreads();
#pragma unroll
    for (int r = 0; r < 8; r++) {
        int idx = tid + r * 256;
        int n = idx >> 5, cp = idx & 31;
        g_xth[((size_t)b * NN + n0 + n) * 128 + c0 / 2 + cp] =
            pack_h2(sT[2 * cp][n], sT[2 * cp + 1][n]);
    }
}

// ---------------------------------------------------------------------------
// wcvt: convert wq/wv/wt to fp16 pairs; also zero BN accumulators
// ---------------------------------------------------------------------------
__global__ __launch_bounds__(256) void wcvt_kernel(
    const float* __restrict__ wq, const float* __restrict__ wv,
    const float* __restrict__ wt)
{
    int idx = blockIdx.x * 256 + threadIdx.x;
    if (idx < 256) { g_bnsum[idx] = 0.f; g_bnsum2[idx] = 0.f; }
    if (idx < 8192) {
        float2 f = *reinterpret_cast<const float2*>(&wq[idx * 2]);
        g_wqh[idx] = pack_h2(f.x, f.y);
    } else if (idx < 8192 + 32768) {
        int i = idx - 8192;
        float2 f = *reinterpret_cast<const float2*>(&wv[i * 2]);
        g_wvh[i] = pack_h2(f.x, f.y);
    } else if (idx < 8192 + 65536) {
        int i = idx - 8192 - 32768;
        float2 f = *reinterpret_cast<const float2*>(&wt[i * 2]);
        g_wth[i] = pack_h2(f.x, f.y);
    }
}

// ---------------------------------------------------------------------------
// convq_tc: q^T[n][o] = x^T[n][:] . wq[o][:]  -> g_qh[(b*N+n)*32 + o/2]
// (scalar LDS fragment loads — higher MLP wins at 8 warps/CTA)
// ---------------------------------------------------------------------------
__global__ __launch_bounds__(256) void convq_tc_kernel()
{
    const int b  = blockIdx.z;
    const int n0 = blockIdx.x * 128;
    const unsigned* xth = g_xth + (size_t)b * NN * 128;

    __shared__ unsigned sA[128][36];
    __shared__ unsigned sB[64][36];

    const int tid = threadIdx.x;
    const int lane = tid & 31, wid = tid >> 5;
    const int wm = wid >> 2, wn = wid & 3;
    const int gp = lane >> 2, tg = lane & 3;

    float acc[4][2][4] = {};

    for (int ks = 0; ks < 4; ks++) {
        int kp0g = ks * 32;
        __syncthreads();
#pragma unroll
        for (int r = 0; r < 16; r++) {
            int idx = tid + r * 256;
            int row = idx >> 5, kp = idx & 31;
            sA[row][kp] = xth[(size_t)(n0 + row) * 128 + kp0g + kp];
        }
#pragma unroll
        for (int r = 0; r < 8; r++) {
            int idx = tid + r * 256;
            int row = idx >> 5, kp = idx & 31;
            sB[row][kp] = g_wqh[(size_t)row * 128 + kp0g + kp];
        }
        __syncthreads();
#pragma unroll
        for (int kk = 0; kk < 4; kk++) {
            int kp0 = kk * 8;
            unsigned a[4][4], bf[2][2];
#pragma unroll
            for (int i = 0; i < 4; i++) {
                int row = wm * 64 + i * 16 + gp;
                a[i][0] = sA[row][kp0 + tg];
                a[i][1] = sA[row + 8][kp0 + tg];
                a[i][2] = sA[row][kp0 + 4 + tg];
                a[i][3] = sA[row + 8][kp0 + 4 + tg];
            }
#pragma unroll
            for (int j = 0; j < 2; j++) {
                int col = wn * 16 + j * 8 + gp;
                bf[j][0] = sB[col][kp0 + tg];
                bf[j][1] = sB[col][kp0 + 4 + tg];
            }
#pragma unroll
            for (int i = 0; i < 4; i++)
#pragma unroll
                for (int j = 0; j < 2; j++)
                    mma_fp16(acc[i][j], a[i][0], a[i][1], a[i][2], a[i][3],
                             bf[j][0], bf[j][1]);
        }
    }

#pragma unroll
    for (int i = 0; i < 4; i++) {
        int n = n0 + wm * 64 + i * 16 + gp;
#pragma unroll
        for (int j = 0; j < 2; j++) {
            int op = wn * 8 + j * 4 + tg;
            g_qh[((size_t)b * NN + n) * 32 + op]     = pack_h2(acc[i][j][0], acc[i][j][1]);
            g_qh[((size_t)b * NN + n + 8) * 32 + op] = pack_h2(acc[i][j][2], acc[i][j][3]);
        }
    }
}

// ---------------------------------------------------------------------------
// convv_tc: v[o][n] = wv[o][:] . x^T[n][:] + bv  (scalar LDS)
// ---------------------------------------------------------------------------
__global__ __launch_bounds__(256) void convv_tc_kernel(const float* __restrict__ bias)
{
    const int b  = blockIdx.z;
    const int o0 = blockIdx.y * 128;
    const int n0 = blockIdx.x * 128;
    const unsigned* xth = g_xth + (size_t)b * NN * 128;

    __shared__ unsigned sA[128][36];
    __shared__ unsigned sB[128][36];

    const int tid = threadIdx.x;
    const int lane = tid & 31, wid = tid >> 5;
    const int wm = wid >> 2, wn = wid & 3;
    const int gp = lane >> 2, tg = lane & 3;

    float acc[4][4][4] = {};

    for (int ks = 0; ks < 4; ks++) {
        int kp0g = ks * 32;
        __syncthreads();
#pragma unroll
        for (int r = 0; r < 16; r++) {
            int idx = tid + r * 256;
            int row = idx >> 5, kp = idx & 31;
            sA[row][kp] = g_wvh[(size_t)(o0 + row) * 128 + kp0g + kp];
            sB[row][kp] = xth[(size_t)(n0 + row) * 128 + kp0g + kp];
        }
        __syncthreads();
#pragma unroll
        for (int kk = 0; kk < 4; kk++) {
            int kp0 = kk * 8;
            unsigned a[4][4], bf[4][2];
#pragma unroll
            for (int i = 0; i < 4; i++) {
                int row = wm * 64 + i * 16 + gp;
                a[i][0] = sA[row][kp0 + tg];
                a[i][1] = sA[row + 8][kp0 + tg];
                a[i][2] = sA[row][kp0 + 4 + tg];
                a[i][3] = sA[row + 8][kp0 + 4 + tg];
            }
#pragma unroll
            for (int j = 0; j < 4; j++) {
                int col = wn * 32 + j * 8 + gp;
                bf[j][0] = sB[col][kp0 + tg];
                bf[j][1] = sB[col][kp0 + 4 + tg];
            }
#pragma unroll
            for (int i = 0; i < 4; i++)
#pragma unroll
                for (int j = 0; j < 4; j++)
                    mma_fp16(acc[i][j], a[i][0], a[i][1], a[i][2], a[i][3],
                             bf[j][0], bf[j][1]);
        }
    }

#pragma unroll
    for (int i = 0; i < 4; i++) {
        int o = o0 + wm * 64 + i * 16 + gp;
        float b0 = bias[o], b1 = bias[o + 8];
#pragma unroll
        for (int j = 0; j < 4; j++) {
            int np = (n0 + wn * 32 + j * 8 + 2 * tg) / 2;
            g_vh[((size_t)b * CC + o) * (NN / 2) + np] =
                pack_h2(acc[i][j][0] + b0, acc[i][j][1] + b0);
            g_vh[((size_t)b * CC + o + 8) * (NN / 2) + np] =
                pack_h2(acc[i][j][2] + b1, acc[i][j][3] + b1);
        }
    }
}

// ---------------------------------------------------------------------------
// convt_tc: t[o][n] = wt[o][:] . (x^T - x_a^T)[n][:] + bt  -> g_t fp32
// Fused BN partial sums -> g_bnsum/g_bnsum2 (atomics). (scalar LDS)
// ---------------------------------------------------------------------------
__global__ __launch_bounds__(256) void convt_tc_kernel(const float* __restrict__ bias)
{
    const int b  = blockIdx.z;
    const int o0 = blockIdx.y * 128;
    const int n0 = blockIdx.x * 128;
    const unsigned* xth  = g_xth  + (size_t)b * NN * 128;
    const unsigned* xath = g_xaTh + (size_t)b * NN * 128;

    __shared__ unsigned sA[128][36];
    __shared__ unsigned sB[128][36];
    __shared__ float sS[128], sS2[128];

    const int tid = threadIdx.x;
    const int lane = tid & 31, wid = tid >> 5;
    const int wm = wid >> 2, wn = wid & 3;
    const int gp = lane >> 2, tg = lane & 3;

    if (tid < 128) { sS[tid] = 0.f; sS2[tid] = 0.f; }

    float acc[4][4][4] = {};

    for (int ks = 0; ks < 4; ks++) {
        int kp0g = ks * 32;
        __syncthreads();
#pragma unroll
        for (int r = 0; r < 16; r++) {
            int idx = tid + r * 256;
            int row = idx >> 5, kp = idx & 31;
            sA[row][kp] = g_wth[(size_t)(o0 + row) * 128 + kp0g + kp];
            size_t gi = (size_t)(n0 + row) * 128 + kp0g + kp;
            __half2 xv = *reinterpret_cast<const __half2*>(&xth[gi]);
            __half2 av = *reinterpret_cast<const __half2*>(&xath[gi]);
            __half2 d = __hsub2(xv, av);
            sB[row][kp] = *reinterpret_cast<unsigned*>(&d);
        }
        __syncthreads();
#pragma unroll
        for (int kk = 0; kk < 4; kk++) {
            int kp0 = kk * 8;
            unsigned a[4][4], bf[4][2];
#pragma unroll
            for (int i = 0; i < 4; i++) {
                int row = wm * 64 + i * 16 + gp;
                a[i][0] = sA[row][kp0 + tg];
                a[i][1] = sA[row + 8][kp0 + tg];
                a[i][2] = sA[row][kp0 + 4 + tg];
                a[i][3] = sA[row + 8][kp0 + 4 + tg];
            }
#pragma unroll
            for (int j = 0; j < 4; j++) {
                int col = wn * 32 + j * 8 + gp;
                bf[j][0] = sB[col][kp0 + tg];
                bf[j][1] = sB[col][kp0 + 4 + tg];
            }
#pragma unroll
            for (int i = 0; i < 4; i++)
#pragma unroll
                for (int j = 0; j < 4; j++)
                    mma_fp16(acc[i][j], a[i][0], a[i][1], a[i][2], a[i][3],
                             bf[j][0], bf[j][1]);
        }
    }

#pragma unroll
    for (int i = 0; i < 4; i++) {
        int ol = wm * 64 + i * 16 + gp;
        int o = o0 + ol;
        float b0 = bias[o], b1 = bias[o + 8];
        float sa = 0.f, sa2 = 0.f, sb = 0.f, sb2 = 0.f;
#pragma unroll
        for (int j = 0; j < 4; j++) {
            int n = n0 + wn * 32 + j * 8 + 2 * tg;
            float t00 = acc[i][j][0] + b0, t01 = acc[i][j][1] + b0;
            float t10 = acc[i][j][2] + b1, t11 = acc[i][j][3] + b1;
            sa += t00 + t01;  sa2 += t00 * t00 + t01 * t01;
            sb += t10 + t11;  sb2 += t10 * t10 + t11 * t11;
            *reinterpret_cast<float2*>(&g_t[((size_t)b * CC + o) * NN + n]) =
                make_float2(t00, t01);
            *reinterpret_cast<float2*>(&g_t[((size_t)b * CC + o + 8) * NN + n]) =
                make_float2(t10, t11);
        }
#pragma unroll
        for (int off = 1; off <= 2; off <<= 1) {
            sa  += __shfl_xor_sync(0xffffffffu, sa,  off);
            sa2 += __shfl_xor_sync(0xffffffffu, sa2, off);
            sb  += __shfl_xor_sync(0xffffffffu, sb,  off);
            sb2 += __shfl_xor_sync(0xffffffffu, sb2, off);
        }
        if (tg == 0) {
            atomicAdd(&sS[ol], sa);      atomicAdd(&sS2[ol], sa2);
            atomicAdd(&sS[ol + 8], sb);  atomicAdd(&sS2[ol + 8], sb2);
        }
    }
    __syncthreads();
    if (tid < 128) {
        atomicAdd(&g_bnsum[o0 + tid], sS[tid]);
        atomicAdd(&g_bnsum2[o0 + tid], sS2[tid]);
    }
}

// ---------------------------------------------------------------------------
// bnfin: mean/rstd from accumulated sums (1 block)
// ---------------------------------------------------------------------------
__global__ void bnfin_kernel()
{
    int c = threadIdx.x;
    const float invM = 1.f / (float)(BB * NN);
    float mean = g_bnsum[c] * invM;
    float var = g_bnsum2[c] * invM - mean * mean;
    g_mean[c] = mean;
    g_rstd[c] = rsqrtf(var + 1e-5f);
}

// ---------------------------------------------------------------------------
// pass1: fused energy + row softmax stats (flash pass, scalar LDS).
// ---------------------------------------------------------------------------
__global__ __launch_bounds__(256) void pass1_kernel()
{
    const int b  = blockIdx.y;
    const int n0 = blockIdx.x * 128;
    const unsigned* qh = g_qh + (size_t)b * NN * 32;

    __shared__ unsigned sA[128][36];
    __shared__ unsigned sB[128][36];
    __shared__ float2 sMrg[4][128];

    const int tid = threadIdx.x;
    const int lane = tid & 31, wid = tid >> 5;
    const int wm = wid >> 2, wn = wid & 3;
    const int gp = lane >> 2, tg = lane & 3;

#pragma unroll
    for (int r = 0; r < 16; r++) {
        int idx = tid + r * 256;
        int row = idx >> 5, kp = idx & 31;
        sA[row][kp] = qh[(size_t)(n0 + row) * 32 + kp];
    }

    float rmax[8], rsum[8];
#pragma unroll
    for (int i = 0; i < 8; i++) { rmax[i] = -1e30f; rsum[i] = 0.f; }

    for (int m0 = 0; m0 < NN; m0 += 128) {
        __syncthreads();
#pragma unroll
        for (int r = 0; r < 16; r++) {
            int idx = tid + r * 256;
            int row = idx >> 5, kp = idx & 31;
            sB[row][kp] = qh[(size_t)(m0 + row) * 32 + kp];
        }
        __syncthreads();

        float acc[4][4][4] = {};
#pragma unroll
        for (int ks = 0; ks < 4; ks++) {
            int kp0 = ks * 8;
            unsigned a[4][4], bf[4][2];
#pragma unroll
            for (int i = 0; i < 4; i++) {
                int row = wm * 64 + i * 16 + gp;
                a[i][0] = sA[row][kp0 + tg];
                a[i][1] = sA[row + 8][kp0 + tg];
                a[i][2] = sA[row][kp0 + 4 + tg];
                a[i][3] = sA[row + 8][kp0 + 4 + tg];
            }
#pragma unroll
            for (int j = 0; j < 4; j++) {
                int col = wn * 32 + j * 8 + gp;
                bf[j][0] = sB[col][kp0 + tg];
                bf[j][1] = sB[col][kp0 + 4 + tg];
            }
#pragma unroll
            for (int i = 0; i < 4; i++)
#pragma unroll
                for (int j = 0; j < 4; j++)
                    mma_fp16(acc[i][j], a[i][0], a[i][1], a[i][2], a[i][3],
                             bf[j][0], bf[j][1]);
        }

#pragma unroll
        for (int i = 0; i < 4; i++) {
            float m0v = -1e30f, m1v = -1e30f;
#pragma unroll
            for (int j = 0; j < 4; j++) {
                m0v = fmaxf(m0v, fmaxf(acc[i][j][0], acc[i][j][1]));
                m1v = fmaxf(m1v, fmaxf(acc[i][j][2], acc[i][j][3]));
            }
            m0v = fmaxf(m0v, __shfl_xor_sync(0xffffffffu, m0v, 1));
            m0v = fmaxf(m0v, __shfl_xor_sync(0xffffffffu, m0v, 2));
            m1v = fmaxf(m1v, __shfl_xor_sync(0xffffffffu, m1v, 1));
            m1v = fmaxf(m1v, __shfl_xor_sync(0xffffffffu, m1v, 2));
            float nm0 = fmaxf(rmax[2 * i],     m0v);
            float nm1 = fmaxf(rmax[2 * i + 1], m1v);
            float s0 = 0.f, s1 = 0.f;
#pragma unroll
            for (int j = 0; j < 4; j++) {
                s0 += __expf(acc[i][j][0] - nm0) + __expf(acc[i][j][1] - nm0);
                s1 += __expf(acc[i][j][2] - nm1) + __expf(acc[i][j][3] - nm1);
            }
            s0 += __shfl_xor_sync(0xffffffffu, s0, 1);
            s0 += __shfl_xor_sync(0xffffffffu, s0, 2);
            s1 += __shfl_xor_sync(0xffffffffu, s1, 1);
            s1 += __shfl_xor_sync(0xffffffffu, s1, 2);
            rsum[2 * i]     = rsum[2 * i]     * __expf(rmax[2 * i]     - nm0) + s0;
            rsum[2 * i + 1] = rsum[2 * i + 1] * __expf(rmax[2 * i + 1] - nm1) + s1;
            rmax[2 * i]     = nm0;
            rmax[2 * i + 1] = nm1;
        }
    }

    if (tg == 0) {
#pragma unroll
        for (int i = 0; i < 4; i++) {
            int row = wm * 64 + i * 16 + gp;
            sMrg[wn][row]     = make_float2(rmax[2 * i],     rsum[2 * i]);
            sMrg[wn][row + 8] = make_float2(rmax[2 * i + 1], rsum[2 * i + 1]);
        }
    }
    __syncthreads();
    if (tid < 128) {
        float2 v0 = sMrg[0][tid], v1 = sMrg[1][tid];
        float2 v2 = sMrg[2][tid], v3 = sMrg[3][tid];
        float M = fmaxf(fmaxf(v0.x, v1.x), fmaxf(v2.x, v3.x));
        float S = v0.y * __expf(v0.x - M) + v1.y * __expf(v1.x - M)
                + v2.y * __expf(v2.x - M) + v3.y * __expf(v3.x - M);
        g_rowmax[b * NN + n0 + tid] = M;
        g_rowinv[b * NN + n0 + tid] = 1.f / S;
    }
}

// ---------------------------------------------------------------------------
// xa: fused E-recompute + P + colsum + x_a^T, single-sync software pipeline,
// ldmatrix fragment loads (kept: proven win at 16 warps).
// ---------------------------------------------------------------------------
#define XA_W_SVH 0
#define XA_W_SQM (2 * 256 * 36)
#define XA_W_SQN (XA_W_SQM + 128 * 36)
#define XA_W_SPH (XA_W_SQN + 2 * 64 * 36)
#define XA_W_COL (XA_W_SPH + 2 * 128 * 36)
#define XA_SMEM_WORDS (XA_W_COL + 128)

__global__ __launch_bounds__(512, 1) void xa_kernel()
{
    const int b  = blockIdx.y;
    const int m0 = blockIdx.x * 128;
    const unsigned* vbh = g_vh + (size_t)b * CC * (NN / 2);
    const float* rmx = g_rowmax + b * NN;
    const float* rin = g_rowinv + b * NN;
    const unsigned* qh = g_qh + (size_t)b * NN * 32;

    extern __shared__ unsigned shm[];
    unsigned (*sQm)[36] = reinterpret_cast<unsigned(*)[36]>(shm + XA_W_SQM);
    float* sCol = reinterpret_cast<float*>(shm + XA_W_COL);
    const unsigned sbase = (unsigned)__cvta_generic_to_shared(shm);

    const int tid = threadIdx.x;
    const int lane = tid & 31, wid = tid >> 5;
    const int gp = lane >> 2, tg = lane & 3;
    const int nh = wid & 3, mh = wid >> 2;       // mma1 roles (4x4)
    const int wm = wid >> 2, wn = wid & 3;       // mma2 roles

    // q_m tile (constant for the block)
#pragma unroll
    for (int r = 0; r < 8; r++) {
        int idx = tid + r * 512;
        int row = idx >> 5, kp = idx & 31;
        sQm[row][kp] = qh[(size_t)(m0 + row) * 32 + kp];
    }
    if (tid < 128) sCol[tid] = 0.f;

    auto issue_V = [&](int chunk) {
        int buf = chunk & 1;
        int np0 = chunk * 32;
#pragma unroll
        for (int t = 0; t < 4; t++) {
            int idx = tid + t * 512;
            int row = idx >> 3, seg = idx & 7;
            unsigned dst = sbase + (XA_W_SVH + buf * 256 * 36 + row * 36 + seg * 4) * 4;
            cpa16(dst, vbh + (size_t)row * (NN / 2) + np0 + seg * 4);
        }
    };
    auto issue_Qn = [&](int chunk) {
        int buf = chunk & 1;
        int row = tid >> 3, seg = tid & 7;
        unsigned dst = sbase + (XA_W_SQN + buf * 64 * 36 + row * 36 + seg * 4) * 4;
        cpa16(dst, qh + (size_t)(chunk * 64 + row) * 32 + seg * 4);
    };

    // mma1 for chunk: compute E^chunk and write P into sPh[chunk&1]
    auto do_mma1 = [&](int chunk) {
        int buf = chunk & 1;
        int WQn = XA_W_SQN + buf * 64 * 36;
        __half (*sPhB)[72] = reinterpret_cast<__half(*)[72]>(shm + XA_W_SPH + buf * 128 * 36);
        float e[4][4] = {};
#pragma unroll
        for (int ks = 0; ks < 4; ks++) {
            int kp0 = ks * 8;
            unsigned a0, a1, a2, a3, bf[4][2];
            ldsm4(a0, a1, a2, a3, adrA(sbase, WQn, 36, nh * 16, kp0, lane));
            ldsm4(bf[0][0], bf[0][1], bf[1][0], bf[1][1],
                  adrB(sbase, XA_W_SQM, 36, mh * 32, kp0, lane));
            ldsm4(bf[2][0], bf[2][1], bf[3][0], bf[3][1],
                  adrB(sbase, XA_W_SQM, 36, mh * 32 + 16, kp0, lane));
#pragma unroll
            for (int j = 0; j < 4; j++)
                mma_fp16(e[j], a0, a1, a2, a3, bf[j][0], bf[j][1]);
        }
        int r0 = chunk * 64 + nh * 16 + gp;
        float mx0 = __ldg(&rmx[r0]),     iv0 = __ldg(&rin[r0]);
        float mx1 = __ldg(&rmx[r0 + 8]), iv1 = __ldg(&rin[r0 + 8]);
        int nr0 = nh * 16 + gp, nr1 = nr0 + 8;
#pragma unroll
        for (int j = 0; j < 4; j++) {
            int cb = mh * 32 + j * 8 + 2 * tg;
            sPhB[cb][nr0]     = __float2half(__expf(e[j][0] - mx0) * iv0);
            sPhB[cb + 1][nr0] = __float2half(__expf(e[j][1] - mx0) * iv0);
            sPhB[cb][nr1]     = __float2half(__expf(e[j][2] - mx1) * iv1);
            sPhB[cb + 1][nr1] = __float2half(__expf(e[j][3] - mx1) * iv1);
        }
    };

    // prologue
    issue_V(0); issue_V(1); issue_Qn(0); issue_Qn(1); cpa_commit();
    cpa_wait0();
    __syncthreads();

    do_mma1(0);            // P(0)
    __syncthreads();
    issue_Qn(2); cpa_commit();

    float acc[2][8][4] = {};

    for (int i = 0; i < 64; i++) {
        const int buf = i & 1;
        int WV = XA_W_SVH + buf * 256 * 36;
        int WP = XA_W_SPH + buf * 128 * 36;
        __half (*sPhB)[72] = reinterpret_cast<__half(*)[72]>(shm + WP);

        // 1. mma1(i+1) into the other P buffer
        if (i < 63)
            do_mma1(i + 1);

        // 2. colsum(i)
        {
            int m = tid & 127, seg = tid >> 7;
            const __half2* prow = reinterpret_cast<const __half2*>(sPhB[m]);
            float cs = 0.f;
#pragma unroll
            for (int k = 0; k < 8; k++) {
                float2 f = __half22float2(prow[seg * 8 + k]);
                cs += f.x + f.y;
            }
            atomicAdd(&sCol[m], cs);
        }

        // 3. mma2(i): acc[m,c] += P[m][n] * V[c][n]
#pragma unroll
        for (int ks = 0; ks < 4; ks++) {
            int kp0 = ks * 8;
            unsigned pa[2][4], bf[8][2];
#pragma unroll
            for (int ii = 0; ii < 2; ii++)
                ldsm4(pa[ii][0], pa[ii][1], pa[ii][2], pa[ii][3],
                      adrA(sbase, WP, 36, wm * 32 + ii * 16, kp0, lane));
#pragma unroll
            for (int g = 0; g < 4; g++)
                ldsm4(bf[2 * g][0], bf[2 * g][1], bf[2 * g + 1][0], bf[2 * g + 1][1],
                      adrB(sbase, WV, 36, wn * 64 + g * 16, kp0, lane));
#pragma unroll
            for (int ii = 0; ii < 2; ii++)
#pragma unroll
                for (int j = 0; j < 8; j++)
                    mma_fp16(acc[ii][j], pa[ii][0], pa[ii][1], pa[ii][2], pa[ii][3],
                             bf[j][0], bf[j][1]);
        }

        // 4. wait; 5. single sync; 6. next loads
        cpa_wait0();
        __syncthreads();
        if (i + 2 < 64) issue_V(i + 2);
        if (i + 3 < 64) issue_Qn(i + 3);
        cpa_commit();
    }

    // epilogue: x_a^T[m][c] = acc * inv(m); write fp16 pairs (c contig)
#pragma unroll
    for (int ii = 0; ii < 2; ii++) {
        int mr = wm * 32 + ii * 16 + gp;
        float i0 = 1.f / (1e-9f + sCol[mr]);
        float i1 = 1.f / (1e-9f + sCol[mr + 8]);
        size_t r0 = ((size_t)b * NN + m0 + mr) * 128;
        size_t r1 = r0 + 8 * 128;
#pragma unroll
        for (int j = 0; j < 8; j++) {
            int cp = wn * 32 + j * 4 + tg;
            g_xaTh[r0 + cp] = pack_h2(acc[ii][j][0] * i0, acc[ii][j][1] * i0);
            g_xaTh[r1 + cp] = pack_h2(acc[ii][j][2] * i1, acc[ii][j][3] * i1);
        }
    }
}

// ---------------------------------------------------------------------------
// Final: out = x + relu(gamma * (t - mean) * rstd + beta)
// ---------------------------------------------------------------------------
__global__ __launch_bounds__(256) void final_kernel(
    const float* __restrict__ x, const float* __restrict__ gamma,
    const float* __restrict__ beta, float* __restrict__ out)
{
    size_t i = (size_t)blockIdx.x * 256 + threadIdx.x;
    int c = (int)((i >> 12) & 255);
    float t = g_t[i];
    float th = (t - g_mean[c]) * g_rstd[c];
    float r = fmaxf(0.f, gamma[c] * th + beta[c]);
    out[i] = x[i] + r;
}

// ---------------------------------------------------------------------------
extern "C" void kernel_launch(void* const* d_in, const int* in_sizes, int n_in,
                              void* d_out, int out_size)
{
    const float* x     = (const float*)d_in[0];
    const float* wq    = (const float*)d_in[1];
    const float* wv    = (const float*)d_in[2];
    const float* bv    = (const float*)d_in[3];
    const float* wt    = (const float*)d_in[4];
    const float* bt    = (const float*)d_in[5];
    const float* gamma = (const float*)d_in[6];
    const float* beta  = (const float*)d_in[7];
    float* out = (float*)d_out;

    const int xa_smem = XA_SMEM_WORDS * 4;
    cudaFuncSetAttribute(xa_kernel,
                         cudaFuncAttributeMaxDynamicSharedMemorySize, xa_smem);

    // x^T fp16 + weight fp16 conversions (also zeroes BN accumulators)
    xt_kernel<<<dim3(NN / 64, CC / 64, BB), 256>>>(x);
    wcvt_kernel<<<(8192 + 65536 + 255) / 256, 256>>>(wq, wv, wt);
    // q^T = x^T wq^T  (weight-tied Q/K), fp16 mma
    convq_tc_kernel<<<dim3(NN / 128, 1, BB), 256>>>();
    // v = wv x + bv, fp16 mma
    convv_tc_kernel<<<dim3(NN / 128, CC / 128, BB), 256>>>(bv);
    // fused energy + row softmax stats
    pass1_kernel<<<dim3(NN / 128, BB), 256>>>();
    // fused E-recompute + softmax + double-norm + x_a^T (ldmatrix pipeline)
    xa_kernel<<<dim3(NN / 128, BB), 512, xa_smem>>>();
    // t = wt (x - x_a) + bt, fp16 mma, fused BN partial sums
    convt_tc_kernel<<<dim3(NN / 128, CC / 128, BB), 256>>>(bt);
    // BN finalize + fused relu/residual
    bnfin_kernel<<<1, CC>>>();
    final_kernel<<<(BB * CC * NN) / 256, 256>>>(x, gamma, beta, out);
}

// round 14
// speedup vs baseline: 1.0830x; 1.0251x over previous
#include <cuda_runtime.h>
#include <cuda_fp16.h>
#include <cstdint>

#define BB 4
#define CC 256
#define NN 4096
#define DD 64

// Scratch (device globals: allocation-free kernel_launch)
__device__ unsigned g_qh[(size_t)BB * NN * 32];         // 2 MB  q fp16 pairs [b][n][d/2]
__device__ unsigned g_vh[(size_t)BB * CC * (NN / 2)];   // 8 MB  v fp16 pairs [b][c][n/2]
__device__ unsigned g_xth[(size_t)BB * NN * (CC / 2)];  // 8 MB  x^T fp16 pairs [b][n][c/2]
__device__ unsigned g_xaTh[(size_t)BB * NN * (CC / 2)]; // 8 MB  x_a^T fp16 pairs [b][n][c/2]
__device__ unsigned g_wqh[DD * (CC / 2)];               // wq fp16 pairs [o][c/2]
__device__ unsigned g_wvh[CC * (CC / 2)];
__device__ unsigned g_wth[CC * (CC / 2)];
__device__ float g_rowmax[BB * NN];
__device__ float g_rowinv[BB * NN];
__device__ float g_t[(size_t)BB * CC * NN];             // 16 MB
__device__ float g_bnsum[CC];
__device__ float g_bnsum2[CC];
__device__ float g_mean[CC];
__device__ float g_rstd[CC];

// ---------------------------------------------------------------------------
// helpers
// ---------------------------------------------------------------------------
__device__ __forceinline__ void mma_fp16(
    float* c,
    unsigned a0, unsigned a1, unsigned a2, unsigned a3,
    unsigned b0, unsigned b1)
{
    asm volatile(
        "mma.sync.aligned.m16n8k16.row.col.f32.f16.f16.f32 "
        "{%0,%1,%2,%3}, {%4,%5,%6,%7}, {%8,%9}, {%0,%1,%2,%3};\n"
        : "+f"(c[0]), "+f"(c[1]), "+f"(c[2]), "+f"(c[3])
        : "r"(a0), "r"(a1), "r"(a2), "r"(a3), "r"(b0), "r"(b1));
}

__device__ __forceinline__ void ldsm4(
    unsigned& r0, unsigned& r1, unsigned& r2, unsigned& r3, unsigned addr)
{
    asm volatile(
        "ldmatrix.sync.aligned.m8n8.x4.shared.b16 {%0,%1,%2,%3}, [%4];\n"
        : "=r"(r0), "=r"(r1), "=r"(r2), "=r"(r3) : "r"(addr));
}

// A-layout x4 address
__device__ __forceinline__ unsigned adrA(unsigned sb, int Wwords, int stride,
                                         int row0, int kp0, int lane)
{
    int row = row0 + ((lane >> 3) & 1) * 8 + (lane & 7);
    int col = kp0 + ((lane >> 4) & 1) * 4;
    return sb + (unsigned)(Wwords + row * stride + col) * 4u;
}

// B-layout x4 address
__device__ __forceinline__ unsigned adrB(unsigned sb, int Wwords, int stride,
                                         int col0, int kp0, int lane)
{
    int row = col0 + ((lane >> 4) & 1) * 8 + (lane & 7);
    int col = kp0 + ((lane >> 3) & 1) * 4;
    return sb + (unsigned)(Wwords + row * stride + col) * 4u;
}

__device__ __forceinline__ void cpa16(unsigned sdst, const void* gsrc)
{
    asm volatile("cp.async.cg.shared.global [%0], [%1], 16;\n"
                 :: "r"(sdst), "l"(gsrc));
}
__device__ __forceinline__ void cpa_commit()
{
    asm volatile("cp.async.commit_group;\n");
}
__device__ __forceinline__ void cpa_wait0()
{
    asm volatile("cp.async.wait_group 0;\n");
}

__device__ __forceinline__ unsigned pack_h2(float a, float b)
{
    __half2 h = __floats2half2_rn(a, b);
    return *reinterpret_cast<unsigned*>(&h);
}

// ---------------------------------------------------------------------------
// xt: transpose + convert x[b][c][n] fp32 -> g_xth[(b*N+n)*128 + c/2] fp16 pairs
// ---------------------------------------------------------------------------
__global__ __launch_bounds__(256) void xt_kernel(const float* __restrict__ x)
{
    const int b  = blockIdx.z;
    const int c0 = blockIdx.y * 64;
    const int n0 = blockIdx.x * 64;
    const float* xb = x + ((size_t)b * CC + c0) * NN + n0;

    __shared__ float sT[64][65];
    const int tid = threadIdx.x;

#pragma unroll
    for (int r = 0; r < 16; r++) {
        int idx = tid + r * 256;
        int c = idx >> 6, n = idx & 63;
        sT[c][n] = xb[(size_t)c * NN + n];
    }
    __syncthreads();
#pragma unroll
    for (int r = 0; r < 8; r++) {
        int idx = tid + r * 256;
        int n = idx >> 5, cp = idx & 31;
        g_xth[((size_t)b * NN + n0 + n) * 128 + c0 / 2 + cp] =
            pack_h2(sT[2 * cp][n], sT[2 * cp + 1][n]);
    }
}

// ---------------------------------------------------------------------------
// wcvt: convert wq/wv/wt to fp16 pairs; also zero BN accumulators
// ---------------------------------------------------------------------------
__global__ __launch_bounds__(256) void wcvt_kernel(
    const float* __restrict__ wq, const float* __restrict__ wv,
    const float* __restrict__ wt)
{
    int idx = blockIdx.x * 256 + threadIdx.x;
    if (idx < 256) { g_bnsum[idx] = 0.f; g_bnsum2[idx] = 0.f; }
    if (idx < 8192) {
        float2 f = *reinterpret_cast<const float2*>(&wq[idx * 2]);
        g_wqh[idx] = pack_h2(f.x, f.y);
    } else if (idx < 8192 + 32768) {
        int i = idx - 8192;
        float2 f = *reinterpret_cast<const float2*>(&wv[i * 2]);
        g_wvh[i] = pack_h2(f.x, f.y);
    } else if (idx < 8192 + 65536) {
        int i = idx - 8192 - 32768;
        float2 f = *reinterpret_cast<const float2*>(&wt[i * 2]);
        g_wth[i] = pack_h2(f.x, f.y);
    }
}

// ---------------------------------------------------------------------------
// convq_tc: q^T[n][o] = x^T[n][:] . wq[o][:]  -> g_qh[(b*N+n)*32 + o/2]
// (scalar LDS — higher MLP wins at 8 warps/CTA)
// ---------------------------------------------------------------------------
__global__ __launch_bounds__(256) void convq_tc_kernel()
{
    const int b  = blockIdx.z;
    const int n0 = blockIdx.x * 128;
    const unsigned* xth = g_xth + (size_t)b * NN * 128;

    __shared__ unsigned sA[128][36];
    __shared__ unsigned sB[64][36];

    const int tid = threadIdx.x;
    const int lane = tid & 31, wid = tid >> 5;
    const int wm = wid >> 2, wn = wid & 3;
    const int gp = lane >> 2, tg = lane & 3;

    float acc[4][2][4] = {};

    for (int ks = 0; ks < 4; ks++) {
        int kp0g = ks * 32;
        __syncthreads();
#pragma unroll
        for (int r = 0; r < 16; r++) {
            int idx = tid + r * 256;
            int row = idx >> 5, kp = idx & 31;
            sA[row][kp] = xth[(size_t)(n0 + row) * 128 + kp0g + kp];
        }
#pragma unroll
        for (int r = 0; r < 8; r++) {
            int idx = tid + r * 256;
            int row = idx >> 5, kp = idx & 31;
            sB[row][kp] = g_wqh[(size_t)row * 128 + kp0g + kp];
        }
        __syncthreads();
#pragma unroll
        for (int kk = 0; kk < 4; kk++) {
            int kp0 = kk * 8;
            unsigned a[4][4], bf[2][2];
#pragma unroll
            for (int i = 0; i < 4; i++) {
                int row = wm * 64 + i * 16 + gp;
                a[i][0] = sA[row][kp0 + tg];
                a[i][1] = sA[row + 8][kp0 + tg];
                a[i][2] = sA[row][kp0 + 4 + tg];
                a[i][3] = sA[row + 8][kp0 + 4 + tg];
            }
#pragma unroll
            for (int j = 0; j < 2; j++) {
                int col = wn * 16 + j * 8 + gp;
                bf[j][0] = sB[col][kp0 + tg];
                bf[j][1] = sB[col][kp0 + 4 + tg];
            }
#pragma unroll
            for (int i = 0; i < 4; i++)
#pragma unroll
                for (int j = 0; j < 2; j++)
                    mma_fp16(acc[i][j], a[i][0], a[i][1], a[i][2], a[i][3],
                             bf[j][0], bf[j][1]);
        }
    }

#pragma unroll
    for (int i = 0; i < 4; i++) {
        int n = n0 + wm * 64 + i * 16 + gp;
#pragma unroll
        for (int j = 0; j < 2; j++) {
            int op = wn * 8 + j * 4 + tg;
            g_qh[((size_t)b * NN + n) * 32 + op]     = pack_h2(acc[i][j][0], acc[i][j][1]);
            g_qh[((size_t)b * NN + n + 8) * 32 + op] = pack_h2(acc[i][j][2], acc[i][j][3]);
        }
    }
}

// ---------------------------------------------------------------------------
// convv_tc: v[o][n] = wv[o][:] . x^T[n][:] + bv  (scalar LDS)
// ---------------------------------------------------------------------------
__global__ __launch_bounds__(256) void convv_tc_kernel(const float* __restrict__ bias)
{
    const int b  = blockIdx.z;
    const int o0 = blockIdx.y * 128;
    const int n0 = blockIdx.x * 128;
    const unsigned* xth = g_xth + (size_t)b * NN * 128;

    __shared__ unsigned sA[128][36];
    __shared__ unsigned sB[128][36];

    const int tid = threadIdx.x;
    const int lane = tid & 31, wid = tid >> 5;
    const int wm = wid >> 2, wn = wid & 3;
    const int gp = lane >> 2, tg = lane & 3;

    float acc[4][4][4] = {};

    for (int ks = 0; ks < 4; ks++) {
        int kp0g = ks * 32;
        __syncthreads();
#pragma unroll
        for (int r = 0; r < 16; r++) {
            int idx = tid + r * 256;
            int row = idx >> 5, kp = idx & 31;
            sA[row][kp] = g_wvh[(size_t)(o0 + row) * 128 + kp0g + kp];
            sB[row][kp] = xth[(size_t)(n0 + row) * 128 + kp0g + kp];
        }
        __syncthreads();
#pragma unroll
        for (int kk = 0; kk < 4; kk++) {
            int kp0 = kk * 8;
            unsigned a[4][4], bf[4][2];
#pragma unroll
            for (int i = 0; i < 4; i++) {
                int row = wm * 64 + i * 16 + gp;
                a[i][0] = sA[row][kp0 + tg];
                a[i][1] = sA[row + 8][kp0 + tg];
                a[i][2] = sA[row][kp0 + 4 + tg];
                a[i][3] = sA[row + 8][kp0 + 4 + tg];
            }
#pragma unroll
            for (int j = 0; j < 4; j++) {
                int col = wn * 32 + j * 8 + gp;
                bf[j][0] = sB[col][kp0 + tg];
                bf[j][1] = sB[col][kp0 + 4 + tg];
            }
#pragma unroll
            for (int i = 0; i < 4; i++)
#pragma unroll
                for (int j = 0; j < 4; j++)
                    mma_fp16(acc[i][j], a[i][0], a[i][1], a[i][2], a[i][3],
                             bf[j][0], bf[j][1]);
        }
    }

#pragma unroll
    for (int i = 0; i < 4; i++) {
        int o = o0 + wm * 64 + i * 16 + gp;
        float b0 = bias[o], b1 = bias[o + 8];
#pragma unroll
        for (int j = 0; j < 4; j++) {
            int np = (n0 + wn * 32 + j * 8 + 2 * tg) / 2;
            g_vh[((size_t)b * CC + o) * (NN / 2) + np] =
                pack_h2(acc[i][j][0] + b0, acc[i][j][1] + b0);
            g_vh[((size_t)b * CC + o + 8) * (NN / 2) + np] =
                pack_h2(acc[i][j][2] + b1, acc[i][j][3] + b1);
        }
    }
}

// ---------------------------------------------------------------------------
// convt_tc: t[o][n] = wt[o][:] . (x^T - x_a^T)[n][:] + bt  -> g_t fp32
// Fused BN partial sums -> g_bnsum/g_bnsum2. (scalar LDS)
// ---------------------------------------------------------------------------
__global__ __launch_bounds__(256) void convt_tc_kernel(const float* __restrict__ bias)
{
    const int b  = blockIdx.z;
    const int o0 = blockIdx.y * 128;
    const int n0 = blockIdx.x * 128;
    const unsigned* xth  = g_xth  + (size_t)b * NN * 128;
    const unsigned* xath = g_xaTh + (size_t)b * NN * 128;

    __shared__ unsigned sA[128][36];
    __shared__ unsigned sB[128][36];
    __shared__ float sS[128], sS2[128];

    const int tid = threadIdx.x;
    const int lane = tid & 31, wid = tid >> 5;
    const int wm = wid >> 2, wn = wid & 3;
    const int gp = lane >> 2, tg = lane & 3;

    if (tid < 128) { sS[tid] = 0.f; sS2[tid] = 0.f; }

    float acc[4][4][4] = {};

    for (int ks = 0; ks < 4; ks++) {
        int kp0g = ks * 32;
        __syncthreads();
#pragma unroll
        for (int r = 0; r < 16; r++) {
            int idx = tid + r * 256;
            int row = idx >> 5, kp = idx & 31;
            sA[row][kp] = g_wth[(size_t)(o0 + row) * 128 + kp0g + kp];
            size_t gi = (size_t)(n0 + row) * 128 + kp0g + kp;
            __half2 xv = *reinterpret_cast<const __half2*>(&xth[gi]);
            __half2 av = *reinterpret_cast<const __half2*>(&xath[gi]);
            __half2 d = __hsub2(xv, av);
            sB[row][kp] = *reinterpret_cast<unsigned*>(&d);
        }
        __syncthreads();
#pragma unroll
        for (int kk = 0; kk < 4; kk++) {
            int kp0 = kk * 8;
            unsigned a[4][4], bf[4][2];
#pragma unroll
            for (int i = 0; i < 4; i++) {
                int row = wm * 64 + i * 16 + gp;
                a[i][0] = sA[row][kp0 + tg];
                a[i][1] = sA[row + 8][kp0 + tg];
                a[i][2] = sA[row][kp0 + 4 + tg];
                a[i][3] = sA[row + 8][kp0 + 4 + tg];
            }
#pragma unroll
            for (int j = 0; j < 4; j++) {
                int col = wn * 32 + j * 8 + gp;
                bf[j][0] = sB[col][kp0 + tg];
                bf[j][1] = sB[col][kp0 + 4 + tg];
            }
#pragma unroll
            for (int i = 0; i < 4; i++)
#pragma unroll
                for (int j = 0; j < 4; j++)
                    mma_fp16(acc[i][j], a[i][0], a[i][1], a[i][2], a[i][3],
                             bf[j][0], bf[j][1]);
        }
    }

#pragma unroll
    for (int i = 0; i < 4; i++) {
        int ol = wm * 64 + i * 16 + gp;
        int o = o0 + ol;
        float b0 = bias[o], b1 = bias[o + 8];
        float sa = 0.f, sa2 = 0.f, sb = 0.f, sb2 = 0.f;
#pragma unroll
        for (int j = 0; j < 4; j++) {
            int n = n0 + wn * 32 + j * 8 + 2 * tg;
            float t00 = acc[i][j][0] + b0, t01 = acc[i][j][1] + b0;
            float t10 = acc[i][j][2] + b1, t11 = acc[i][j][3] + b1;
            sa += t00 + t01;  sa2 += t00 * t00 + t01 * t01;
            sb += t10 + t11;  sb2 += t10 * t10 + t11 * t11;
            *reinterpret_cast<float2*>(&g_t[((size_t)b * CC + o) * NN + n]) =
                make_float2(t00, t01);
            *reinterpret_cast<float2*>(&g_t[((size_t)b * CC + o + 8) * NN + n]) =
                make_float2(t10, t11);
        }
#pragma unroll
        for (int off = 1; off <= 2; off <<= 1) {
            sa  += __shfl_xor_sync(0xffffffffu, sa,  off);
            sa2 += __shfl_xor_sync(0xffffffffu, sa2, off);
            sb  += __shfl_xor_sync(0xffffffffu, sb,  off);
            sb2 += __shfl_xor_sync(0xffffffffu, sb2, off);
        }
        if (tg == 0) {
            atomicAdd(&sS[ol], sa);      atomicAdd(&sS2[ol], sa2);
            atomicAdd(&sS[ol + 8], sb);  atomicAdd(&sS2[ol + 8], sb2);
        }
    }
    __syncthreads();
    if (tid < 128) {
        atomicAdd(&g_bnsum[o0 + tid], sS[tid]);
        atomicAdd(&g_bnsum2[o0 + tid], sS2[tid]);
    }
}

// ---------------------------------------------------------------------------
// bnfin: mean/rstd from accumulated sums (1 block)
// ---------------------------------------------------------------------------
__global__ void bnfin_kernel()
{
    int c = threadIdx.x;
    const float invM = 1.f / (float)(BB * NN);
    float mean = g_bnsum[c] * invM;
    float var = g_bnsum2[c] * invM - mean * mean;
    g_mean[c] = mean;
    g_rstd[c] = rsqrtf(var + 1e-5f);
}

// ---------------------------------------------------------------------------
// pass1: fused energy + row softmax stats (flash pass, scalar LDS).
// ---------------------------------------------------------------------------
__global__ __launch_bounds__(256) void pass1_kernel()
{
    const int b  = blockIdx.y;
    const int n0 = blockIdx.x * 128;
    const unsigned* qh = g_qh + (size_t)b * NN * 32;

    __shared__ unsigned sA[128][36];
    __shared__ unsigned sB[128][36];
    __shared__ float2 sMrg[4][128];

    const int tid = threadIdx.x;
    const int lane = tid & 31, wid = tid >> 5;
    const int wm = wid >> 2, wn = wid & 3;
    const int gp = lane >> 2, tg = lane & 3;

#pragma unroll
    for (int r = 0; r < 16; r++) {
        int idx = tid + r * 256;
        int row = idx >> 5, kp = idx & 31;
        sA[row][kp] = qh[(size_t)(n0 + row) * 32 + kp];
    }

    float rmax[8], rsum[8];
#pragma unroll
    for (int i = 0; i < 8; i++) { rmax[i] = -1e30f; rsum[i] = 0.f; }

    for (int m0 = 0; m0 < NN; m0 += 128) {
        __syncthreads();
#pragma unroll
        for (int r = 0; r < 16; r++) {
            int idx = tid + r * 256;
            int row = idx >> 5, kp = idx & 31;
            sB[row][kp] = qh[(size_t)(m0 + row) * 32 + kp];
        }
        __syncthreads();

        float acc[4][4][4] = {};
#pragma unroll
        for (int ks = 0; ks < 4; ks++) {
            int kp0 = ks * 8;
            unsigned a[4][4], bf[4][2];
#pragma unroll
            for (int i = 0; i < 4; i++) {
                int row = wm * 64 + i * 16 + gp;
                a[i][0] = sA[row][kp0 + tg];
                a[i][1] = sA[row + 8][kp0 + tg];
                a[i][2] = sA[row][kp0 + 4 + tg];
                a[i][3] = sA[row + 8][kp0 + 4 + tg];
            }
#pragma unroll
            for (int j = 0; j < 4; j++) {
                int col = wn * 32 + j * 8 + gp;
                bf[j][0] = sB[col][kp0 + tg];
                bf[j][1] = sB[col][kp0 + 4 + tg];
            }
#pragma unroll
            for (int i = 0; i < 4; i++)
#pragma unroll
                for (int j = 0; j < 4; j++)
                    mma_fp16(acc[i][j], a[i][0], a[i][1], a[i][2], a[i][3],
                             bf[j][0], bf[j][1]);
        }

#pragma unroll
        for (int i = 0; i < 4; i++) {
            float m0v = -1e30f, m1v = -1e30f;
#pragma unroll
            for (int j = 0; j < 4; j++) {
                m0v = fmaxf(m0v, fmaxf(acc[i][j][0], acc[i][j][1]));
                m1v = fmaxf(m1v, fmaxf(acc[i][j][2], acc[i][j][3]));
            }
            m0v = fmaxf(m0v, __shfl_xor_sync(0xffffffffu, m0v, 1));
            m0v = fmaxf(m0v, __shfl_xor_sync(0xffffffffu, m0v, 2));
            m1v = fmaxf(m1v, __shfl_xor_sync(0xffffffffu, m1v, 1));
            m1v = fmaxf(m1v, __shfl_xor_sync(0xffffffffu, m1v, 2));
            float nm0 = fmaxf(rmax[2 * i],     m0v);
            float nm1 = fmaxf(rmax[2 * i + 1], m1v);
            float s0 = 0.f, s1 = 0.f;
#pragma unroll
            for (int j = 0; j < 4; j++) {
                s0 += __expf(acc[i][j][0] - nm0) + __expf(acc[i][j][1] - nm0);
                s1 += __expf(acc[i][j][2] - nm1) + __expf(acc[i][j][3] - nm1);
            }
            s0 += __shfl_xor_sync(0xffffffffu, s0, 1);
            s0 += __shfl_xor_sync(0xffffffffu, s0, 2);
            s1 += __shfl_xor_sync(0xffffffffu, s1, 1);
            s1 += __shfl_xor_sync(0xffffffffu, s1, 2);
            rsum[2 * i]     = rsum[2 * i]     * __expf(rmax[2 * i]     - nm0) + s0;
            rsum[2 * i + 1] = rsum[2 * i + 1] * __expf(rmax[2 * i + 1] - nm1) + s1;
            rmax[2 * i]     = nm0;
            rmax[2 * i + 1] = nm1;
        }
    }

    if (tg == 0) {
#pragma unroll
        for (int i = 0; i < 4; i++) {
            int row = wm * 64 + i * 16 + gp;
            sMrg[wn][row]     = make_float2(rmax[2 * i],     rsum[2 * i]);
            sMrg[wn][row + 8] = make_float2(rmax[2 * i + 1], rsum[2 * i + 1]);
        }
    }
    __syncthreads();
    if (tid < 128) {
        float2 v0 = sMrg[0][tid], v1 = sMrg[1][tid];
        float2 v2 = sMrg[2][tid], v3 = sMrg[3][tid];
        float M = fmaxf(fmaxf(v0.x, v1.x), fmaxf(v2.x, v3.x));
        float S = v0.y * __expf(v0.x - M) + v1.y * __expf(v1.x - M)
                + v2.y * __expf(v2.x - M) + v3.y * __expf(v3.x - M);
        g_rowmax[b * NN + n0 + tid] = M;
        g_rowinv[b * NN + n0 + tid] = 1.f / S;
    }
}

// ---------------------------------------------------------------------------
// xa: fused E-recompute + P + x_a^T, single-sync pipeline, ldmatrix loads.
// Colsum accumulated in REGISTERS at P-production time (no per-chunk LDS
// re-read, no per-chunk atomics); one shfl+atomic merge after the loop.
// ---------------------------------------------------------------------------
#define XA_W_SVH 0
#define XA_W_SQM (2 * 256 * 36)
#define XA_W_SQN (XA_W_SQM + 128 * 36)
#define XA_W_SPH (XA_W_SQN + 2 * 64 * 36)
#define XA_W_COL (XA_W_SPH + 2 * 128 * 36)
#define XA_SMEM_WORDS (XA_W_COL + 128)

__global__ __launch_bounds__(512, 1) void xa_kernel()
{
    const int b  = blockIdx.y;
    const int m0 = blockIdx.x * 128;
    const unsigned* vbh = g_vh + (size_t)b * CC * (NN / 2);
    const float* rmx = g_rowmax + b * NN;
    const float* rin = g_rowinv + b * NN;
    const unsigned* qh = g_qh + (size_t)b * NN * 32;

    extern __shared__ unsigned shm[];
    unsigned (*sQm)[36] = reinterpret_cast<unsigned(*)[36]>(shm + XA_W_SQM);
    float* sCol = reinterpret_cast<float*>(shm + XA_W_COL);
    const unsigned sbase = (unsigned)__cvta_generic_to_shared(shm);

    const int tid = threadIdx.x;
    const int lane = tid & 31, wid = tid >> 5;
    const int gp = lane >> 2, tg = lane & 3;
    const int nh = wid & 3, mh = wid >> 2;       // mma1 roles (4x4)
    const int wm = wid >> 2, wn = wid & 3;       // mma2 roles

    // q_m tile (constant for the block)
#pragma unroll
    for (int r = 0; r < 8; r++) {
        int idx = tid + r * 512;
        int row = idx >> 5, kp = idx & 31;
        sQm[row][kp] = qh[(size_t)(m0 + row) * 32 + kp];
    }
    if (tid < 128) sCol[tid] = 0.f;

    // per-thread colsum partials for this thread's 8 P columns
    float cs[8];
#pragma unroll
    for (int j = 0; j < 8; j++) cs[j] = 0.f;

    auto issue_V = [&](int chunk) {
        int buf = chunk & 1;
        int np0 = chunk * 32;
#pragma unroll
        for (int t = 0; t < 4; t++) {
            int idx = tid + t * 512;
            int row = idx >> 3, seg = idx & 7;
            unsigned dst = sbase + (XA_W_SVH + buf * 256 * 36 + row * 36 + seg * 4) * 4;
            cpa16(dst, vbh + (size_t)row * (NN / 2) + np0 + seg * 4);
        }
    };
    auto issue_Qn = [&](int chunk) {
        int buf = chunk & 1;
        int row = tid >> 3, seg = tid & 7;
        unsigned dst = sbase + (XA_W_SQN + buf * 64 * 36 + row * 36 + seg * 4) * 4;
        cpa16(dst, qh + (size_t)(chunk * 64 + row) * 32 + seg * 4);
    };

    // mma1 for chunk: compute E^chunk, write P into sPh[chunk&1], and
    // accumulate this thread's colsum partials from the fp16-rounded values.
    auto do_mma1 = [&](int chunk) {
        int buf = chunk & 1;
        int WQn = XA_W_SQN + buf * 64 * 36;
        __half (*sPhB)[72] = reinterpret_cast<__half(*)[72]>(shm + XA_W_SPH + buf * 128 * 36);
        float e[4][4] = {};
#pragma unroll
        for (int ks = 0; ks < 4; ks++) {
            int kp0 = ks * 8;
            unsigned a0, a1, a2, a3, bf[4][2];
            ldsm4(a0, a1, a2, a3, adrA(sbase, WQn, 36, nh * 16, kp0, lane));
            ldsm4(bf[0][0], bf[0][1], bf[1][0], bf[1][1],
                  adrB(sbase, XA_W_SQM, 36, mh * 32, kp0, lane));
            ldsm4(bf[2][0], bf[2][1], bf[3][0], bf[3][1],
                  adrB(sbase, XA_W_SQM, 36, mh * 32 + 16, kp0, lane));
#pragma unroll
            for (int j = 0; j < 4; j++)
                mma_fp16(e[j], a0, a1, a2, a3, bf[j][0], bf[j][1]);
        }
        int r0 = chunk * 64 + nh * 16 + gp;
        float mx0 = __ldg(&rmx[r0]),     iv0 = __ldg(&rin[r0]);
        float mx1 = __ldg(&rmx[r0 + 8]), iv1 = __ldg(&rin[r0 + 8]);
        int nr0 = nh * 16 + gp, nr1 = nr0 + 8;
#pragma unroll
        for (int j = 0; j < 4; j++) {
            int cb = mh * 32 + j * 8 + 2 * tg;
            __half h00 = __float2half(__expf(e[j][0] - mx0) * iv0);
            __half h01 = __float2half(__expf(e[j][1] - mx0) * iv0);
            __half h10 = __float2half(__expf(e[j][2] - mx1) * iv1);
            __half h11 = __float2half(__expf(e[j][3] - mx1) * iv1);
            sPhB[cb][nr0]     = h00;
            sPhB[cb + 1][nr0] = h01;
            sPhB[cb][nr1]     = h10;
            sPhB[cb + 1][nr1] = h11;
            cs[2 * j]     += __half2float(h00) + __half2float(h10);
            cs[2 * j + 1] += __half2float(h01) + __half2float(h11);
        }
    };

    // prologue
    issue_V(0); issue_V(1); issue_Qn(0); issue_Qn(1); cpa_commit();
    cpa_wait0();
    __syncthreads();

    do_mma1(0);            // P(0)
    __syncthreads();
    issue_Qn(2); cpa_commit();

    float acc[2][8][4] = {};

    for (int i = 0; i < 64; i++) {
        const int buf = i & 1;
        int WV = XA_W_SVH + buf * 256 * 36;
        int WP = XA_W_SPH + buf * 128 * 36;

        // 1. mma1(i+1) into the other P buffer
        if (i < 63)
            do_mma1(i + 1);

        // 2. mma2(i): acc[m,c] += P[m][n] * V[c][n]
#pragma unroll
        for (int ks = 0; ks < 4; ks++) {
            int kp0 = ks * 8;
            unsigned pa[2][4], bf[8][2];
#pragma unroll
            for (int ii = 0; ii < 2; ii++)
                ldsm4(pa[ii][0], pa[ii][1], pa[ii][2], pa[ii][3],
                      adrA(sbase, WP, 36, wm * 32 + ii * 16, kp0, lane));
#pragma unroll
            for (int g = 0; g < 4; g++)
                ldsm4(bf[2 * g][0], bf[2 * g][1], bf[2 * g + 1][0], bf[2 * g + 1][1],
                      adrB(sbase, WV, 36, wn * 64 + g * 16, kp0, lane));
#pragma unroll
            for (int ii = 0; ii < 2; ii++)
#pragma unroll
                for (int j = 0; j < 8; j++)
                    mma_fp16(acc[ii][j], pa[ii][0], pa[ii][1], pa[ii][2], pa[ii][3],
                             bf[j][0], bf[j][1]);
        }

        // 3. wait; 4. single sync; 5. next loads
        cpa_wait0();
        __syncthreads();
        if (i + 2 < 64) issue_V(i + 2);
        if (i + 3 < 64) issue_Qn(i + 3);
        cpa_commit();
    }

    // colsum merge: reduce over gp (lanes xor 4,8,16), then 4 warps (nh) per
    // column via shared atomics — once, after the loop.
#pragma unroll
    for (int j = 0; j < 8; j++) {
        float v = cs[j];
        v += __shfl_xor_sync(0xffffffffu, v, 4);
        v += __shfl_xor_sync(0xffffffffu, v, 8);
        v += __shfl_xor_sync(0xffffffffu, v, 16);
        cs[j] = v;
    }
    if (gp == 0) {
#pragma unroll
        for (int j = 0; j < 4; j++) {
            int cb = mh * 32 + j * 8 + 2 * tg;
            atomicAdd(&sCol[cb], cs[2 * j]);
            atomicAdd(&sCol[cb + 1], cs[2 * j + 1]);
        }
    }
    __syncthreads();

    // epilogue: x_a^T[m][c] = acc * inv(m); write fp16 pairs (c contig)
#pragma unroll
    for (int ii = 0; ii < 2; ii++) {
        int mr = wm * 32 + ii * 16 + gp;
        float i0 = 1.f / (1e-9f + sCol[mr]);
        float i1 = 1.f / (1e-9f + sCol[mr + 8]);
        size_t r0 = ((size_t)b * NN + m0 + mr) * 128;
        size_t r1 = r0 + 8 * 128;
#pragma unroll
        for (int j = 0; j < 8; j++) {
            int cp = wn * 32 + j * 4 + tg;
            g_xaTh[r0 + cp] = pack_h2(acc[ii][j][0] * i0, acc[ii][j][1] * i0);
            g_xaTh[r1 + cp] = pack_h2(acc[ii][j][2] * i1, acc[ii][j][3] * i1);
        }
    }
}

// ---------------------------------------------------------------------------
// Final: out = x + relu(gamma * (t - mean) * rstd + beta)
// ---------------------------------------------------------------------------
__global__ __launch_bounds__(256) void final_kernel(
    const float* __restrict__ x, const float* __restrict__ gamma,
    const float* __restrict__ beta, float* __restrict__ out)
{
    size_t i = (size_t)blockIdx.x * 256 + threadIdx.x;
    int c = (int)((i >> 12) & 255);
    float t = g_t[i];
    float th = (t - g_mean[c]) * g_rstd[c];
    float r = fmaxf(0.f, gamma[c] * th + beta[c]);
    out[i] = x[i] + r;
}

// ---------------------------------------------------------------------------
extern "C" void kernel_launch(void* const* d_in, const int* in_sizes, int n_in,
                              void* d_out, int out_size)
{
    const float* x     = (const float*)d_in[0];
    const float* wq    = (const float*)d_in[1];
    const float* wv    = (const float*)d_in[2];
    const float* bv    = (const float*)d_in[3];
    const float* wt    = (const float*)d_in[4];
    const float* bt    = (const float*)d_in[5];
    const float* gamma = (const float*)d_in[6];
    const float* beta  = (const float*)d_in[7];
    float* out = (float*)d_out;

    const int xa_smem = XA_SMEM_WORDS * 4;
    cudaFuncSetAttribute(xa_kernel,
                         cudaFuncAttributeMaxDynamicSharedMemorySize, xa_smem);

    // x^T fp16 + weight fp16 conversions (also zeroes BN accumulators)
    xt_kernel<<<dim3(NN / 64, CC / 64, BB), 256>>>(x);
    wcvt_kernel<<<(8192 + 65536 + 255) / 256, 256>>>(wq, wv, wt);
    // q^T = x^T wq^T  (weight-tied Q/K), fp16 mma
    convq_tc_kernel<<<dim3(NN / 128, 1, BB), 256>>>();
    // v = wv x + bv, fp16 mma
    convv_tc_kernel<<<dim3(NN / 128, CC / 128, BB), 256>>>(bv);
    // fused energy + row softmax stats
    pass1_kernel<<<dim3(NN / 128, BB), 256>>>();
    // fused E-recompute + softmax + double-norm + x_a^T (register colsum)
    xa_kernel<<<dim3(NN / 128, BB), 512, xa_smem>>>();
    // t = wt (x - x_a) + bt, fp16 mma, fused BN partial sums
    convt_tc_kernel<<<dim3(NN / 128, CC / 128, BB), 256>>>(bt);
    // BN finalize + fused relu/residual
    bnfin_kernel<<<1, CC>>>();
    final_kernel<<<(BB * CC * NN) / 256, 256>>>(x, gamma, beta, out);
}

// round 15
// speedup vs baseline: 1.1158x; 1.0303x over previous
#include <cuda_runtime.h>
#include <cuda_fp16.h>
#include <cstdint>

#define BB 4
#define CC 256
#define NN 4096
#define DD 64

// Scratch (device globals: allocation-free kernel_launch)
__device__ unsigned g_qh[(size_t)BB * NN * 32];         // 2 MB  q fp16 pairs [b][n][d/2]
__device__ unsigned g_vh[(size_t)BB * CC * (NN / 2)];   // 8 MB  v fp16 pairs [b][c][n/2]
__device__ unsigned g_xth[(size_t)BB * NN * (CC / 2)];  // 8 MB  x^T fp16 pairs [b][n][c/2]
__device__ unsigned g_xaTh[(size_t)BB * NN * (CC / 2)]; // 8 MB  x_a^T fp16 pairs [b][n][c/2]
__device__ unsigned g_wqh[DD * (CC / 2)];               // wq fp16 pairs [o][c/2]
__device__ unsigned g_wvh[CC * (CC / 2)];
__device__ unsigned g_wth[CC * (CC / 2)];
__device__ float g_rowmax[BB * NN];
__device__ float g_rowinv[BB * NN];
__device__ float g_t[(size_t)BB * CC * NN];             // 16 MB
__device__ float g_bnsum[CC];
__device__ float g_bnsum2[CC];
__device__ float g_mean[CC];
__device__ float g_rstd[CC];

// ---------------------------------------------------------------------------
// helpers
// ---------------------------------------------------------------------------
__device__ __forceinline__ void mma_fp16(
    float* c,
    unsigned a0, unsigned a1, unsigned a2, unsigned a3,
    unsigned b0, unsigned b1)
{
    asm volatile(
        "mma.sync.aligned.m16n8k16.row.col.f32.f16.f16.f32 "
        "{%0,%1,%2,%3}, {%4,%5,%6,%7}, {%8,%9}, {%0,%1,%2,%3};\n"
        : "+f"(c[0]), "+f"(c[1]), "+f"(c[2]), "+f"(c[3])
        : "r"(a0), "r"(a1), "r"(a2), "r"(a3), "r"(b0), "r"(b1));
}

__device__ __forceinline__ void ldsm4(
    unsigned& r0, unsigned& r1, unsigned& r2, unsigned& r3, unsigned addr)
{
    asm volatile(
        "ldmatrix.sync.aligned.m8n8.x4.shared.b16 {%0,%1,%2,%3}, [%4];\n"
        : "=r"(r0), "=r"(r1), "=r"(r2), "=r"(r3) : "r"(addr));
}

// A-layout x4 address
__device__ __forceinline__ unsigned adrA(unsigned sb, int Wwords, int stride,
                                         int row0, int kp0, int lane)
{
    int row = row0 + ((lane >> 3) & 1) * 8 + (lane & 7);
    int col = kp0 + ((lane >> 4) & 1) * 4;
    return sb + (unsigned)(Wwords + row * stride + col) * 4u;
}

// B-layout x4 address
__device__ __forceinline__ unsigned adrB(unsigned sb, int Wwords, int stride,
                                         int col0, int kp0, int lane)
{
    int row = col0 + ((lane >> 4) & 1) * 8 + (lane & 7);
    int col = kp0 + ((lane >> 3) & 1) * 4;
    return sb + (unsigned)(Wwords + row * stride + col) * 4u;
}

__device__ __forceinline__ void cpa16(unsigned sdst, const void* gsrc)
{
    asm volatile("cp.async.cg.shared.global [%0], [%1], 16;\n"
                 :: "r"(sdst), "l"(gsrc));
}
__device__ __forceinline__ void cpa_commit()
{
    asm volatile("cp.async.commit_group;\n");
}
__device__ __forceinline__ void cpa_wait0()
{
    asm volatile("cp.async.wait_group 0;\n");
}

__device__ __forceinline__ unsigned pack_h2(float a, float b)
{
    __half2 h = __floats2half2_rn(a, b);
    return *reinterpret_cast<unsigned*>(&h);
}

// ---------------------------------------------------------------------------
// xt: transpose + convert x[b][c][n] fp32 -> g_xth[(b*N+n)*128 + c/2] fp16 pairs
// ---------------------------------------------------------------------------
__global__ __launch_bounds__(256) void xt_kernel(const float* __restrict__ x)
{
    const int b  = blockIdx.z;
    const int c0 = blockIdx.y * 64;
    const int n0 = blockIdx.x * 64;
    const float* xb = x + ((size_t)b * CC + c0) * NN + n0;

    __shared__ float sT[64][65];
    const int tid = threadIdx.x;

#pragma unroll
    for (int r = 0; r < 16; r++) {
        int idx = tid + r * 256;
        int c = idx >> 6, n = idx & 63;
        sT[c][n] = xb[(size_t)c * NN + n];
    }
    __syncthreads();
#pragma unroll
    for (int r = 0; r < 8; r++) {
        int idx = tid + r * 256;
        int n = idx >> 5, cp = idx & 31;
        g_xth[((size_t)b * NN + n0 + n) * 128 + c0 / 2 + cp] =
            pack_h2(sT[2 * cp][n], sT[2 * cp + 1][n]);
    }
}

// ---------------------------------------------------------------------------
// wcvt: convert wq/wv/wt to fp16 pairs; also zero BN accumulators
// ---------------------------------------------------------------------------
__global__ __launch_bounds__(256) void wcvt_kernel(
    const float* __restrict__ wq, const float* __restrict__ wv,
    const float* __restrict__ wt)
{
    int idx = blockIdx.x * 256 + threadIdx.x;
    if (idx < 256) { g_bnsum[idx] = 0.f; g_bnsum2[idx] = 0.f; }
    if (idx < 8192) {
        float2 f = *reinterpret_cast<const float2*>(&wq[idx * 2]);
        g_wqh[idx] = pack_h2(f.x, f.y);
    } else if (idx < 8192 + 32768) {
        int i = idx - 8192;
        float2 f = *reinterpret_cast<const float2*>(&wv[i * 2]);
        g_wvh[i] = pack_h2(f.x, f.y);
    } else if (idx < 8192 + 65536) {
        int i = idx - 8192 - 32768;
        float2 f = *reinterpret_cast<const float2*>(&wt[i * 2]);
        g_wth[i] = pack_h2(f.x, f.y);
    }
}

// ---------------------------------------------------------------------------
// convq_tc: q^T[n][o] = x^T[n][:] . wq[o][:]  -> g_qh[(b*N+n)*32 + o/2]
// (scalar LDS — higher MLP wins at 8 warps/CTA)
// ---------------------------------------------------------------------------
__global__ __launch_bounds__(256) void convq_tc_kernel()
{
    const int b  = blockIdx.z;
    const int n0 = blockIdx.x * 128;
    const unsigned* xth = g_xth + (size_t)b * NN * 128;

    __shared__ unsigned sA[128][36];
    __shared__ unsigned sB[64][36];

    const int tid = threadIdx.x;
    const int lane = tid & 31, wid = tid >> 5;
    const int wm = wid >> 2, wn = wid & 3;
    const int gp = lane >> 2, tg = lane & 3;

    float acc[4][2][4] = {};

    for (int ks = 0; ks < 4; ks++) {
        int kp0g = ks * 32;
        __syncthreads();
#pragma unroll
        for (int r = 0; r < 16; r++) {
            int idx = tid + r * 256;
            int row = idx >> 5, kp = idx & 31;
            sA[row][kp] = xth[(size_t)(n0 + row) * 128 + kp0g + kp];
        }
#pragma unroll
        for (int r = 0; r < 8; r++) {
            int idx = tid + r * 256;
            int row = idx >> 5, kp = idx & 31;
            sB[row][kp] = g_wqh[(size_t)row * 128 + kp0g + kp];
        }
        __syncthreads();
#pragma unroll
        for (int kk = 0; kk < 4; kk++) {
            int kp0 = kk * 8;
            unsigned a[4][4], bf[2][2];
#pragma unroll
            for (int i = 0; i < 4; i++) {
                int row = wm * 64 + i * 16 + gp;
                a[i][0] = sA[row][kp0 + tg];
                a[i][1] = sA[row + 8][kp0 + tg];
                a[i][2] = sA[row][kp0 + 4 + tg];
                a[i][3] = sA[row + 8][kp0 + 4 + tg];
            }
#pragma unroll
            for (int j = 0; j < 2; j++) {
                int col = wn * 16 + j * 8 + gp;
                bf[j][0] = sB[col][kp0 + tg];
                bf[j][1] = sB[col][kp0 + 4 + tg];
            }
#pragma unroll
            for (int i = 0; i < 4; i++)
#pragma unroll
                for (int j = 0; j < 2; j++)
                    mma_fp16(acc[i][j], a[i][0], a[i][1], a[i][2], a[i][3],
                             bf[j][0], bf[j][1]);
        }
    }

#pragma unroll
    for (int i = 0; i < 4; i++) {
        int n = n0 + wm * 64 + i * 16 + gp;
#pragma unroll
        for (int j = 0; j < 2; j++) {
            int op = wn * 8 + j * 4 + tg;
            g_qh[((size_t)b * NN + n) * 32 + op]     = pack_h2(acc[i][j][0], acc[i][j][1]);
            g_qh[((size_t)b * NN + n + 8) * 32 + op] = pack_h2(acc[i][j][2], acc[i][j][3]);
        }
    }
}

// ---------------------------------------------------------------------------
// convv_tc: v[o][n] = wv[o][:] . x^T[n][:] + bv.  512 threads, CTA covers
// ALL 256 channels x 128 n  -> grid 32x4 = 128 CTAs (one wave).
// ---------------------------------------------------------------------------
#define CV_W_SA 0
#define CV_W_SB (256 * 36)
#define CV_SMEM_WORDS (CV_W_SB + 128 * 36)

__global__ __launch_bounds__(512, 1) void convv_tc_kernel(const float* __restrict__ bias)
{
    const int b  = blockIdx.y;
    const int n0 = blockIdx.x * 128;
    const unsigned* xth = g_xth + (size_t)b * NN * 128;

    extern __shared__ unsigned shm[];
    unsigned (*sA)[36] = reinterpret_cast<unsigned(*)[36]>(shm + CV_W_SA);  // wv [256][36]
    unsigned (*sB)[36] = reinterpret_cast<unsigned(*)[36]>(shm + CV_W_SB);  // x^T [128][36]

    const int tid = threadIdx.x;
    const int lane = tid & 31, wid = tid >> 5;
    const int wm = wid >> 2, wn = wid & 3;
    const int gp = lane >> 2, tg = lane & 3;

    float acc[4][4][4] = {};

    for (int ks = 0; ks < 4; ks++) {
        int kp0g = ks * 32;
        __syncthreads();
#pragma unroll
        for (int r = 0; r < 16; r++) {
            int idx = tid + r * 512;
            int row = idx >> 5, kp = idx & 31;
            sA[row][kp] = g_wvh[(size_t)row * 128 + kp0g + kp];
        }
#pragma unroll
        for (int r = 0; r < 8; r++) {
            int idx = tid + r * 512;
            int row = idx >> 5, kp = idx & 31;
            sB[row][kp] = xth[(size_t)(n0 + row) * 128 + kp0g + kp];
        }
        __syncthreads();
#pragma unroll
        for (int kk = 0; kk < 4; kk++) {
            int kp0 = kk * 8;
            unsigned a[4][4], bf[4][2];
#pragma unroll
            for (int i = 0; i < 4; i++) {
                int row = wm * 64 + i * 16 + gp;
                a[i][0] = sA[row][kp0 + tg];
                a[i][1] = sA[row + 8][kp0 + tg];
                a[i][2] = sA[row][kp0 + 4 + tg];
                a[i][3] = sA[row + 8][kp0 + 4 + tg];
            }
#pragma unroll
            for (int j = 0; j < 4; j++) {
                int col = wn * 32 + j * 8 + gp;
                bf[j][0] = sB[col][kp0 + tg];
                bf[j][1] = sB[col][kp0 + 4 + tg];
            }
#pragma unroll
            for (int i = 0; i < 4; i++)
#pragma unroll
                for (int j = 0; j < 4; j++)
                    mma_fp16(acc[i][j], a[i][0], a[i][1], a[i][2], a[i][3],
                             bf[j][0], bf[j][1]);
        }
    }

#pragma unroll
    for (int i = 0; i < 4; i++) {
        int o = wm * 64 + i * 16 + gp;
        float b0 = bias[o], b1 = bias[o + 8];
#pragma unroll
        for (int j = 0; j < 4; j++) {
            int np = (n0 + wn * 32 + j * 8 + 2 * tg) / 2;
            g_vh[((size_t)b * CC + o) * (NN / 2) + np] =
                pack_h2(acc[i][j][0] + b0, acc[i][j][1] + b0);
            g_vh[((size_t)b * CC + o + 8) * (NN / 2) + np] =
                pack_h2(acc[i][j][2] + b1, acc[i][j][3] + b1);
        }
    }
}

// ---------------------------------------------------------------------------
// convt_tc: t[o][n] = wt[o][:] . (x^T - x_a^T)[n][:] + bt  -> g_t fp32.
// 512 threads, all 256 channels, one wave. Fused BN partial sums.
// ---------------------------------------------------------------------------
#define CT_W_SA 0
#define CT_W_SB (256 * 36)
#define CT_W_SS (CT_W_SB + 128 * 36)
#define CT_SMEM_WORDS (CT_W_SS + 512)

__global__ __launch_bounds__(512, 1) void convt_tc_kernel(const float* __restrict__ bias)
{
    const int b  = blockIdx.y;
    const int n0 = blockIdx.x * 128;
    const unsigned* xth  = g_xth  + (size_t)b * NN * 128;
    const unsigned* xath = g_xaTh + (size_t)b * NN * 128;

    extern __shared__ unsigned shm[];
    unsigned (*sA)[36] = reinterpret_cast<unsigned(*)[36]>(shm + CT_W_SA);  // wt [256][36]
    unsigned (*sB)[36] = reinterpret_cast<unsigned(*)[36]>(shm + CT_W_SB);  // xd [128][36]
    float* sS  = reinterpret_cast<float*>(shm + CT_W_SS);
    float* sS2 = sS + 256;

    const int tid = threadIdx.x;
    const int lane = tid & 31, wid = tid >> 5;
    const int wm = wid >> 2, wn = wid & 3;
    const int gp = lane >> 2, tg = lane & 3;

    if (tid < 256) { sS[tid] = 0.f; sS2[tid] = 0.f; }

    float acc[4][4][4] = {};

    for (int ks = 0; ks < 4; ks++) {
        int kp0g = ks * 32;
        __syncthreads();
#pragma unroll
        for (int r = 0; r < 16; r++) {
            int idx = tid + r * 512;
            int row = idx >> 5, kp = idx & 31;
            sA[row][kp] = g_wth[(size_t)row * 128 + kp0g + kp];
        }
#pragma unroll
        for (int r = 0; r < 8; r++) {
            int idx = tid + r * 512;
            int row = idx >> 5, kp = idx & 31;
            size_t gi = (size_t)(n0 + row) * 128 + kp0g + kp;
            __half2 xv = *reinterpret_cast<const __half2*>(&xth[gi]);
            __half2 av = *reinterpret_cast<const __half2*>(&xath[gi]);
            __half2 d = __hsub2(xv, av);
            sB[row][kp] = *reinterpret_cast<unsigned*>(&d);
        }
        __syncthreads();
#pragma unroll
        for (int kk = 0; kk < 4; kk++) {
            int kp0 = kk * 8;
            unsigned a[4][4], bf[4][2];
#pragma unroll
            for (int i = 0; i < 4; i++) {
                int row = wm * 64 + i * 16 + gp;
                a[i][0] = sA[row][kp0 + tg];
                a[i][1] = sA[row + 8][kp0 + tg];
                a[i][2] = sA[row][kp0 + 4 + tg];
                a[i][3] = sA[row + 8][kp0 + 4 + tg];
            }
#pragma unroll
            for (int j = 0; j < 4; j++) {
                int col = wn * 32 + j * 8 + gp;
                bf[j][0] = sB[col][kp0 + tg];
                bf[j][1] = sB[col][kp0 + 4 + tg];
            }
#pragma unroll
            for (int i = 0; i < 4; i++)
#pragma unroll
                for (int j = 0; j < 4; j++)
                    mma_fp16(acc[i][j], a[i][0], a[i][1], a[i][2], a[i][3],
                             bf[j][0], bf[j][1]);
        }
    }

#pragma unroll
    for (int i = 0; i < 4; i++) {
        int o = wm * 64 + i * 16 + gp;
        float b0 = bias[o], b1 = bias[o + 8];
        float sa = 0.f, sa2 = 0.f, sb = 0.f, sb2 = 0.f;
#pragma unroll
        for (int j = 0; j < 4; j++) {
            int n = n0 + wn * 32 + j * 8 + 2 * tg;
            float t00 = acc[i][j][0] + b0, t01 = acc[i][j][1] + b0;
            float t10 = acc[i][j][2] + b1, t11 = acc[i][j][3] + b1;
            sa += t00 + t01;  sa2 += t00 * t00 + t01 * t01;
            sb += t10 + t11;  sb2 += t10 * t10 + t11 * t11;
            *reinterpret_cast<float2*>(&g_t[((size_t)b * CC + o) * NN + n]) =
                make_float2(t00, t01);
            *reinterpret_cast<float2*>(&g_t[((size_t)b * CC + o + 8) * NN + n]) =
                make_float2(t10, t11);
        }
#pragma unroll
        for (int off = 1; off <= 2; off <<= 1) {
            sa  += __shfl_xor_sync(0xffffffffu, sa,  off);
            sa2 += __shfl_xor_sync(0xffffffffu, sa2, off);
            sb  += __shfl_xor_sync(0xffffffffu, sb,  off);
            sb2 += __shfl_xor_sync(0xffffffffu, sb2, off);
        }
        if (tg == 0) {
            atomicAdd(&sS[o], sa);      atomicAdd(&sS2[o], sa2);
            atomicAdd(&sS[o + 8], sb);  atomicAdd(&sS2[o + 8], sb2);
        }
    }
    __syncthreads();
    if (tid < 256) {
        atomicAdd(&g_bnsum[tid], sS[tid]);
        atomicAdd(&g_bnsum2[tid], sS2[tid]);
    }
}

// ---------------------------------------------------------------------------
// bnfin: mean/rstd from accumulated sums (1 block)
// ---------------------------------------------------------------------------
__global__ void bnfin_kernel()
{
    int c = threadIdx.x;
    const float invM = 1.f / (float)(BB * NN);
    float mean = g_bnsum[c] * invM;
    float var = g_bnsum2[c] * invM - mean * mean;
    g_mean[c] = mean;
    g_rstd[c] = rsqrtf(var + 1e-5f);
}

// ---------------------------------------------------------------------------
// pass1: fused energy + row softmax stats, cp.async double-buffered B tile,
// single sync per chunk (xa-style pipeline).
// ---------------------------------------------------------------------------
#define P1_W_SA 0
#define P1_W_SB (128 * 36)
#define P1_W_MRG (P1_W_SB + 2 * 128 * 36)
#define P1_SMEM_WORDS (P1_W_MRG + 4 * 128 * 2)

__global__ __launch_bounds__(256) void pass1_kernel()
{
    const int b  = blockIdx.y;
    const int n0 = blockIdx.x * 128;
    const unsigned* qh = g_qh + (size_t)b * NN * 32;

    extern __shared__ unsigned shm[];
    unsigned (*sA)[36] = reinterpret_cast<unsigned(*)[36]>(shm + P1_W_SA);
    float2* sMrg = reinterpret_cast<float2*>(shm + P1_W_MRG);   // [wn][row] = [4][128]
    const unsigned sbase = (unsigned)__cvta_generic_to_shared(shm);

    const int tid = threadIdx.x;
    const int lane = tid & 31, wid = tid >> 5;
    const int wm = wid >> 2, wn = wid & 3;
    const int gp = lane >> 2, tg = lane & 3;

#pragma unroll
    for (int r = 0; r < 16; r++) {
        int idx = tid + r * 256;
        int row = idx >> 5, kp = idx & 31;
        sA[row][kp] = qh[(size_t)(n0 + row) * 32 + kp];
    }

    auto issue_B = [&](int chunk) {
        int buf = chunk & 1;
        int m0 = chunk * 128;
#pragma unroll
        for (int t = 0; t < 4; t++) {
            int idx = tid + t * 256;
            int row = idx >> 3, seg = idx & 7;
            unsigned dst = sbase + (P1_W_SB + buf * 128 * 36 + row * 36 + seg * 4) * 4;
            cpa16(dst, qh + (size_t)(m0 + row) * 32 + seg * 4);
        }
        cpa_commit();
    };

    float rmax[8], rsum[8];
#pragma unroll
    for (int i = 0; i < 8; i++) { rmax[i] = -1e30f; rsum[i] = 0.f; }

    issue_B(0);
    issue_B(1);
    cpa_wait0();
    __syncthreads();

    for (int ch = 0; ch < 32; ch++) {
        unsigned (*sB)[36] = reinterpret_cast<unsigned(*)[36]>(
            shm + P1_W_SB + (ch & 1) * 128 * 36);

        float acc[4][4][4] = {};
#pragma unroll
        for (int ks = 0; ks < 4; ks++) {
            int kp0 = ks * 8;
            unsigned a[4][4], bf[4][2];
#pragma unroll
            for (int i = 0; i < 4; i++) {
                int row = wm * 64 + i * 16 + gp;
                a[i][0] = sA[row][kp0 + tg];
                a[i][1] = sA[row + 8][kp0 + tg];
                a[i][2] = sA[row][kp0 + 4 + tg];
                a[i][3] = sA[row + 8][kp0 + 4 + tg];
            }
#pragma unroll
            for (int j = 0; j < 4; j++) {
                int col = wn * 32 + j * 8 + gp;
                bf[j][0] = sB[col][kp0 + tg];
                bf[j][1] = sB[col][kp0 + 4 + tg];
            }
#pragma unroll
            for (int i = 0; i < 4; i++)
#pragma unroll
                for (int j = 0; j < 4; j++)
                    mma_fp16(acc[i][j], a[i][0], a[i][1], a[i][2], a[i][3],
                             bf[j][0], bf[j][1]);
        }

#pragma unroll
        for (int i = 0; i < 4; i++) {
            float m0v = -1e30f, m1v = -1e30f;
#pragma unroll
            for (int j = 0; j < 4; j++) {
                m0v = fmaxf(m0v, fmaxf(acc[i][j][0], acc[i][j][1]));
                m1v = fmaxf(m1v, fmaxf(acc[i][j][2], acc[i][j][3]));
            }
            m0v = fmaxf(m0v, __shfl_xor_sync(0xffffffffu, m0v, 1));
            m0v = fmaxf(m0v, __shfl_xor_sync(0xffffffffu, m0v, 2));
            m1v = fmaxf(m1v, __shfl_xor_sync(0xffffffffu, m1v, 1));
            m1v = fmaxf(m1v, __shfl_xor_sync(0xffffffffu, m1v, 2));
            float nm0 = fmaxf(rmax[2 * i],     m0v);
            float nm1 = fmaxf(rmax[2 * i + 1], m1v);
            float s0 = 0.f, s1 = 0.f;
#pragma unroll
            for (int j = 0; j < 4; j++) {
                s0 += __expf(acc[i][j][0] - nm0) + __expf(acc[i][j][1] - nm0);
                s1 += __expf(acc[i][j][2] - nm1) + __expf(acc[i][j][3] - nm1);
            }
            s0 += __shfl_xor_sync(0xffffffffu, s0, 1);
            s0 += __shfl_xor_sync(0xffffffffu, s0, 2);
            s1 += __shfl_xor_sync(0xffffffffu, s1, 1);
            s1 += __shfl_xor_sync(0xffffffffu, s1, 2);
            rsum[2 * i]     = rsum[2 * i]     * __expf(rmax[2 * i]     - nm0) + s0;
            rsum[2 * i + 1] = rsum[2 * i + 1] * __expf(rmax[2 * i + 1] - nm1) + s1;
            rmax[2 * i]     = nm0;
            rmax[2 * i + 1] = nm1;
        }

        cpa_wait0();       // loads for chunk ch+1 complete
        __syncthreads();   // all warps done reading buffer ch&1
        if (ch + 2 < 32)
            issue_B(ch + 2);
    }

    if (tg == 0) {
#pragma unroll
        for (int i = 0; i < 4; i++) {
            int row = wm * 64 + i * 16 + gp;
            sMrg[wn * 128 + row]     = make_float2(rmax[2 * i],     rsum[2 * i]);
            sMrg[wn * 128 + row + 8] = make_float2(rmax[2 * i + 1], rsum[2 * i + 1]);
        }
    }
    __syncthreads();
    if (tid < 128) {
        float2 v0 = sMrg[tid], v1 = sMrg[128 + tid];
        float2 v2 = sMrg[256 + tid], v3 = sMrg[384 + tid];
        float M = fmaxf(fmaxf(v0.x, v1.x), fmaxf(v2.x, v3.x));
        float S = v0.y * __expf(v0.x - M) + v1.y * __expf(v1.x - M)
                + v2.y * __expf(v2.x - M) + v3.y * __expf(v3.x - M);
        g_rowmax[b * NN + n0 + tid] = M;
        g_rowinv[b * NN + n0 + tid] = 1.f / S;
    }
}

// ---------------------------------------------------------------------------
// xa: fused E-recompute + P + x_a^T, single-sync pipeline, ldmatrix loads,
// register colsum. (R14 proven-best)
// ---------------------------------------------------------------------------
#define XA_W_SVH 0
#define XA_W_SQM (2 * 256 * 36)
#define XA_W_SQN (XA_W_SQM + 128 * 36)
#define XA_W_SPH (XA_W_SQN + 2 * 64 * 36)
#define XA_W_COL (XA_W_SPH + 2 * 128 * 36)
#define XA_SMEM_WORDS (XA_W_COL + 128)

__global__ __launch_bounds__(512, 1) void xa_kernel()
{
    const int b  = blockIdx.y;
    const int m0 = blockIdx.x * 128;
    const unsigned* vbh = g_vh + (size_t)b * CC * (NN / 2);
    const float* rmx = g_rowmax + b * NN;
    const float* rin = g_rowinv + b * NN;
    const unsigned* qh = g_qh + (size_t)b * NN * 32;

    extern __shared__ unsigned shm[];
    unsigned (*sQm)[36] = reinterpret_cast<unsigned(*)[36]>(shm + XA_W_SQM);
    float* sCol = reinterpret_cast<float*>(shm + XA_W_COL);
    const unsigned sbase = (unsigned)__cvta_generic_to_shared(shm);

    const int tid = threadIdx.x;
    const int lane = tid & 31, wid = tid >> 5;
    const int gp = lane >> 2, tg = lane & 3;
    const int nh = wid & 3, mh = wid >> 2;       // mma1 roles (4x4)
    const int wm = wid >> 2, wn = wid & 3;       // mma2 roles

#pragma unroll
    for (int r = 0; r < 8; r++) {
        int idx = tid + r * 512;
        int row = idx >> 5, kp = idx & 31;
        sQm[row][kp] = qh[(size_t)(m0 + row) * 32 + kp];
    }
    if (tid < 128) sCol[tid] = 0.f;

    float cs[8];
#pragma unroll
    for (int j = 0; j < 8; j++) cs[j] = 0.f;

    auto issue_V = [&](int chunk) {
        int buf = chunk & 1;
        int np0 = chunk * 32;
#pragma unroll
        for (int t = 0; t < 4; t++) {
            int idx = tid + t * 512;
            int row = idx >> 3, seg = idx & 7;
            unsigned dst = sbase + (XA_W_SVH + buf * 256 * 36 + row * 36 + seg * 4) * 4;
            cpa16(dst, vbh + (size_t)row * (NN / 2) + np0 + seg * 4);
        }
    };
    auto issue_Qn = [&](int chunk) {
        int buf = chunk & 1;
        int row = tid >> 3, seg = tid & 7;
        unsigned dst = sbase + (XA_W_SQN + buf * 64 * 36 + row * 36 + seg * 4) * 4;
        cpa16(dst, qh + (size_t)(chunk * 64 + row) * 32 + seg * 4);
    };

    auto do_mma1 = [&](int chunk) {
        int buf = chunk & 1;
        int WQn = XA_W_SQN + buf * 64 * 36;
        __half (*sPhB)[72] = reinterpret_cast<__half(*)[72]>(shm + XA_W_SPH + buf * 128 * 36);
        float e[4][4] = {};
#pragma unroll
        for (int ks = 0; ks < 4; ks++) {
            int kp0 = ks * 8;
            unsigned a0, a1, a2, a3, bf[4][2];
            ldsm4(a0, a1, a2, a3, adrA(sbase, WQn, 36, nh * 16, kp0, lane));
            ldsm4(bf[0][0], bf[0][1], bf[1][0], bf[1][1],
                  adrB(sbase, XA_W_SQM, 36, mh * 32, kp0, lane));
            ldsm4(bf[2][0], bf[2][1], bf[3][0], bf[3][1],
                  adrB(sbase, XA_W_SQM, 36, mh * 32 + 16, kp0, lane));
#pragma unroll
            for (int j = 0; j < 4; j++)
                mma_fp16(e[j], a0, a1, a2, a3, bf[j][0], bf[j][1]);
        }
        int r0 = chunk * 64 + nh * 16 + gp;
        float mx0 = __ldg(&rmx[r0]),     iv0 = __ldg(&rin[r0]);
        float mx1 = __ldg(&rmx[r0 + 8]), iv1 = __ldg(&rin[r0 + 8]);
        int nr0 = nh * 16 + gp, nr1 = nr0 + 8;
#pragma unroll
        for (int j = 0; j < 4; j++) {
            int cb = mh * 32 + j * 8 + 2 * tg;
            __half h00 = __float2half(__expf(e[j][0] - mx0) * iv0);
            __half h01 = __float2half(__expf(e[j][1] - mx0) * iv0);
            __half h10 = __float2half(__expf(e[j][2] - mx1) * iv1);
            __half h11 = __float2half(__expf(e[j][3] - mx1) * iv1);
            sPhB[cb][nr0]     = h00;
            sPhB[cb + 1][nr0] = h01;
            sPhB[cb][nr1]     = h10;
            sPhB[cb + 1][nr1] = h11;
            cs[2 * j]     += __half2float(h00) + __half2float(h10);
            cs[2 * j + 1] += __half2float(h01) + __half2float(h11);
        }
    };

    issue_V(0); issue_V(1); issue_Qn(0); issue_Qn(1); cpa_commit();
    cpa_wait0();
    __syncthreads();

    do_mma1(0);
    __syncthreads();
    issue_Qn(2); cpa_commit();

    float acc[2][8][4] = {};

    for (int i = 0; i < 64; i++) {
        const int buf = i & 1;
        int WV = XA_W_SVH + buf * 256 * 36;
        int WP = XA_W_SPH + buf * 128 * 36;

        if (i < 63)
            do_mma1(i + 1);

#pragma unroll
        for (int ks = 0; ks < 4; ks++) {
            int kp0 = ks * 8;
            unsigned pa[2][4], bf[8][2];
#pragma unroll
            for (int ii = 0; ii < 2; ii++)
                ldsm4(pa[ii][0], pa[ii][1], pa[ii][2], pa[ii][3],
                      adrA(sbase, WP, 36, wm * 32 + ii * 16, kp0, lane));
#pragma unroll
            for (int g = 0; g < 4; g++)
                ldsm4(bf[2 * g][0], bf[2 * g][1], bf[2 * g + 1][0], bf[2 * g + 1][1],
                      adrB(sbase, WV, 36, wn * 64 + g * 16, kp0, lane));
#pragma unroll
            for (int ii = 0; ii < 2; ii++)
#pragma unroll
                for (int j = 0; j < 8; j++)
                    mma_fp16(acc[ii][j], pa[ii][0], pa[ii][1], pa[ii][2], pa[ii][3],
                             bf[j][0], bf[j][1]);
        }

        cpa_wait0();
        __syncthreads();
        if (i + 2 < 64) issue_V(i + 2);
        if (i + 3 < 64) issue_Qn(i + 3);
        cpa_commit();
    }

#pragma unroll
    for (int j = 0; j < 8; j++) {
        float v = cs[j];
        v += __shfl_xor_sync(0xffffffffu, v, 4);
        v += __shfl_xor_sync(0xffffffffu, v, 8);
        v += __shfl_xor_sync(0xffffffffu, v, 16);
        cs[j] = v;
    }
    if (gp == 0) {
#pragma unroll
        for (int j = 0; j < 4; j++) {
            int cb = mh * 32 + j * 8 + 2 * tg;
            atomicAdd(&sCol[cb], cs[2 * j]);
            atomicAdd(&sCol[cb + 1], cs[2 * j + 1]);
        }
    }
    __syncthreads();

#pragma unroll
    for (int ii = 0; ii < 2; ii++) {
        int mr = wm * 32 + ii * 16 + gp;
        float i0 = 1.f / (1e-9f + sCol[mr]);
        float i1 = 1.f / (1e-9f + sCol[mr + 8]);
        size_t r0 = ((size_t)b * NN + m0 + mr) * 128;
        size_t r1 = r0 + 8 * 128;
#pragma unroll
        for (int j = 0; j < 8; j++) {
            int cp = wn * 32 + j * 4 + tg;
            g_xaTh[r0 + cp] = pack_h2(acc[ii][j][0] * i0, acc[ii][j][1] * i0);
            g_xaTh[r1 + cp] = pack_h2(acc[ii][j][2] * i1, acc[ii][j][3] * i1);
        }
    }
}

// ---------------------------------------------------------------------------
// Final: out = x + relu(gamma * (t - mean) * rstd + beta)
// ---------------------------------------------------------------------------
__global__ __launch_bounds__(256) void final_kernel(
    const float* __restrict__ x, const float* __restrict__ gamma,
    const float* __restrict__ beta, float* __restrict__ out)
{
    size_t i = (size_t)blockIdx.x * 256 + threadIdx.x;
    int c = (int)((i >> 12) & 255);
    float t = g_t[i];
    float th = (t - g_mean[c]) * g_rstd[c];
    float r = fmaxf(0.f, gamma[c] * th + beta[c]);
    out[i] = x[i] + r;
}

// ---------------------------------------------------------------------------
extern "C" void kernel_launch(void* const* d_in, const int* in_sizes, int n_in,
                              void* d_out, int out_size)
{
    const float* x     = (const float*)d_in[0];
    const float* wq    = (const float*)d_in[1];
    const float* wv    = (const float*)d_in[2];
    const float* bv    = (const float*)d_in[3];
    const float* wt    = (const float*)d_in[4];
    const float* bt    = (const float*)d_in[5];
    const float* gamma = (const float*)d_in[6];
    const float* beta  = (const float*)d_in[7];
    float* out = (float*)d_out;

    const int xa_smem = XA_SMEM_WORDS * 4;
    const int cv_smem = CV_SMEM_WORDS * 4;
    const int ct_smem = CT_SMEM_WORDS * 4;
    const int p1_smem = P1_SMEM_WORDS * 4;
    cudaFuncSetAttribute(xa_kernel,
                         cudaFuncAttributeMaxDynamicSharedMemorySize, xa_smem);
    cudaFuncSetAttribute(convv_tc_kernel,
                         cudaFuncAttributeMaxDynamicSharedMemorySize, cv_smem);
    cudaFuncSetAttribute(convt_tc_kernel,
                         cudaFuncAttributeMaxDynamicSharedMemorySize, ct_smem);
    cudaFuncSetAttribute(pass1_kernel,
                         cudaFuncAttributeMaxDynamicSharedMemorySize, p1_smem);

    // x^T fp16 + weight fp16 conversions (also zeroes BN accumulators)
    xt_kernel<<<dim3(NN / 64, CC / 64, BB), 256>>>(x);
    wcvt_kernel<<<(8192 + 65536 + 255) / 256, 256>>>(wq, wv, wt);
    // q^T = x^T wq^T  (weight-tied Q/K), fp16 mma
    convq_tc_kernel<<<dim3(NN / 128, 1, BB), 256>>>();
    // v = wv x + bv, fp16 mma (one wave, 512 threads)
    convv_tc_kernel<<<dim3(NN / 128, BB), 512, cv_smem>>>(bv);
    // fused energy + row softmax stats (cp.async pipeline)
    pass1_kernel<<<dim3(NN / 128, BB), 256, p1_smem>>>();
    // fused E-recompute + softmax + double-norm + x_a^T (register colsum)
    xa_kernel<<<dim3(NN / 128, BB), 512, xa_smem>>>();
    // t = wt (x - x_a) + bt, fp16 mma, fused BN partial sums (one wave)
    convt_tc_kernel<<<dim3(NN / 128, BB), 512, ct_smem>>>(bt);
    // BN finalize + fused relu/residual
    bnfin_kernel<<<1, CC>>>();
    final_kernel<<<(BB * CC * NN) / 256, 256>>>(x, gamma, beta, out);
}

// round 16
// speedup vs baseline: 1.1215x; 1.0052x over previous
#include <cuda_runtime.h>
#include <cuda_fp16.h>
#include <cstdint>

#define BB 4
#define CC 256
#define NN 4096
#define DD 64

// Scratch (device globals: allocation-free kernel_launch)
__device__ unsigned g_qh[(size_t)BB * NN * 32];         // 2 MB  q fp16 pairs [b][n][d/2]
__device__ unsigned g_vh[(size_t)BB * CC * (NN / 2)];   // 8 MB  v fp16 pairs [b][c][n/2]
__device__ unsigned g_xth[(size_t)BB * NN * (CC / 2)];  // 8 MB  x^T fp16 pairs [b][n][c/2]
__device__ unsigned g_xaTh[(size_t)BB * NN * (CC / 2)]; // 8 MB  x_a^T fp16 pairs [b][n][c/2]
__device__ unsigned g_wqh[DD * (CC / 2)];               // wq fp16 pairs [o][c/2]
__device__ unsigned g_wvh[CC * (CC / 2)];
__device__ unsigned g_wth[CC * (CC / 2)];
__device__ float g_rowmax[BB * NN];
__device__ float g_rowinv[BB * NN];
__device__ float g_t[(size_t)BB * CC * NN];             // 16 MB
__device__ float g_bnsum[CC];
__device__ float g_bnsum2[CC];
__device__ float g_mean[CC];
__device__ float g_rstd[CC];

// ---------------------------------------------------------------------------
// helpers
// ---------------------------------------------------------------------------
__device__ __forceinline__ void mma_fp16(
    float* c,
    unsigned a0, unsigned a1, unsigned a2, unsigned a3,
    unsigned b0, unsigned b1)
{
    asm volatile(
        "mma.sync.aligned.m16n8k16.row.col.f32.f16.f16.f32 "
        "{%0,%1,%2,%3}, {%4,%5,%6,%7}, {%8,%9}, {%0,%1,%2,%3};\n"
        : "+f"(c[0]), "+f"(c[1]), "+f"(c[2]), "+f"(c[3])
        : "r"(a0), "r"(a1), "r"(a2), "r"(a3), "r"(b0), "r"(b1));
}

__device__ __forceinline__ void ldsm4(
    unsigned& r0, unsigned& r1, unsigned& r2, unsigned& r3, unsigned addr)
{
    asm volatile(
        "ldmatrix.sync.aligned.m8n8.x4.shared.b16 {%0,%1,%2,%3}, [%4];\n"
        : "=r"(r0), "=r"(r1), "=r"(r2), "=r"(r3) : "r"(addr));
}

// A-layout x4 address
__device__ __forceinline__ unsigned adrA(unsigned sb, int Wwords, int stride,
                                         int row0, int kp0, int lane)
{
    int row = row0 + ((lane >> 3) & 1) * 8 + (lane & 7);
    int col = kp0 + ((lane >> 4) & 1) * 4;
    return sb + (unsigned)(Wwords + row * stride + col) * 4u;
}

// B-layout x4 address
__device__ __forceinline__ unsigned adrB(unsigned sb, int Wwords, int stride,
                                         int col0, int kp0, int lane)
{
    int row = col0 + ((lane >> 4) & 1) * 8 + (lane & 7);
    int col = kp0 + ((lane >> 3) & 1) * 4;
    return sb + (unsigned)(Wwords + row * stride + col) * 4u;
}

__device__ __forceinline__ void cpa16(unsigned sdst, const void* gsrc)
{
    asm volatile("cp.async.cg.shared.global [%0], [%1], 16;\n"
                 :: "r"(sdst), "l"(gsrc));
}
__device__ __forceinline__ void cpa_commit()
{
    asm volatile("cp.async.commit_group;\n");
}
__device__ __forceinline__ void cpa_wait0()
{
    asm volatile("cp.async.wait_group 0;\n");
}

__device__ __forceinline__ unsigned pack_h2(float a, float b)
{
    __half2 h = __floats2half2_rn(a, b);
    return *reinterpret_cast<unsigned*>(&h);
}

// ---------------------------------------------------------------------------
// xt: transpose + convert x[b][c][n] fp32 -> g_xth[(b*N+n)*128 + c/2] fp16 pairs
// ---------------------------------------------------------------------------
__global__ __launch_bounds__(256) void xt_kernel(const float* __restrict__ x)
{
    const int b  = blockIdx.z;
    const int c0 = blockIdx.y * 64;
    const int n0 = blockIdx.x * 64;
    const float* xb = x + ((size_t)b * CC + c0) * NN + n0;

    __shared__ float sT[64][65];
    const int tid = threadIdx.x;

#pragma unroll
    for (int r = 0; r < 16; r++) {
        int idx = tid + r * 256;
        int c = idx >> 6, n = idx & 63;
        sT[c][n] = xb[(size_t)c * NN + n];
    }
    __syncthreads();
#pragma unroll
    for (int r = 0; r < 8; r++) {
        int idx = tid + r * 256;
        int n = idx >> 5, cp = idx & 31;
        g_xth[((size_t)b * NN + n0 + n) * 128 + c0 / 2 + cp] =
            pack_h2(sT[2 * cp][n], sT[2 * cp + 1][n]);
    }
}

// ---------------------------------------------------------------------------
// wcvt: convert wq/wv/wt to fp16 pairs; also zero BN accumulators
// ---------------------------------------------------------------------------
__global__ __launch_bounds__(256) void wcvt_kernel(
    const float* __restrict__ wq, const float* __restrict__ wv,
    const float* __restrict__ wt)
{
    int idx = blockIdx.x * 256 + threadIdx.x;
    if (idx < 256) { g_bnsum[idx] = 0.f; g_bnsum2[idx] = 0.f; }
    if (idx < 8192) {
        float2 f = *reinterpret_cast<const float2*>(&wq[idx * 2]);
        g_wqh[idx] = pack_h2(f.x, f.y);
    } else if (idx < 8192 + 32768) {
        int i = idx - 8192;
        float2 f = *reinterpret_cast<const float2*>(&wv[i * 2]);
        g_wvh[i] = pack_h2(f.x, f.y);
    } else if (idx < 8192 + 65536) {
        int i = idx - 8192 - 32768;
        float2 f = *reinterpret_cast<const float2*>(&wt[i * 2]);
        g_wth[i] = pack_h2(f.x, f.y);
    }
}

// ---------------------------------------------------------------------------
// convq_tc: q^T[n][o] = x^T[n][:] . wq[o][:]  -> g_qh[(b*N+n)*32 + o/2]
// (scalar LDS — higher MLP wins at 8 warps/CTA)
// ---------------------------------------------------------------------------
__global__ __launch_bounds__(256) void convq_tc_kernel()
{
    const int b  = blockIdx.z;
    const int n0 = blockIdx.x * 128;
    const unsigned* xth = g_xth + (size_t)b * NN * 128;

    __shared__ unsigned sA[128][36];
    __shared__ unsigned sB[64][36];

    const int tid = threadIdx.x;
    const int lane = tid & 31, wid = tid >> 5;
    const int wm = wid >> 2, wn = wid & 3;
    const int gp = lane >> 2, tg = lane & 3;

    float acc[4][2][4] = {};

    for (int ks = 0; ks < 4; ks++) {
        int kp0g = ks * 32;
        __syncthreads();
#pragma unroll
        for (int r = 0; r < 16; r++) {
            int idx = tid + r * 256;
            int row = idx >> 5, kp = idx & 31;
            sA[row][kp] = xth[(size_t)(n0 + row) * 128 + kp0g + kp];
        }
#pragma unroll
        for (int r = 0; r < 8; r++) {
            int idx = tid + r * 256;
            int row = idx >> 5, kp = idx & 31;
            sB[row][kp] = g_wqh[(size_t)row * 128 + kp0g + kp];
        }
        __syncthreads();
#pragma unroll
        for (int kk = 0; kk < 4; kk++) {
            int kp0 = kk * 8;
            unsigned a[4][4], bf[2][2];
#pragma unroll
            for (int i = 0; i < 4; i++) {
                int row = wm * 64 + i * 16 + gp;
                a[i][0] = sA[row][kp0 + tg];
                a[i][1] = sA[row + 8][kp0 + tg];
                a[i][2] = sA[row][kp0 + 4 + tg];
                a[i][3] = sA[row + 8][kp0 + 4 + tg];
            }
#pragma unroll
            for (int j = 0; j < 2; j++) {
                int col = wn * 16 + j * 8 + gp;
                bf[j][0] = sB[col][kp0 + tg];
                bf[j][1] = sB[col][kp0 + 4 + tg];
            }
#pragma unroll
            for (int i = 0; i < 4; i++)
#pragma unroll
                for (int j = 0; j < 2; j++)
                    mma_fp16(acc[i][j], a[i][0], a[i][1], a[i][2], a[i][3],
                             bf[j][0], bf[j][1]);
        }
    }

#pragma unroll
    for (int i = 0; i < 4; i++) {
        int n = n0 + wm * 64 + i * 16 + gp;
#pragma unroll
        for (int j = 0; j < 2; j++) {
            int op = wn * 8 + j * 4 + tg;
            g_qh[((size_t)b * NN + n) * 32 + op]     = pack_h2(acc[i][j][0], acc[i][j][1]);
            g_qh[((size_t)b * NN + n + 8) * 32 + op] = pack_h2(acc[i][j][2], acc[i][j][3]);
        }
    }
}

// ---------------------------------------------------------------------------
// convv_tc: v[o][n] = wv[o][:] . x^T[n][:] + bv  (scalar LDS, 256 threads,
// 128x128 tile, 2 CTAs/SM — proven best config)
// ---------------------------------------------------------------------------
__global__ __launch_bounds__(256) void convv_tc_kernel(const float* __restrict__ bias)
{
    const int b  = blockIdx.z;
    const int o0 = blockIdx.y * 128;
    const int n0 = blockIdx.x * 128;
    const unsigned* xth = g_xth + (size_t)b * NN * 128;

    __shared__ unsigned sA[128][36];
    __shared__ unsigned sB[128][36];

    const int tid = threadIdx.x;
    const int lane = tid & 31, wid = tid >> 5;
    const int wm = wid >> 2, wn = wid & 3;
    const int gp = lane >> 2, tg = lane & 3;

    float acc[4][4][4] = {};

    for (int ks = 0; ks < 4; ks++) {
        int kp0g = ks * 32;
        __syncthreads();
#pragma unroll
        for (int r = 0; r < 16; r++) {
            int idx = tid + r * 256;
            int row = idx >> 5, kp = idx & 31;
            sA[row][kp] = g_wvh[(size_t)(o0 + row) * 128 + kp0g + kp];
            sB[row][kp] = xth[(size_t)(n0 + row) * 128 + kp0g + kp];
        }
        __syncthreads();
#pragma unroll
        for (int kk = 0; kk < 4; kk++) {
            int kp0 = kk * 8;
            unsigned a[4][4], bf[4][2];
#pragma unroll
            for (int i = 0; i < 4; i++) {
                int row = wm * 64 + i * 16 + gp;
                a[i][0] = sA[row][kp0 + tg];
                a[i][1] = sA[row + 8][kp0 + tg];
                a[i][2] = sA[row][kp0 + 4 + tg];
                a[i][3] = sA[row + 8][kp0 + 4 + tg];
            }
#pragma unroll
            for (int j = 0; j < 4; j++) {
                int col = wn * 32 + j * 8 + gp;
                bf[j][0] = sB[col][kp0 + tg];
                bf[j][1] = sB[col][kp0 + 4 + tg];
            }
#pragma unroll
            for (int i = 0; i < 4; i++)
#pragma unroll
                for (int j = 0; j < 4; j++)
                    mma_fp16(acc[i][j], a[i][0], a[i][1], a[i][2], a[i][3],
                             bf[j][0], bf[j][1]);
        }
    }

#pragma unroll
    for (int i = 0; i < 4; i++) {
        int o = o0 + wm * 64 + i * 16 + gp;
        float b0 = bias[o], b1 = bias[o + 8];
#pragma unroll
        for (int j = 0; j < 4; j++) {
            int np = (n0 + wn * 32 + j * 8 + 2 * tg) / 2;
            g_vh[((size_t)b * CC + o) * (NN / 2) + np] =
                pack_h2(acc[i][j][0] + b0, acc[i][j][1] + b0);
            g_vh[((size_t)b * CC + o + 8) * (NN / 2) + np] =
                pack_h2(acc[i][j][2] + b1, acc[i][j][3] + b1);
        }
    }
}

// ---------------------------------------------------------------------------
// convt_tc: t[o][n] = wt[o][:] . (x^T - x_a^T)[n][:] + bt  -> g_t fp32.
// 512 threads, all 256 channels, one wave. Fused BN partial sums.
// ---------------------------------------------------------------------------
#define CT_W_SA 0
#define CT_W_SB (256 * 36)
#define CT_W_SS (CT_W_SB + 128 * 36)
#define CT_SMEM_WORDS (CT_W_SS + 512)

__global__ __launch_bounds__(512, 1) void convt_tc_kernel(const float* __restrict__ bias)
{
    const int b  = blockIdx.y;
    const int n0 = blockIdx.x * 128;
    const unsigned* xth  = g_xth  + (size_t)b * NN * 128;
    const unsigned* xath = g_xaTh + (size_t)b * NN * 128;

    extern __shared__ unsigned shm[];
    unsigned (*sA)[36] = reinterpret_cast<unsigned(*)[36]>(shm + CT_W_SA);  // wt [256][36]
    unsigned (*sB)[36] = reinterpret_cast<unsigned(*)[36]>(shm + CT_W_SB);  // xd [128][36]
    float* sS  = reinterpret_cast<float*>(shm + CT_W_SS);
    float* sS2 = sS + 256;

    const int tid = threadIdx.x;
    const int lane = tid & 31, wid = tid >> 5;
    const int wm = wid >> 2, wn = wid & 3;
    const int gp = lane >> 2, tg = lane & 3;

    if (tid < 256) { sS[tid] = 0.f; sS2[tid] = 0.f; }

    float acc[4][4][4] = {};

    for (int ks = 0; ks < 4; ks++) {
        int kp0g = ks * 32;
        __syncthreads();
#pragma unroll
        for (int r = 0; r < 16; r++) {
            int idx = tid + r * 512;
            int row = idx >> 5, kp = idx & 31;
            sA[row][kp] = g_wth[(size_t)row * 128 + kp0g + kp];
        }
#pragma unroll
        for (int r = 0; r < 8; r++) {
            int idx = tid + r * 512;
            int row = idx >> 5, kp = idx & 31;
            size_t gi = (size_t)(n0 + row) * 128 + kp0g + kp;
            __half2 xv = *reinterpret_cast<const __half2*>(&xth[gi]);
            __half2 av = *reinterpret_cast<const __half2*>(&xath[gi]);
            __half2 d = __hsub2(xv, av);
            sB[row][kp] = *reinterpret_cast<unsigned*>(&d);
        }
        __syncthreads();
#pragma unroll
        for (int kk = 0; kk < 4; kk++) {
            int kp0 = kk * 8;
            unsigned a[4][4], bf[4][2];
#pragma unroll
            for (int i = 0; i < 4; i++) {
                int row = wm * 64 + i * 16 + gp;
                a[i][0] = sA[row][kp0 + tg];
                a[i][1] = sA[row + 8][kp0 + tg];
                a[i][2] = sA[row][kp0 + 4 + tg];
                a[i][3] = sA[row + 8][kp0 + 4 + tg];
            }
#pragma unroll
            for (int j = 0; j < 4; j++) {
                int col = wn * 32 + j * 8 + gp;
                bf[j][0] = sB[col][kp0 + tg];
                bf[j][1] = sB[col][kp0 + 4 + tg];
            }
#pragma unroll
            for (int i = 0; i < 4; i++)
#pragma unroll
                for (int j = 0; j < 4; j++)
                    mma_fp16(acc[i][j], a[i][0], a[i][1], a[i][2], a[i][3],
                             bf[j][0], bf[j][1]);
        }
    }

#pragma unroll
    for (int i = 0; i < 4; i++) {
        int o = wm * 64 + i * 16 + gp;
        float b0 = bias[o], b1 = bias[o + 8];
        float sa = 0.f, sa2 = 0.f, sb = 0.f, sb2 = 0.f;
#pragma unroll
        for (int j = 0; j < 4; j++) {
            int n = n0 + wn * 32 + j * 8 + 2 * tg;
            float t00 = acc[i][j][0] + b0, t01 = acc[i][j][1] + b0;
            float t10 = acc[i][j][2] + b1, t11 = acc[i][j][3] + b1;
            sa += t00 + t01;  sa2 += t00 * t00 + t01 * t01;
            sb += t10 + t11;  sb2 += t10 * t10 + t11 * t11;
            *reinterpret_cast<float2*>(&g_t[((size_t)b * CC + o) * NN + n]) =
                make_float2(t00, t01);
            *reinterpret_cast<float2*>(&g_t[((size_t)b * CC + o + 8) * NN + n]) =
                make_float2(t10, t11);
        }
#pragma unroll
        for (int off = 1; off <= 2; off <<= 1) {
            sa  += __shfl_xor_sync(0xffffffffu, sa,  off);
            sa2 += __shfl_xor_sync(0xffffffffu, sa2, off);
            sb  += __shfl_xor_sync(0xffffffffu, sb,  off);
            sb2 += __shfl_xor_sync(0xffffffffu, sb2, off);
        }
        if (tg == 0) {
            atomicAdd(&sS[o], sa);      atomicAdd(&sS2[o], sa2);
            atomicAdd(&sS[o + 8], sb);  atomicAdd(&sS2[o + 8], sb2);
        }
    }
    __syncthreads();
    if (tid < 256) {
        atomicAdd(&g_bnsum[tid], sS[tid]);
        atomicAdd(&g_bnsum2[tid], sS2[tid]);
    }
}

// ---------------------------------------------------------------------------
// bnfin: mean/rstd from accumulated sums (1 block)
// ---------------------------------------------------------------------------
__global__ void bnfin_kernel()
{
    int c = threadIdx.x;
    const float invM = 1.f / (float)(BB * NN);
    float mean = g_bnsum[c] * invM;
    float var = g_bnsum2[c] * invM - mean * mean;
    g_mean[c] = mean;
    g_rstd[c] = rsqrtf(var + 1e-5f);
}

// ---------------------------------------------------------------------------
// pass1: fused energy + row softmax stats, cp.async double-buffered B tile,
// single sync per chunk (xa-style pipeline).
// ---------------------------------------------------------------------------
#define P1_W_SA 0
#define P1_W_SB (128 * 36)
#define P1_W_MRG (P1_W_SB + 2 * 128 * 36)
#define P1_SMEM_WORDS (P1_W_MRG + 4 * 128 * 2)

__global__ __launch_bounds__(256) void pass1_kernel()
{
    const int b  = blockIdx.y;
    const int n0 = blockIdx.x * 128;
    const unsigned* qh = g_qh + (size_t)b * NN * 32;

    extern __shared__ unsigned shm[];
    unsigned (*sA)[36] = reinterpret_cast<unsigned(*)[36]>(shm + P1_W_SA);
    float2* sMrg = reinterpret_cast<float2*>(shm + P1_W_MRG);   // [wn][row] = [4][128]
    const unsigned sbase = (unsigned)__cvta_generic_to_shared(shm);

    const int tid = threadIdx.x;
    const int lane = tid & 31, wid = tid >> 5;
    const int wm = wid >> 2, wn = wid & 3;
    const int gp = lane >> 2, tg = lane & 3;

#pragma unroll
    for (int r = 0; r < 16; r++) {
        int idx = tid + r * 256;
        int row = idx >> 5, kp = idx & 31;
        sA[row][kp] = qh[(size_t)(n0 + row) * 32 + kp];
    }

    auto issue_B = [&](int chunk) {
        int buf = chunk & 1;
        int m0 = chunk * 128;
#pragma unroll
        for (int t = 0; t < 4; t++) {
            int idx = tid + t * 256;
            int row = idx >> 3, seg = idx & 7;
            unsigned dst = sbase + (P1_W_SB + buf * 128 * 36 + row * 36 + seg * 4) * 4;
            cpa16(dst, qh + (size_t)(m0 + row) * 32 + seg * 4);
        }
        cpa_commit();
    };

    float rmax[8], rsum[8];
#pragma unroll
    for (int i = 0; i < 8; i++) { rmax[i] = -1e30f; rsum[i] = 0.f; }

    issue_B(0);
    issue_B(1);
    cpa_wait0();
    __syncthreads();

    for (int ch = 0; ch < 32; ch++) {
        unsigned (*sB)[36] = reinterpret_cast<unsigned(*)[36]>(
            shm + P1_W_SB + (ch & 1) * 128 * 36);

        float acc[4][4][4] = {};
#pragma unroll
        for (int ks = 0; ks < 4; ks++) {
            int kp0 = ks * 8;
            unsigned a[4][4], bf[4][2];
#pragma unroll
            for (int i = 0; i < 4; i++) {
                int row = wm * 64 + i * 16 + gp;
                a[i][0] = sA[row][kp0 + tg];
                a[i][1] = sA[row + 8][kp0 + tg];
                a[i][2] = sA[row][kp0 + 4 + tg];
                a[i][3] = sA[row + 8][kp0 + 4 + tg];
            }
#pragma unroll
            for (int j = 0; j < 4; j++) {
                int col = wn * 32 + j * 8 + gp;
                bf[j][0] = sB[col][kp0 + tg];
                bf[j][1] = sB[col][kp0 + 4 + tg];
            }
#pragma unroll
            for (int i = 0; i < 4; i++)
#pragma unroll
                for (int j = 0; j < 4; j++)
                    mma_fp16(acc[i][j], a[i][0], a[i][1], a[i][2], a[i][3],
                             bf[j][0], bf[j][1]);
        }

#pragma unroll
        for (int i = 0; i < 4; i++) {
            float m0v = -1e30f, m1v = -1e30f;
#pragma unroll
            for (int j = 0; j < 4; j++) {
                m0v = fmaxf(m0v, fmaxf(acc[i][j][0], acc[i][j][1]));
                m1v = fmaxf(m1v, fmaxf(acc[i][j][2], acc[i][j][3]));
            }
            m0v = fmaxf(m0v, __shfl_xor_sync(0xffffffffu, m0v, 1));
            m0v = fmaxf(m0v, __shfl_xor_sync(0xffffffffu, m0v, 2));
            m1v = fmaxf(m1v, __shfl_xor_sync(0xffffffffu, m1v, 1));
            m1v = fmaxf(m1v, __shfl_xor_sync(0xffffffffu, m1v, 2));
            float nm0 = fmaxf(rmax[2 * i],     m0v);
            float nm1 = fmaxf(rmax[2 * i + 1], m1v);
            float s0 = 0.f, s1 = 0.f;
#pragma unroll
            for (int j = 0; j < 4; j++) {
                s0 += __expf(acc[i][j][0] - nm0) + __expf(acc[i][j][1] - nm0);
                s1 += __expf(acc[i][j][2] - nm1) + __expf(acc[i][j][3] - nm1);
            }
            s0 += __shfl_xor_sync(0xffffffffu, s0, 1);
            s0 += __shfl_xor_sync(0xffffffffu, s0, 2);
            s1 += __shfl_xor_sync(0xffffffffu, s1, 1);
            s1 += __shfl_xor_sync(0xffffffffu, s1, 2);
            rsum[2 * i]     = rsum[2 * i]     * __expf(rmax[2 * i]     - nm0) + s0;
            rsum[2 * i + 1] = rsum[2 * i + 1] * __expf(rmax[2 * i + 1] - nm1) + s1;
            rmax[2 * i]     = nm0;
            rmax[2 * i + 1] = nm1;
        }

        cpa_wait0();       // loads for chunk ch+1 complete
        __syncthreads();   // all warps done reading buffer ch&1
        if (ch + 2 < 32)
            issue_B(ch + 2);
    }

    if (tg == 0) {
#pragma unroll
        for (int i = 0; i < 4; i++) {
            int row = wm * 64 + i * 16 + gp;
            sMrg[wn * 128 + row]     = make_float2(rmax[2 * i],     rsum[2 * i]);
            sMrg[wn * 128 + row + 8] = make_float2(rmax[2 * i + 1], rsum[2 * i + 1]);
        }
    }
    __syncthreads();
    if (tid < 128) {
        float2 v0 = sMrg[tid], v1 = sMrg[128 + tid];
        float2 v2 = sMrg[256 + tid], v3 = sMrg[384 + tid];
        float M = fmaxf(fmaxf(v0.x, v1.x), fmaxf(v2.x, v3.x));
        float S = v0.y * __expf(v0.x - M) + v1.y * __expf(v1.x - M)
                + v2.y * __expf(v2.x - M) + v3.y * __expf(v3.x - M);
        g_rowmax[b * NN + n0 + tid] = M;
        g_rowinv[b * NN + n0 + tid] = 1.f / S;
    }
}

// ---------------------------------------------------------------------------
// xa: fused E-recompute + P + x_a^T, single-sync pipeline, ldmatrix loads,
// register colsum. (R14 proven-best)
// ---------------------------------------------------------------------------
#define XA_W_SVH 0
#define XA_W_SQM (2 * 256 * 36)
#define XA_W_SQN (XA_W_SQM + 128 * 36)
#define XA_W_SPH (XA_W_SQN + 2 * 64 * 36)
#define XA_W_COL (XA_W_SPH + 2 * 128 * 36)
#define XA_SMEM_WORDS (XA_W_COL + 128)

__global__ __launch_bounds__(512, 1) void xa_kernel()
{
    const int b  = blockIdx.y;
    const int m0 = blockIdx.x * 128;
    const unsigned* vbh = g_vh + (size_t)b * CC * (NN / 2);
    const float* rmx = g_rowmax + b * NN;
    const float* rin = g_rowinv + b * NN;
    const unsigned* qh = g_qh + (size_t)b * NN * 32;

    extern __shared__ unsigned shm[];
    unsigned (*sQm)[36] = reinterpret_cast<unsigned(*)[36]>(shm + XA_W_SQM);
    float* sCol = reinterpret_cast<float*>(shm + XA_W_COL);
    const unsigned sbase = (unsigned)__cvta_generic_to_shared(shm);

    const int tid = threadIdx.x;
    const int lane = tid & 31, wid = tid >> 5;
    const int gp = lane >> 2, tg = lane & 3;
    const int nh = wid & 3, mh = wid >> 2;       // mma1 roles (4x4)
    const int wm = wid >> 2, wn = wid & 3;       // mma2 roles

#pragma unroll
    for (int r = 0; r < 8; r++) {
        int idx = tid + r * 512;
        int row = idx >> 5, kp = idx & 31;
        sQm[row][kp] = qh[(size_t)(m0 + row) * 32 + kp];
    }
    if (tid < 128) sCol[tid] = 0.f;

    float cs[8];
#pragma unroll
    for (int j = 0; j < 8; j++) cs[j] = 0.f;

    auto issue_V = [&](int chunk) {
        int buf = chunk & 1;
        int np0 = chunk * 32;
#pragma unroll
        for (int t = 0; t < 4; t++) {
            int idx = tid + t * 512;
            int row = idx >> 3, seg = idx & 7;
            unsigned dst = sbase + (XA_W_SVH + buf * 256 * 36 + row * 36 + seg * 4) * 4;
            cpa16(dst, vbh + (size_t)row * (NN / 2) + np0 + seg * 4);
        }
    };
    auto issue_Qn = [&](int chunk) {
        int buf = chunk & 1;
        int row = tid >> 3, seg = tid & 7;
        unsigned dst = sbase + (XA_W_SQN + buf * 64 * 36 + row * 36 + seg * 4) * 4;
        cpa16(dst, qh + (size_t)(chunk * 64 + row) * 32 + seg * 4);
    };

    auto do_mma1 = [&](int chunk) {
        int buf = chunk & 1;
        int WQn = XA_W_SQN + buf * 64 * 36;
        __half (*sPhB)[72] = reinterpret_cast<__half(*)[72]>(shm + XA_W_SPH + buf * 128 * 36);
        float e[4][4] = {};
#pragma unroll
        for (int ks = 0; ks < 4; ks++) {
            int kp0 = ks * 8;
            unsigned a0, a1, a2, a3, bf[4][2];
            ldsm4(a0, a1, a2, a3, adrA(sbase, WQn, 36, nh * 16, kp0, lane));
            ldsm4(bf[0][0], bf[0][1], bf[1][0], bf[1][1],
                  adrB(sbase, XA_W_SQM, 36, mh * 32, kp0, lane));
            ldsm4(bf[2][0], bf[2][1], bf[3][0], bf[3][1],
                  adrB(sbase, XA_W_SQM, 36, mh * 32 + 16, kp0, lane));
#pragma unroll
            for (int j = 0; j < 4; j++)
                mma_fp16(e[j], a0, a1, a2, a3, bf[j][0], bf[j][1]);
        }
        int r0 = chunk * 64 + nh * 16 + gp;
        float mx0 = __ldg(&rmx[r0]),     iv0 = __ldg(&rin[r0]);
        float mx1 = __ldg(&rmx[r0 + 8]), iv1 = __ldg(&rin[r0 + 8]);
        int nr0 = nh * 16 + gp, nr1 = nr0 + 8;
#pragma unroll
        for (int j = 0; j < 4; j++) {
            int cb = mh * 32 + j * 8 + 2 * tg;
            __half h00 = __float2half(__expf(e[j][0] - mx0) * iv0);
            __half h01 = __float2half(__expf(e[j][1] - mx0) * iv0);
            __half h10 = __float2half(__expf(e[j][2] - mx1) * iv1);
            __half h11 = __float2half(__expf(e[j][3] - mx1) * iv1);
            sPhB[cb][nr0]     = h00;
            sPhB[cb + 1][nr0] = h01;
            sPhB[cb][nr1]     = h10;
            sPhB[cb + 1][nr1] = h11;
            cs[2 * j]     += __half2float(h00) + __half2float(h10);
            cs[2 * j + 1] += __half2float(h01) + __half2float(h11);
        }
    };

    issue_V(0); issue_V(1); issue_Qn(0); issue_Qn(1); cpa_commit();
    cpa_wait0();
    __syncthreads();

    do_mma1(0);
    __syncthreads();
    issue_Qn(2); cpa_commit();

    float acc[2][8][4] = {};

    for (int i = 0; i < 64; i++) {
        const int buf = i & 1;
        int WV = XA_W_SVH + buf * 256 * 36;
        int WP = XA_W_SPH + buf * 128 * 36;

        if (i < 63)
            do_mma1(i + 1);

#pragma unroll
        for (int ks = 0; ks < 4; ks++) {
            int kp0 = ks * 8;
            unsigned pa[2][4], bf[8][2];
#pragma unroll
            for (int ii = 0; ii < 2; ii++)
                ldsm4(pa[ii][0], pa[ii][1], pa[ii][2], pa[ii][3],
                      adrA(sbase, WP, 36, wm * 32 + ii * 16, kp0, lane));
#pragma unroll
            for (int g = 0; g < 4; g++)
                ldsm4(bf[2 * g][0], bf[2 * g][1], bf[2 * g + 1][0], bf[2 * g + 1][1],
                      adrB(sbase, WV, 36, wn * 64 + g * 16, kp0, lane));
#pragma unroll
            for (int ii = 0; ii < 2; ii++)
#pragma unroll
                for (int j = 0; j < 8; j++)
                    mma_fp16(acc[ii][j], pa[ii][0], pa[ii][1], pa[ii][2], pa[ii][3],
                             bf[j][0], bf[j][1]);
        }

        cpa_wait0();
        __syncthreads();
        if (i + 2 < 64) issue_V(i + 2);
        if (i + 3 < 64) issue_Qn(i + 3);
        cpa_commit();
    }

#pragma unroll
    for (int j = 0; j < 8; j++) {
        float v = cs[j];
        v += __shfl_xor_sync(0xffffffffu, v, 4);
        v += __shfl_xor_sync(0xffffffffu, v, 8);
        v += __shfl_xor_sync(0xffffffffu, v, 16);
        cs[j] = v;
    }
    if (gp == 0) {
#pragma unroll
        for (int j = 0; j < 4; j++) {
            int cb = mh * 32 + j * 8 + 2 * tg;
            atomicAdd(&sCol[cb], cs[2 * j]);
            atomicAdd(&sCol[cb + 1], cs[2 * j + 1]);
        }
    }
    __syncthreads();

#pragma unroll
    for (int ii = 0; ii < 2; ii++) {
        int mr = wm * 32 + ii * 16 + gp;
        float i0 = 1.f / (1e-9f + sCol[mr]);
        float i1 = 1.f / (1e-9f + sCol[mr + 8]);
        size_t r0 = ((size_t)b * NN + m0 + mr) * 128;
        size_t r1 = r0 + 8 * 128;
#pragma unroll
        for (int j = 0; j < 8; j++) {
            int cp = wn * 32 + j * 4 + tg;
            g_xaTh[r0 + cp] = pack_h2(acc[ii][j][0] * i0, acc[ii][j][1] * i0);
            g_xaTh[r1 + cp] = pack_h2(acc[ii][j][2] * i1, acc[ii][j][3] * i1);
        }
    }
}

// ---------------------------------------------------------------------------
// Final: out = x + relu(gamma * (t - mean) * rstd + beta)
// ---------------------------------------------------------------------------
__global__ __launch_bounds__(256) void final_kernel(
    const float* __restrict__ x, const float* __restrict__ gamma,
    const float* __restrict__ beta, float* __restrict__ out)
{
    size_t i = (size_t)blockIdx.x * 256 + threadIdx.x;
    int c = (int)((i >> 12) & 255);
    float t = g_t[i];
    float th = (t - g_mean[c]) * g_rstd[c];
    float r = fmaxf(0.f, gamma[c] * th + beta[c]);
    out[i] = x[i] + r;
}

// ---------------------------------------------------------------------------
extern "C" void kernel_launch(void* const* d_in, const int* in_sizes, int n_in,
                              void* d_out, int out_size)
{
    const float* x     = (const float*)d_in[0];
    const float* wq    = (const float*)d_in[1];
    const float* wv    = (const float*)d_in[2];
    const float* bv    = (const float*)d_in[3];
    const float* wt    = (const float*)d_in[4];
    const float* bt    = (const float*)d_in[5];
    const float* gamma = (const float*)d_in[6];
    const float* beta  = (const float*)d_in[7];
    float* out = (float*)d_out;

    const int xa_smem = XA_SMEM_WORDS * 4;
    const int ct_smem = CT_SMEM_WORDS * 4;
    const int p1_smem = P1_SMEM_WORDS * 4;
    cudaFuncSetAttribute(xa_kernel,
                         cudaFuncAttributeMaxDynamicSharedMemorySize, xa_smem);
    cudaFuncSetAttribute(convt_tc_kernel,
                         cudaFuncAttributeMaxDynamicSharedMemorySize, ct_smem);
    cudaFuncSetAttribute(pass1_kernel,
                         cudaFuncAttributeMaxDynamicSharedMemorySize, p1_smem);

    // x^T fp16 + weight fp16 conversions (also zeroes BN accumulators)
    xt_kernel<<<dim3(NN / 64, CC / 64, BB), 256>>>(x);
    wcvt_kernel<<<(8192 + 65536 + 255) / 256, 256>>>(wq, wv, wt);
    // q^T = x^T wq^T  (weight-tied Q/K), fp16 mma
    convq_tc_kernel<<<dim3(NN / 128, 1, BB), 256>>>();
    // v = wv x + bv, fp16 mma (256 threads, proven config)
    convv_tc_kernel<<<dim3(NN / 128, CC / 128, BB), 256>>>(bv);
    // fused energy + row softmax stats (cp.async pipeline)
    pass1_kernel<<<dim3(NN / 128, BB), 256, p1_smem>>>();
    // fused E-recompute + softmax + double-norm + x_a^T (register colsum)
    xa_kernel<<<dim3(NN / 128, BB), 512, xa_smem>>>();
    // t = wt (x - x_a) + bt, fp16 mma, fused BN partial sums (one wave)
    convt_tc_kernel<<<dim3(NN / 128, BB), 512, ct_smem>>>(bt);
    // BN finalize + fused relu/residual
    bnfin_kernel<<<1, CC>>>();
    final_kernel<<<(BB * CC * NN) / 256, 256>>>(x, gamma, beta, out);
}

// round 17
// speedup vs baseline: 1.1324x; 1.0097x over previous
#include <cuda_runtime.h>
#include <cuda_fp16.h>
#include <cstdint>

#define BB 4
#define CC 256
#define NN 4096
#define DD 64

// Scratch (device globals: allocation-free kernel_launch)
__device__ unsigned g_qh[(size_t)BB * NN * 32];         // 2 MB  q fp16 pairs [b][n][d/2]
__device__ unsigned g_vh[(size_t)BB * CC * (NN / 2)];   // 8 MB  v fp16 pairs [b][c][n/2]
__device__ unsigned g_xth[(size_t)BB * NN * (CC / 2)];  // 8 MB  x^T fp16 pairs [b][n][c/2]
__device__ unsigned g_xaTh[(size_t)BB * NN * (CC / 2)]; // 8 MB  x_a^T fp16 pairs [b][n][c/2]
__device__ unsigned g_wqh[DD * (CC / 2)];               // wq fp16 pairs [o][c/2]
__device__ unsigned g_wvh[CC * (CC / 2)];
__device__ unsigned g_wth[CC * (CC / 2)];
__device__ float g_rowmax[BB * NN];
__device__ float g_rowinv[BB * NN];
__device__ float g_t[(size_t)BB * CC * NN];             // 16 MB
__device__ float g_bnsum[CC];
__device__ float g_bnsum2[CC];

// ---------------------------------------------------------------------------
// helpers
// ---------------------------------------------------------------------------
__device__ __forceinline__ void mma_fp16(
    float* c,
    unsigned a0, unsigned a1, unsigned a2, unsigned a3,
    unsigned b0, unsigned b1)
{
    asm volatile(
        "mma.sync.aligned.m16n8k16.row.col.f32.f16.f16.f32 "
        "{%0,%1,%2,%3}, {%4,%5,%6,%7}, {%8,%9}, {%0,%1,%2,%3};\n"
        : "+f"(c[0]), "+f"(c[1]), "+f"(c[2]), "+f"(c[3])
        : "r"(a0), "r"(a1), "r"(a2), "r"(a3), "r"(b0), "r"(b1));
}

__device__ __forceinline__ void ldsm4(
    unsigned& r0, unsigned& r1, unsigned& r2, unsigned& r3, unsigned addr)
{
    asm volatile(
        "ldmatrix.sync.aligned.m8n8.x4.shared.b16 {%0,%1,%2,%3}, [%4];\n"
        : "=r"(r0), "=r"(r1), "=r"(r2), "=r"(r3) : "r"(addr));
}

// A-layout x4 address
__device__ __forceinline__ unsigned adrA(unsigned sb, int Wwords, int stride,
                                         int row0, int kp0, int lane)
{
    int row = row0 + ((lane >> 3) & 1) * 8 + (lane & 7);
    int col = kp0 + ((lane >> 4) & 1) * 4;
    return sb + (unsigned)(Wwords + row * stride + col) * 4u;
}

// B-layout x4 address
__device__ __forceinline__ unsigned adrB(unsigned sb, int Wwords, int stride,
                                         int col0, int kp0, int lane)
{
    int row = col0 + ((lane >> 4) & 1) * 8 + (lane & 7);
    int col = kp0 + ((lane >> 3) & 1) * 4;
    return sb + (unsigned)(Wwords + row * stride + col) * 4u;
}

__device__ __forceinline__ void cpa16(unsigned sdst, const void* gsrc)
{
    asm volatile("cp.async.cg.shared.global [%0], [%1], 16;\n"
                 :: "r"(sdst), "l"(gsrc));
}
__device__ __forceinline__ void cpa_commit()
{
    asm volatile("cp.async.commit_group;\n");
}
__device__ __forceinline__ void cpa_wait0()
{
    asm volatile("cp.async.wait_group 0;\n");
}

__device__ __forceinline__ unsigned pack_h2(float a, float b)
{
    __half2 h = __floats2half2_rn(a, b);
    return *reinterpret_cast<unsigned*>(&h);
}

// ---------------------------------------------------------------------------
// xt: transpose + convert x[b][c][n] fp32 -> g_xth[(b*N+n)*128 + c/2] fp16 pairs
// ---------------------------------------------------------------------------
__global__ __launch_bounds__(256) void xt_kernel(const float* __restrict__ x)
{
    const int b  = blockIdx.z;
    const int c0 = blockIdx.y * 64;
    const int n0 = blockIdx.x * 64;
    const float* xb = x + ((size_t)b * CC + c0) * NN + n0;

    __shared__ float sT[64][65];
    const int tid = threadIdx.x;

#pragma unroll
    for (int r = 0; r < 16; r++) {
        int idx = tid + r * 256;
        int c = idx >> 6, n = idx & 63;
        sT[c][n] = xb[(size_t)c * NN + n];
    }
    __syncthreads();
#pragma unroll
    for (int r = 0; r < 8; r++) {
        int idx = tid + r * 256;
        int n = idx >> 5, cp = idx & 31;
        g_xth[((size_t)b * NN + n0 + n) * 128 + c0 / 2 + cp] =
            pack_h2(sT[2 * cp][n], sT[2 * cp + 1][n]);
    }
}

// ---------------------------------------------------------------------------
// wcvt: convert wq/wv/wt to fp16 pairs; also zero BN accumulators
// ---------------------------------------------------------------------------
__global__ __launch_bounds__(256) void wcvt_kernel(
    const float* __restrict__ wq, const float* __restrict__ wv,
    const float* __restrict__ wt)
{
    int idx = blockIdx.x * 256 + threadIdx.x;
    if (idx < 256) { g_bnsum[idx] = 0.f; g_bnsum2[idx] = 0.f; }
    if (idx < 8192) {
        float2 f = *reinterpret_cast<const float2*>(&wq[idx * 2]);
        g_wqh[idx] = pack_h2(f.x, f.y);
    } else if (idx < 8192 + 32768) {
        int i = idx - 8192;
        float2 f = *reinterpret_cast<const float2*>(&wv[i * 2]);
        g_wvh[i] = pack_h2(f.x, f.y);
    } else if (idx < 8192 + 65536) {
        int i = idx - 8192 - 32768;
        float2 f = *reinterpret_cast<const float2*>(&wt[i * 2]);
        g_wth[i] = pack_h2(f.x, f.y);
    }
}

// ---------------------------------------------------------------------------
// convq_tc: q^T[n][o] = x^T[n][:] . wq[o][:]  -> g_qh[(b*N+n)*32 + o/2]
// ---------------------------------------------------------------------------
__global__ __launch_bounds__(256) void convq_tc_kernel()
{
    const int b  = blockIdx.z;
    const int n0 = blockIdx.x * 128;
    const unsigned* xth = g_xth + (size_t)b * NN * 128;

    __shared__ unsigned sA[128][36];
    __shared__ unsigned sB[64][36];

    const int tid = threadIdx.x;
    const int lane = tid & 31, wid = tid >> 5;
    const int wm = wid >> 2, wn = wid & 3;
    const int gp = lane >> 2, tg = lane & 3;

    float acc[4][2][4] = {};

    for (int ks = 0; ks < 4; ks++) {
        int kp0g = ks * 32;
        __syncthreads();
#pragma unroll
        for (int r = 0; r < 16; r++) {
            int idx = tid + r * 256;
            int row = idx >> 5, kp = idx & 31;
            sA[row][kp] = xth[(size_t)(n0 + row) * 128 + kp0g + kp];
        }
#pragma unroll
        for (int r = 0; r < 8; r++) {
            int idx = tid + r * 256;
            int row = idx >> 5, kp = idx & 31;
            sB[row][kp] = g_wqh[(size_t)row * 128 + kp0g + kp];
        }
        __syncthreads();
#pragma unroll
        for (int kk = 0; kk < 4; kk++) {
            int kp0 = kk * 8;
            unsigned a[4][4], bf[2][2];
#pragma unroll
            for (int i = 0; i < 4; i++) {
                int row = wm * 64 + i * 16 + gp;
                a[i][0] = sA[row][kp0 + tg];
                a[i][1] = sA[row + 8][kp0 + tg];
                a[i][2] = sA[row][kp0 + 4 + tg];
                a[i][3] = sA[row + 8][kp0 + 4 + tg];
            }
#pragma unroll
            for (int j = 0; j < 2; j++) {
                int col = wn * 16 + j * 8 + gp;
                bf[j][0] = sB[col][kp0 + tg];
                bf[j][1] = sB[col][kp0 + 4 + tg];
            }
#pragma unroll
            for (int i = 0; i < 4; i++)
#pragma unroll
                for (int j = 0; j < 2; j++)
                    mma_fp16(acc[i][j], a[i][0], a[i][1], a[i][2], a[i][3],
                             bf[j][0], bf[j][1]);
        }
    }

#pragma unroll
    for (int i = 0; i < 4; i++) {
        int n = n0 + wm * 64 + i * 16 + gp;
#pragma unroll
        for (int j = 0; j < 2; j++) {
            int op = wn * 8 + j * 4 + tg;
            g_qh[((size_t)b * NN + n) * 32 + op]     = pack_h2(acc[i][j][0], acc[i][j][1]);
            g_qh[((size_t)b * NN + n + 8) * 32 + op] = pack_h2(acc[i][j][2], acc[i][j][3]);
        }
    }
}

// ---------------------------------------------------------------------------
// convv_tc: v[o][n] = wv[o][:] . x^T[n][:] + bv  (scalar LDS, 256 threads)
// ---------------------------------------------------------------------------
__global__ __launch_bounds__(256) void convv_tc_kernel(const float* __restrict__ bias)
{
    const int b  = blockIdx.z;
    const int o0 = blockIdx.y * 128;
    const int n0 = blockIdx.x * 128;
    const unsigned* xth = g_xth + (size_t)b * NN * 128;

    __shared__ unsigned sA[128][36];
    __shared__ unsigned sB[128][36];

    const int tid = threadIdx.x;
    const int lane = tid & 31, wid = tid >> 5;
    const int wm = wid >> 2, wn = wid & 3;
    const int gp = lane >> 2, tg = lane & 3;

    float acc[4][4][4] = {};

    for (int ks = 0; ks < 4; ks++) {
        int kp0g = ks * 32;
        __syncthreads();
#pragma unroll
        for (int r = 0; r < 16; r++) {
            int idx = tid + r * 256;
            int row = idx >> 5, kp = idx & 31;
            sA[row][kp] = g_wvh[(size_t)(o0 + row) * 128 + kp0g + kp];
            sB[row][kp] = xth[(size_t)(n0 + row) * 128 + kp0g + kp];
        }
        __syncthreads();
#pragma unroll
        for (int kk = 0; kk < 4; kk++) {
            int kp0 = kk * 8;
            unsigned a[4][4], bf[4][2];
#pragma unroll
            for (int i = 0; i < 4; i++) {
                int row = wm * 64 + i * 16 + gp;
                a[i][0] = sA[row][kp0 + tg];
                a[i][1] = sA[row + 8][kp0 + tg];
                a[i][2] = sA[row][kp0 + 4 + tg];
                a[i][3] = sA[row + 8][kp0 + 4 + tg];
            }
#pragma unroll
            for (int j = 0; j < 4; j++) {
                int col = wn * 32 + j * 8 + gp;
                bf[j][0] = sB[col][kp0 + tg];
                bf[j][1] = sB[col][kp0 + 4 + tg];
            }
#pragma unroll
            for (int i = 0; i < 4; i++)
#pragma unroll
                for (int j = 0; j < 4; j++)
                    mma_fp16(acc[i][j], a[i][0], a[i][1], a[i][2], a[i][3],
                             bf[j][0], bf[j][1]);
        }
    }

#pragma unroll
    for (int i = 0; i < 4; i++) {
        int o = o0 + wm * 64 + i * 16 + gp;
        float b0 = bias[o], b1 = bias[o + 8];
#pragma unroll
        for (int j = 0; j < 4; j++) {
            int np = (n0 + wn * 32 + j * 8 + 2 * tg) / 2;
            g_vh[((size_t)b * CC + o) * (NN / 2) + np] =
                pack_h2(acc[i][j][0] + b0, acc[i][j][1] + b0);
            g_vh[((size_t)b * CC + o + 8) * (NN / 2) + np] =
                pack_h2(acc[i][j][2] + b1, acc[i][j][3] + b1);
        }
    }
}

// ---------------------------------------------------------------------------
// convt_tc: t[o][n] = wt[o][:] . (x^T - x_a^T)[n][:] + bt  -> g_t fp32.
// 512 threads, all 256 channels, one wave. Fused BN partial sums.
// ---------------------------------------------------------------------------
#define CT_W_SA 0
#define CT_W_SB (256 * 36)
#define CT_W_SS (CT_W_SB + 128 * 36)
#define CT_SMEM_WORDS (CT_W_SS + 512)

__global__ __launch_bounds__(512, 1) void convt_tc_kernel(const float* __restrict__ bias)
{
    const int b  = blockIdx.y;
    const int n0 = blockIdx.x * 128;
    const unsigned* xth  = g_xth  + (size_t)b * NN * 128;
    const unsigned* xath = g_xaTh + (size_t)b * NN * 128;

    extern __shared__ unsigned shm[];
    unsigned (*sA)[36] = reinterpret_cast<unsigned(*)[36]>(shm + CT_W_SA);  // wt [256][36]
    unsigned (*sB)[36] = reinterpret_cast<unsigned(*)[36]>(shm + CT_W_SB);  // xd [128][36]
    float* sS  = reinterpret_cast<float*>(shm + CT_W_SS);
    float* sS2 = sS + 256;

    const int tid = threadIdx.x;
    const int lane = tid & 31, wid = tid >> 5;
    const int wm = wid >> 2, wn = wid & 3;
    const int gp = lane >> 2, tg = lane & 3;

    if (tid < 256) { sS[tid] = 0.f; sS2[tid] = 0.f; }

    float acc[4][4][4] = {};

    for (int ks = 0; ks < 4; ks++) {
        int kp0g = ks * 32;
        __syncthreads();
#pragma unroll
        for (int r = 0; r < 16; r++) {
            int idx = tid + r * 512;
            int row = idx >> 5, kp = idx & 31;
            sA[row][kp] = g_wth[(size_t)row * 128 + kp0g + kp];
        }
#pragma unroll
        for (int r = 0; r < 8; r++) {
            int idx = tid + r * 512;
            int row = idx >> 5, kp = idx & 31;
            size_t gi = (size_t)(n0 + row) * 128 + kp0g + kp;
            __half2 xv = *reinterpret_cast<const __half2*>(&xth[gi]);
            __half2 av = *reinterpret_cast<const __half2*>(&xath[gi]);
            __half2 d = __hsub2(xv, av);
            sB[row][kp] = *reinterpret_cast<unsigned*>(&d);
        }
        __syncthreads();
#pragma unroll
        for (int kk = 0; kk < 4; kk++) {
            int kp0 = kk * 8;
            unsigned a[4][4], bf[4][2];
#pragma unroll
            for (int i = 0; i < 4; i++) {
                int row = wm * 64 + i * 16 + gp;
                a[i][0] = sA[row][kp0 + tg];
                a[i][1] = sA[row + 8][kp0 + tg];
                a[i][2] = sA[row][kp0 + 4 + tg];
                a[i][3] = sA[row + 8][kp0 + 4 + tg];
            }
#pragma unroll
            for (int j = 0; j < 4; j++) {
                int col = wn * 32 + j * 8 + gp;
                bf[j][0] = sB[col][kp0 + tg];
                bf[j][1] = sB[col][kp0 + 4 + tg];
            }
#pragma unroll
            for (int i = 0; i < 4; i++)
#pragma unroll
                for (int j = 0; j < 4; j++)
                    mma_fp16(acc[i][j], a[i][0], a[i][1], a[i][2], a[i][3],
                             bf[j][0], bf[j][1]);
        }
    }

#pragma unroll
    for (int i = 0; i < 4; i++) {
        int o = wm * 64 + i * 16 + gp;
        float b0 = bias[o], b1 = bias[o + 8];
        float sa = 0.f, sa2 = 0.f, sb = 0.f, sb2 = 0.f;
#pragma unroll
        for (int j = 0; j < 4; j++) {
            int n = n0 + wn * 32 + j * 8 + 2 * tg;
            float t00 = acc[i][j][0] + b0, t01 = acc[i][j][1] + b0;
            float t10 = acc[i][j][2] + b1, t11 = acc[i][j][3] + b1;
            sa += t00 + t01;  sa2 += t00 * t00 + t01 * t01;
            sb += t10 + t11;  sb2 += t10 * t10 + t11 * t11;
            *reinterpret_cast<float2*>(&g_t[((size_t)b * CC + o) * NN + n]) =
                make_float2(t00, t01);
            *reinterpret_cast<float2*>(&g_t[((size_t)b * CC + o + 8) * NN + n]) =
                make_float2(t10, t11);
        }
#pragma unroll
        for (int off = 1; off <= 2; off <<= 1) {
            sa  += __shfl_xor_sync(0xffffffffu, sa,  off);
            sa2 += __shfl_xor_sync(0xffffffffu, sa2, off);
            sb  += __shfl_xor_sync(0xffffffffu, sb,  off);
            sb2 += __shfl_xor_sync(0xffffffffu, sb2, off);
        }
        if (tg == 0) {
            atomicAdd(&sS[o], sa);      atomicAdd(&sS2[o], sa2);
            atomicAdd(&sS[o + 8], sb);  atomicAdd(&sS2[o + 8], sb2);
        }
    }
    __syncthreads();
    if (tid < 256) {
        atomicAdd(&g_bnsum[tid], sS[tid]);
        atomicAdd(&g_bnsum2[tid], sS2[tid]);
    }
}

// ---------------------------------------------------------------------------
// pass1: fused energy + row softmax stats, cp.async double-buffered B tile.
// ---------------------------------------------------------------------------
#define P1_W_SA 0
#define P1_W_SB (128 * 36)
#define P1_W_MRG (P1_W_SB + 2 * 128 * 36)
#define P1_SMEM_WORDS (P1_W_MRG + 4 * 128 * 2)

__global__ __launch_bounds__(256) void pass1_kernel()
{
    const int b  = blockIdx.y;
    const int n0 = blockIdx.x * 128;
    const unsigned* qh = g_qh + (size_t)b * NN * 32;

    extern __shared__ unsigned shm[];
    unsigned (*sA)[36] = reinterpret_cast<unsigned(*)[36]>(shm + P1_W_SA);
    float2* sMrg = reinterpret_cast<float2*>(shm + P1_W_MRG);
    const unsigned sbase = (unsigned)__cvta_generic_to_shared(shm);

    const int tid = threadIdx.x;
    const int lane = tid & 31, wid = tid >> 5;
    const int wm = wid >> 2, wn = wid & 3;
    const int gp = lane >> 2, tg = lane & 3;

#pragma unroll
    for (int r = 0; r < 16; r++) {
        int idx = tid + r * 256;
        int row = idx >> 5, kp = idx & 31;
        sA[row][kp] = qh[(size_t)(n0 + row) * 32 + kp];
    }

    auto issue_B = [&](int chunk) {
        int buf = chunk & 1;
        int m0 = chunk * 128;
#pragma unroll
        for (int t = 0; t < 4; t++) {
            int idx = tid + t * 256;
            int row = idx >> 3, seg = idx & 7;
            unsigned dst = sbase + (P1_W_SB + buf * 128 * 36 + row * 36 + seg * 4) * 4;
            cpa16(dst, qh + (size_t)(m0 + row) * 32 + seg * 4);
        }
        cpa_commit();
    };

    float rmax[8], rsum[8];
#pragma unroll
    for (int i = 0; i < 8; i++) { rmax[i] = -1e30f; rsum[i] = 0.f; }

    issue_B(0);
    issue_B(1);
    cpa_wait0();
    __syncthreads();

    for (int ch = 0; ch < 32; ch++) {
        unsigned (*sB)[36] = reinterpret_cast<unsigned(*)[36]>(
            shm + P1_W_SB + (ch & 1) * 128 * 36);

        float acc[4][4][4] = {};
#pragma unroll
        for (int ks = 0; ks < 4; ks++) {
            int kp0 = ks * 8;
            unsigned a[4][4], bf[4][2];
#pragma unroll
            for (int i = 0; i < 4; i++) {
                int row = wm * 64 + i * 16 + gp;
                a[i][0] = sA[row][kp0 + tg];
                a[i][1] = sA[row + 8][kp0 + tg];
                a[i][2] = sA[row][kp0 + 4 + tg];
                a[i][3] = sA[row + 8][kp0 + 4 + tg];
            }
#pragma unroll
            for (int j = 0; j < 4; j++) {
                int col = wn * 32 + j * 8 + gp;
                bf[j][0] = sB[col][kp0 + tg];
                bf[j][1] = sB[col][kp0 + 4 + tg];
            }
#pragma unroll
            for (int i = 0; i < 4; i++)
#pragma unroll
                for (int j = 0; j < 4; j++)
                    mma_fp16(acc[i][j], a[i][0], a[i][1], a[i][2], a[i][3],
                             bf[j][0], bf[j][1]);
        }

#pragma unroll
        for (int i = 0; i < 4; i++) {
            float m0v = -1e30f, m1v = -1e30f;
#pragma unroll
            for (int j = 0; j < 4; j++) {
                m0v = fmaxf(m0v, fmaxf(acc[i][j][0], acc[i][j][1]));
                m1v = fmaxf(m1v, fmaxf(acc[i][j][2], acc[i][j][3]));
            }
            m0v = fmaxf(m0v, __shfl_xor_sync(0xffffffffu, m0v, 1));
            m0v = fmaxf(m0v, __shfl_xor_sync(0xffffffffu, m0v, 2));
            m1v = fmaxf(m1v, __shfl_xor_sync(0xffffffffu, m1v, 1));
            m1v = fmaxf(m1v, __shfl_xor_sync(0xffffffffu, m1v, 2));
            float nm0 = fmaxf(rmax[2 * i],     m0v);
            float nm1 = fmaxf(rmax[2 * i + 1], m1v);
            float s0 = 0.f, s1 = 0.f;
#pragma unroll
            for (int j = 0; j < 4; j++) {
                s0 += __expf(acc[i][j][0] - nm0) + __expf(acc[i][j][1] - nm0);
                s1 += __expf(acc[i][j][2] - nm1) + __expf(acc[i][j][3] - nm1);
            }
            s0 += __shfl_xor_sync(0xffffffffu, s0, 1);
            s0 += __shfl_xor_sync(0xffffffffu, s0, 2);
            s1 += __shfl_xor_sync(0xffffffffu, s1, 1);
            s1 += __shfl_xor_sync(0xffffffffu, s1, 2);
            rsum[2 * i]     = rsum[2 * i]     * __expf(rmax[2 * i]     - nm0) + s0;
            rsum[2 * i + 1] = rsum[2 * i + 1] * __expf(rmax[2 * i + 1] - nm1) + s1;
            rmax[2 * i]     = nm0;
            rmax[2 * i + 1] = nm1;
        }

        cpa_wait0();
        __syncthreads();
        if (ch + 2 < 32)
            issue_B(ch + 2);
    }

    if (tg == 0) {
#pragma unroll
        for (int i = 0; i < 4; i++) {
            int row = wm * 64 + i * 16 + gp;
            sMrg[wn * 128 + row]     = make_float2(rmax[2 * i],     rsum[2 * i]);
            sMrg[wn * 128 + row + 8] = make_float2(rmax[2 * i + 1], rsum[2 * i + 1]);
        }
    }
    __syncthreads();
    if (tid < 128) {
        float2 v0 = sMrg[tid], v1 = sMrg[128 + tid];
        float2 v2 = sMrg[256 + tid], v3 = sMrg[384 + tid];
        float M = fmaxf(fmaxf(v0.x, v1.x), fmaxf(v2.x, v3.x));
        float S = v0.y * __expf(v0.x - M) + v1.y * __expf(v1.x - M)
                + v2.y * __expf(v2.x - M) + v3.y * __expf(v3.x - M);
        g_rowmax[b * NN + n0 + tid] = M;
        g_rowinv[b * NN + n0 + tid] = 1.f / S;
    }
}

// ---------------------------------------------------------------------------
// xa: fused E-recompute + P + x_a^T, single-sync pipeline, ldmatrix loads,
// register colsum. (proven-best)
// ---------------------------------------------------------------------------
#define XA_W_SVH 0
#define XA_W_SQM (2 * 256 * 36)
#define XA_W_SQN (XA_W_SQM + 128 * 36)
#define XA_W_SPH (XA_W_SQN + 2 * 64 * 36)
#define XA_W_COL (XA_W_SPH + 2 * 128 * 36)
#define XA_SMEM_WORDS (XA_W_COL + 128)

__global__ __launch_bounds__(512, 1) void xa_kernel()
{
    const int b  = blockIdx.y;
    const int m0 = blockIdx.x * 128;
    const unsigned* vbh = g_vh + (size_t)b * CC * (NN / 2);
    const float* rmx = g_rowmax + b * NN;
    const float* rin = g_rowinv + b * NN;
    const unsigned* qh = g_qh + (size_t)b * NN * 32;

    extern __shared__ unsigned shm[];
    unsigned (*sQm)[36] = reinterpret_cast<unsigned(*)[36]>(shm + XA_W_SQM);
    float* sCol = reinterpret_cast<float*>(shm + XA_W_COL);
    const unsigned sbase = (unsigned)__cvta_generic_to_shared(shm);

    const int tid = threadIdx.x;
    const int lane = tid & 31, wid = tid >> 5;
    const int gp = lane >> 2, tg = lane & 3;
    const int nh = wid & 3, mh = wid >> 2;       // mma1 roles (4x4)
    const int wm = wid >> 2, wn = wid & 3;       // mma2 roles

#pragma unroll
    for (int r = 0; r < 8; r++) {
        int idx = tid + r * 512;
        int row = idx >> 5, kp = idx & 31;
        sQm[row][kp] = qh[(size_t)(m0 + row) * 32 + kp];
    }
    if (tid < 128) sCol[tid] = 0.f;

    float cs[8];
#pragma unroll
    for (int j = 0; j < 8; j++) cs[j] = 0.f;

    auto issue_V = [&](int chunk) {
        int buf = chunk & 1;
        int np0 = chunk * 32;
#pragma unroll
        for (int t = 0; t < 4; t++) {
            int idx = tid + t * 512;
            int row = idx >> 3, seg = idx & 7;
            unsigned dst = sbase + (XA_W_SVH + buf * 256 * 36 + row * 36 + seg * 4) * 4;
            cpa16(dst, vbh + (size_t)row * (NN / 2) + np0 + seg * 4);
        }
    };
    auto issue_Qn = [&](int chunk) {
        int buf = chunk & 1;
        int row = tid >> 3, seg = tid & 7;
        unsigned dst = sbase + (XA_W_SQN + buf * 64 * 36 + row * 36 + seg * 4) * 4;
        cpa16(dst, qh + (size_t)(chunk * 64 + row) * 32 + seg * 4);
    };

    auto do_mma1 = [&](int chunk) {
        int buf = chunk & 1;
        int WQn = XA_W_SQN + buf * 64 * 36;
        __half (*sPhB)[72] = reinterpret_cast<__half(*)[72]>(shm + XA_W_SPH + buf * 128 * 36);
        float e[4][4] = {};
#pragma unroll
        for (int ks = 0; ks < 4; ks++) {
            int kp0 = ks * 8;
            unsigned a0, a1, a2, a3, bf[4][2];
            ldsm4(a0, a1, a2, a3, adrA(sbase, WQn, 36, nh * 16, kp0, lane));
            ldsm4(bf[0][0], bf[0][1], bf[1][0], bf[1][1],
                  adrB(sbase, XA_W_SQM, 36, mh * 32, kp0, lane));
            ldsm4(bf[2][0], bf[2][1], bf[3][0], bf[3][1],
                  adrB(sbase, XA_W_SQM, 36, mh * 32 + 16, kp0, lane));
#pragma unroll
            for (int j = 0; j < 4; j++)
                mma_fp16(e[j], a0, a1, a2, a3, bf[j][0], bf[j][1]);
        }
        int r0 = chunk * 64 + nh * 16 + gp;
        float mx0 = __ldg(&rmx[r0]),     iv0 = __ldg(&rin[r0]);
        float mx1 = __ldg(&rmx[r0 + 8]), iv1 = __ldg(&rin[r0 + 8]);
        int nr0 = nh * 16 + gp, nr1 = nr0 + 8;
#pragma unroll
        for (int j = 0; j < 4; j++) {
            int cb = mh * 32 + j * 8 + 2 * tg;
            __half h00 = __float2half(__expf(e[j][0] - mx0) * iv0);
            __half h01 = __float2half(__expf(e[j][1] - mx0) * iv0);
            __half h10 = __float2half(__expf(e[j][2] - mx1) * iv1);
            __half h11 = __float2half(__expf(e[j][3] - mx1) * iv1);
            sPhB[cb][nr0]     = h00;
            sPhB[cb + 1][nr0] = h01;
            sPhB[cb][nr1]     = h10;
            sPhB[cb + 1][nr1] = h11;
            cs[2 * j]     += __half2float(h00) + __half2float(h10);
            cs[2 * j + 1] += __half2float(h01) + __half2float(h11);
        }
    };

    issue_V(0); issue_V(1); issue_Qn(0); issue_Qn(1); cpa_commit();
    cpa_wait0();
    __syncthreads();

    do_mma1(0);
    __syncthreads();
    issue_Qn(2); cpa_commit();

    float acc[2][8][4] = {};

    for (int i = 0; i < 64; i++) {
        const int buf = i & 1;
        int WV = XA_W_SVH + buf * 256 * 36;
        int WP = XA_W_SPH + buf * 128 * 36;

        if (i < 63)
            do_mma1(i + 1);

#pragma unroll
        for (int ks = 0; ks < 4; ks++) {
            int kp0 = ks * 8;
            unsigned pa[2][4], bf[8][2];
#pragma unroll
            for (int ii = 0; ii < 2; ii++)
                ldsm4(pa[ii][0], pa[ii][1], pa[ii][2], pa[ii][3],
                      adrA(sbase, WP, 36, wm * 32 + ii * 16, kp0, lane));
#pragma unroll
            for (int g = 0; g < 4; g++)
                ldsm4(bf[2 * g][0], bf[2 * g][1], bf[2 * g + 1][0], bf[2 * g + 1][1],
                      adrB(sbase, WV, 36, wn * 64 + g * 16, kp0, lane));
#pragma unroll
            for (int ii = 0; ii < 2; ii++)
#pragma unroll
                for (int j = 0; j < 8; j++)
                    mma_fp16(acc[ii][j], pa[ii][0], pa[ii][1], pa[ii][2], pa[ii][3],
                             bf[j][0], bf[j][1]);
        }

        cpa_wait0();
        __syncthreads();
        if (i + 2 < 64) issue_V(i + 2);
        if (i + 3 < 64) issue_Qn(i + 3);
        cpa_commit();
    }

#pragma unroll
    for (int j = 0; j < 8; j++) {
        float v = cs[j];
        v += __shfl_xor_sync(0xffffffffu, v, 4);
        v += __shfl_xor_sync(0xffffffffu, v, 8);
        v += __shfl_xor_sync(0xffffffffu, v, 16);
        cs[j] = v;
    }
    if (gp == 0) {
#pragma unroll
        for (int j = 0; j < 4; j++) {
            int cb = mh * 32 + j * 8 + 2 * tg;
            atomicAdd(&sCol[cb], cs[2 * j]);
            atomicAdd(&sCol[cb + 1], cs[2 * j + 1]);
        }
    }
    __syncthreads();

#pragma unroll
    for (int ii = 0; ii < 2; ii++) {
        int mr = wm * 32 + ii * 16 + gp;
        float i0 = 1.f / (1e-9f + sCol[mr]);
        float i1 = 1.f / (1e-9f + sCol[mr + 8]);
        size_t r0 = ((size_t)b * NN + m0 + mr) * 128;
        size_t r1 = r0 + 8 * 128;
#pragma unroll
        for (int j = 0; j < 8; j++) {
            int cp = wn * 32 + j * 4 + tg;
            g_xaTh[r0 + cp] = pack_h2(acc[ii][j][0] * i0, acc[ii][j][1] * i0);
            g_xaTh[r1 + cp] = pack_h2(acc[ii][j][2] * i1, acc[ii][j][3] * i1);
        }
    }
}

// ---------------------------------------------------------------------------
// Final: out = x + relu(gamma * (t - mean) * rstd + beta).
// BN finalize folded in: channel c is constant per 256-thread block, so
// thread 0 computes mean/rstd from g_bnsum and broadcasts via smem.
// ---------------------------------------------------------------------------
__global__ __launch_bounds__(256) void final_kernel(
    const float* __restrict__ x, const float* __restrict__ gamma,
    const float* __restrict__ beta, float* __restrict__ out)
{
    __shared__ float sMean, sRstd;
    size_t i = (size_t)blockIdx.x * 256 + threadIdx.x;
    int c = (int)((i >> 12) & 255);
    if (threadIdx.x == 0) {
        const float invM = 1.f / (float)(BB * NN);
        float mean = g_bnsum[c] * invM;
        float var = g_bnsum2[c] * invM - mean * mean;
        sMean = mean;
        sRstd = rsqrtf(var + 1e-5f);
    }
    __syncthreads();
    float t = g_t[i];
    float th = (t - sMean) * sRstd;
    float r = fmaxf(0.f, gamma[c] * th + beta[c]);
    out[i] = x[i] + r;
}

// ---------------------------------------------------------------------------
extern "C" void kernel_launch(void* const* d_in, const int* in_sizes, int n_in,
                              void* d_out, int out_size)
{
    const float* x     = (const float*)d_in[0];
    const float* wq    = (const float*)d_in[1];
    const float* wv    = (const float*)d_in[2];
    const float* bv    = (const float*)d_in[3];
    const float* wt    = (const float*)d_in[4];
    const float* bt    = (const float*)d_in[5];
    const float* gamma = (const float*)d_in[6];
    const float* beta  = (const float*)d_in[7];
    float* out = (float*)d_out;

    const int xa_smem = XA_SMEM_WORDS * 4;
    const int ct_smem = CT_SMEM_WORDS * 4;
    const int p1_smem = P1_SMEM_WORDS * 4;
    cudaFuncSetAttribute(xa_kernel,
                         cudaFuncAttributeMaxDynamicSharedMemorySize, xa_smem);
    cudaFuncSetAttribute(convt_tc_kernel,
                         cudaFuncAttributeMaxDynamicSharedMemorySize, ct_smem);
    cudaFuncSetAttribute(pass1_kernel,
                         cudaFuncAttributeMaxDynamicSharedMemorySize, p1_smem);

    // Side stream + events for the convv fork (created per call; leaked —
    // destroying a stream that participated in capture invalidates it).
    cudaStream_t s1;
    cudaStreamCreateWithFlags(&s1, cudaStreamNonBlocking);
    cudaEvent_t e0, e1;
    cudaEventCreateWithFlags(&e0, cudaEventDisableTiming);
    cudaEventCreateWithFlags(&e1, cudaEventDisableTiming);

    // main stream: x^T + weight conversions
    xt_kernel<<<dim3(NN / 64, CC / 64, BB), 256>>>(x);
    wcvt_kernel<<<(8192 + 65536 + 255) / 256, 256>>>(wq, wv, wt);
    cudaEventRecord(e0, 0);

    // side stream: v projection (independent of convq/pass1)
    cudaStreamWaitEvent(s1, e0, 0);
    convv_tc_kernel<<<dim3(NN / 128, CC / 128, BB), 256, 0, s1>>>(bv);
    cudaEventRecord(e1, s1);

    // main stream: q projection + softmax stats (overlaps convv)
    convq_tc_kernel<<<dim3(NN / 128, 1, BB), 256>>>();
    pass1_kernel<<<dim3(NN / 128, BB), 256, p1_smem>>>();

    // join: xa needs both pass1 (main) and convv (s1)
    cudaStreamWaitEvent(0, e1, 0);
    xa_kernel<<<dim3(NN / 128, BB), 512, xa_smem>>>();
    // t = wt (x - x_a) + bt, fused BN partial sums (one wave)
    convt_tc_kernel<<<dim3(NN / 128, BB), 512, ct_smem>>>(bt);
    // fused BN finalize + relu/residual
    final_kernel<<<(BB * CC * NN) / 256, 256>>>(x, gamma, beta, out);
}